// round 11
// baseline (speedup 1.0000x reference)
#include <cuda_runtime.h>
#include <cuda_bf16.h>
#include <cstdint>

typedef __nv_bfloat16 bf16;
typedef long long ll;

#define BB    4
#define NTOK  4096
#define DIM   512
#define H     8
#define DH    64
#define MLM   256
#define LGRP  16
#define BH    32
#define INNER 512

// ---------------- sizes ----------------
static const ll SZ_Y     = (ll)BB*NTOK*INNER;
static const ll SZ_HEADS = (ll)BH*NTOK*DH;
static const ll SZ_LM    = (ll)BH*MLM*DH;
static const ll SZ_A2    = (ll)BH*MLM*MLM;

// fp32 scratch
static const ll F_V    = 0;
static const ll F_A2   = F_V    + SZ_HEADS;
static const ll F_TOTAL= F_A2   + SZ_A2;

// bf16 scratch
static const ll B_XH   = 0;
static const ll B_XL   = B_XH   + SZ_Y;
static const ll B_WQTH = B_XL   + SZ_Y;
static const ll B_WQTL = B_WQTH + (ll)DIM*3*INNER;
static const ll B_WOTH = B_WQTL + (ll)DIM*3*INNER;
static const ll B_WOTL = B_WOTH + (ll)DIM*INNER;
static const ll B_QH   = B_WOTL + (ll)DIM*INNER;
static const ll B_QL   = B_QH   + SZ_HEADS;
static const ll B_KH   = B_QL   + SZ_HEADS;
static const ll B_KL   = B_KH   + SZ_HEADS;
static const ll B_VTH  = B_KL   + SZ_HEADS;
static const ll B_VTL  = B_VTH  + SZ_HEADS;
static const ll B_QLMH = B_VTL  + SZ_HEADS;
static const ll B_QLML = B_QLMH + SZ_LM;
static const ll B_KLMH = B_QLML + SZ_LM;
static const ll B_KLML = B_KLMH + SZ_LM;
static const ll B_A2H  = B_KLML + SZ_LM;
static const ll B_A2L  = B_A2H  + SZ_A2;
static const ll B_Z0H  = B_A2L  + SZ_A2;
static const ll B_Z0L  = B_Z0H  + SZ_A2;
static const ll B_Z0TH = B_Z0L  + SZ_A2;
static const ll B_Z0TL = B_Z0TH + SZ_A2;
static const ll B_Z1H  = B_Z0TL + SZ_A2;
static const ll B_Z1L  = B_Z1H  + SZ_A2;
static const ll B_Z1TH = B_Z1L  + SZ_A2;
static const ll B_Z1TL = B_Z1TH + SZ_A2;
static const ll B_XZH  = B_Z1TL + SZ_A2;
static const ll B_XZL  = B_XZH  + SZ_A2;
static const ll B_T1TH = B_XZL  + SZ_A2;
static const ll B_T1TL = B_T1TH + SZ_A2;
static const ll B_T2TH = B_T1TL + SZ_A2;
static const ll B_T2TL = B_T2TH + SZ_A2;
static const ll B_T3TH = B_T2TL + SZ_A2;
static const ll B_T3TL = B_T3TH + SZ_A2;
static const ll B_AVTH = B_T3TL + SZ_A2;
static const ll B_AVTL = B_AVTH + SZ_LM;
static const ll B_ZVTH = B_AVTL + SZ_LM;
static const ll B_ZVTL = B_ZVTH + SZ_LM;
static const ll B_YH   = B_ZVTL + SZ_LM;
static const ll B_YL   = B_YH   + SZ_Y;
static const ll B_TOTAL= B_YL   + SZ_Y;

__device__ __align__(16) float g_f32[F_TOTAL];
__device__ __align__(16) bf16  g_bf[B_TOTAL];
__device__ float g_norm[2];

// ---------------- stream/event context ----------------
struct StreamCtx {
    cudaStream_t s2;
    cudaEvent_t e0, e1, e2, e3, e4, e5;
    StreamCtx() {
        cudaStreamCreateWithFlags(&s2, cudaStreamNonBlocking);
        cudaEventCreateWithFlags(&e0, cudaEventDisableTiming);
        cudaEventCreateWithFlags(&e1, cudaEventDisableTiming);
        cudaEventCreateWithFlags(&e2, cudaEventDisableTiming);
        cudaEventCreateWithFlags(&e3, cudaEventDisableTiming);
        cudaEventCreateWithFlags(&e4, cudaEventDisableTiming);
        cudaEventCreateWithFlags(&e5, cudaEventDisableTiming);
    }
};
static StreamCtx g_ctx;

// ---------------- helpers ----------------
__device__ __forceinline__ uint32_t smem_u32(const void* p) {
    uint32_t a;
    asm("{ .reg .u64 t; cvta.to.shared.u64 t, %1; cvt.u32.u64 %0, t; }" : "=r"(a) : "l"(p));
    return a;
}
__device__ __forceinline__ void cp16(uint32_t s, const void* g) {
    asm volatile("cp.async.cg.shared.global [%0], [%1], 16;" :: "r"(s), "l"(g));
}
#define CP_COMMIT asm volatile("cp.async.commit_group;" ::: "memory")
#define CP_WAIT0  asm volatile("cp.async.wait_group 0;" ::: "memory")

#define LDSM4(R, A) \
    asm volatile("ldmatrix.sync.aligned.m8n8.x4.shared.b16 {%0,%1,%2,%3}, [%4];" \
        : "=r"((R)[0]), "=r"((R)[1]), "=r"((R)[2]), "=r"((R)[3]) : "r"(A))

#define MMA16816(D, Aa, Bb) \
    asm volatile("mma.sync.aligned.m16n8k16.row.col.f32.bf16.bf16.f32 " \
        "{%0,%1,%2,%3}, {%4,%5,%6,%7}, {%8,%9}, {%0,%1,%2,%3};" \
        : "+f"((D)[0]), "+f"((D)[1]), "+f"((D)[2]), "+f"((D)[3]) \
        : "r"((Aa)[0]), "r"((Aa)[1]), "r"((Aa)[2]), "r"((Aa)[3]), \
          "r"((Bb)[0]), "r"((Bb)[1]))

#define SWZ128(o) ((o) ^ (((o) >> 3) & 0x70))

__device__ __forceinline__ void split2(float v, bf16& h, bf16& l) {
    h = __float2bfloat16(v);
    l = __float2bfloat16(v - __bfloat162float(h));
}
__device__ __forceinline__ uint32_t packh2(float a, float b) {
    __nv_bfloat162 p; p.x = __float2bfloat16(a); p.y = __float2bfloat16(b);
    return *(uint32_t*)&p;
}
__device__ __forceinline__ uint32_t packl2(float a, float b) {
    __nv_bfloat162 p;
    p.x = __float2bfloat16(a - __bfloat162float(__float2bfloat16(a)));
    p.y = __float2bfloat16(b - __bfloat162float(__float2bfloat16(b)));
    return *(uint32_t*)&p;
}

// ---------------- generic split-bf16 HMMA NT GEMM ----------------
template<int TM, int TN, bool SPLIT, int NT>
__device__ __forceinline__ void load_stage(uint32_t sbase,
    const bf16* pAh, const bf16* pAl, const bf16* pBh, const bf16* pBl,
    int K, int k0, int tid)
{
    constexpr uint32_t OAL = TM * 128;
    constexpr uint32_t OBH = (SPLIT ? 2 : 1) * TM * 128;
    constexpr uint32_t OBL = OBH + TN * 128;
#pragma unroll
    for (int i = 0; i < TM * 8 / NT; i++) {
        int idx = tid + i * NT;
        int r = idx >> 3, c = idx & 7;
        uint32_t so = SWZ128((uint32_t)(r * 128 + c * 16));
        ll go = (ll)r * K + k0 + c * 8;
        cp16(sbase + so, pAh + go);
        if (SPLIT) cp16(sbase + OAL + so, pAl + go);
    }
#pragma unroll
    for (int i = 0; i < TN * 8 / NT; i++) {
        int idx = tid + i * NT;
        int r = idx >> 3, c = idx & 7;
        uint32_t so = SWZ128((uint32_t)(r * 128 + c * 16));
        ll go = (ll)r * K + k0 + c * 8;
        cp16(sbase + OBH + so, pBh + go);
        if (SPLIT) cp16(sbase + OBL + so, pBl + go);
    }
}

template<int TM, int TN, bool SPLIT, int NT>
__global__ void __launch_bounds__(NT, (NT == 256 && TM == 64) ? 2 : 1) gemm_mma(
    const bf16* __restrict__ Ah, const bf16* __restrict__ Al,
    const bf16* __restrict__ Bh, const bf16* __restrict__ Bl,
    float* __restrict__ C, bf16* __restrict__ Ch, bf16* __restrict__ Cl,
    bf16* __restrict__ CTh, bf16* __restrict__ CTl,
    const float* __restrict__ bias,
    int K, int Kc, int nbatch, int ldc, int ldct,
    ll sA, ll sB, ll sC, ll sCT,
    float alpha, float diagc, int flags)
{
    extern __shared__ char smem[];
    constexpr int WR = (NT == 512) ? 4 : 2;
    constexpr int MI = TM / WR / 16;
    constexpr int NG = TN / 4 / 8;
    constexpr uint32_t OBH = (SPLIT ? 2 : 1) * TM * 128;
    constexpr uint32_t OBL = OBH + TN * 128;
    constexpr int STAGE = (SPLIT ? 2 : 1) * (TM + TN) * 128;

    const int tid = threadIdx.x, wid = tid >> 5, lane = tid & 31;
    const int bz = blockIdx.z % nbatch;
    const int koff = (blockIdx.z / nbatch) * Kc;
    const int m0 = blockIdx.y * TM, n0 = blockIdx.x * TN;
    const int wm = (wid % WR) * (TM / WR);
    const int wn = (wid / WR) * (TN / 4);
    uint32_t sb = smem_u32(smem);

    const bf16* pAh = Ah + bz * sA + (ll)m0 * K + koff;
    const bf16* pAl = SPLIT ? (Al + bz * sA + (ll)m0 * K + koff) : pAh;
    const bf16* pBh = Bh + bz * sB + (ll)n0 * K + koff;
    const bf16* pBl = SPLIT ? (Bl + bz * sB + (ll)n0 * K + koff) : pBh;

    float acc[MI][NG][4];
#pragma unroll
    for (int a = 0; a < MI; a++)
#pragma unroll
        for (int b = 0; b < NG; b++)
#pragma unroll
            for (int c = 0; c < 4; c++) acc[a][b][c] = 0.f;

    const int nch = Kc >> 6;
    load_stage<TM, TN, SPLIT, NT>(sb, pAh, pAl, pBh, pBl, K, 0, tid);
    CP_COMMIT;

    for (int ck = 0; ck < nch; ck++) {
        CP_WAIT0;
        __syncthreads();
        if (ck + 1 < nch) {
            load_stage<TM, TN, SPLIT, NT>(sb + ((ck + 1) & 1) * STAGE, pAh, pAl, pBh, pBl, K, (ck + 1) * 64, tid);
            CP_COMMIT;
        }
        uint32_t s = sb + (ck & 1) * STAGE;
#pragma unroll
        for (int ks = 0; ks < 4; ks++) {
            uint32_t aH[MI][4], aL[MI][4];
#pragma unroll
            for (int mi = 0; mi < MI; mi++) {
                int row = wm + mi * 16 + (lane & 15);
                int c16 = ks * 2 + (lane >> 4);
                uint32_t off = SWZ128((uint32_t)(row * 128 + c16 * 16));
                LDSM4(aH[mi], s + off);
                if (SPLIT) LDSM4(aL[mi], s + TM * 128 + off);
            }
            uint32_t bH[NG][2], bL[NG][2];
#pragma unroll
            for (int bj = 0; bj < NG / 2; bj++) {
                int row = wn + bj * 16 + (lane & 15);
                int c16 = ks * 2 + (lane >> 4);
                uint32_t off = SWZ128((uint32_t)(row * 128 + c16 * 16));
                uint32_t t[4];
                LDSM4(t, s + OBH + off);
                bH[bj * 2][0] = t[0]; bH[bj * 2 + 1][0] = t[1];
                bH[bj * 2][1] = t[2]; bH[bj * 2 + 1][1] = t[3];
                if (SPLIT) {
                    LDSM4(t, s + OBL + off);
                    bL[bj * 2][0] = t[0]; bL[bj * 2 + 1][0] = t[1];
                    bL[bj * 2][1] = t[2]; bL[bj * 2 + 1][1] = t[3];
                }
            }
#pragma unroll
            for (int mi = 0; mi < MI; mi++)
#pragma unroll
                for (int g = 0; g < NG; g++) MMA16816(acc[mi][g], aH[mi], bH[g]);
            if (SPLIT) {
#pragma unroll
                for (int mi = 0; mi < MI; mi++)
#pragma unroll
                    for (int g = 0; g < NG; g++) MMA16816(acc[mi][g], aH[mi], bL[g]);
#pragma unroll
                for (int mi = 0; mi < MI; mi++)
#pragma unroll
                    for (int g = 0; g < NG; g++) MMA16816(acc[mi][g], aL[mi], bH[g]);
            }
        }
    }

    const bool diagT = (flags & 8) != 0;
    const bool diagN = diagT && !(flags & 16);
#pragma unroll
    for (int mi = 0; mi < MI; mi++) {
#pragma unroll
        for (int g = 0; g < NG; g++) {
#pragma unroll
            for (int half = 0; half < 2; half++) {
                int r = m0 + wm + mi * 16 + (lane >> 2) + half * 8;
                int n = n0 + wn + g * 8 + (lane & 3) * 2;
                float a0 = acc[mi][g][half * 2 + 0];
                float a1v = acc[mi][g][half * 2 + 1];
                if (flags & 64) {
                    int nq = n + ldct;
                    int sel = nq >> 9;
                    int hh = (nq >> 6) & 7;
                    int d  = nq & 63;
                    int b  = r >> 12, t = r & 4095;
                    ll hidx = ((ll)((b << 3) + hh) * NTOK + t) * 64 + d;
                    if (sel == 0) {
                        *(uint32_t*)(g_bf + B_QH + hidx) = packh2(a0 * 0.125f, a1v * 0.125f);
                        *(uint32_t*)(g_bf + B_QL + hidx) = packl2(a0 * 0.125f, a1v * 0.125f);
                    } else if (sel == 1) {
                        *(uint32_t*)(g_bf + B_KH + hidx) = packh2(a0, a1v);
                        *(uint32_t*)(g_bf + B_KL + hidx) = packl2(a0, a1v);
                    } else {
                        *(float2*)(g_f32 + F_V + hidx) = make_float2(a0, a1v);
                        bf16 h0, l0, h1, l1;
                        split2(a0, h0, l0); split2(a1v, h1, l1);
                        ll vt = ((ll)((b << 3) + hh) * 64 + d) * NTOK + t;
                        g_bf[B_VTH + vt] = h0;        g_bf[B_VTL + vt] = l0;
                        g_bf[B_VTH + vt + NTOK] = h1; g_bf[B_VTL + vt + NTOK] = l1;
                    }
                    continue;
                }
                if (flags & 3) {
                    float n0v = diagN ? ((r == n)     ? diagc : 0.f) - a0  : alpha * a0;
                    float n1v = diagN ? ((r == n + 1) ? diagc : 0.f) - a1v : alpha * a1v;
                    if (bias) { n0v += bias[n]; n1v += bias[n + 1]; }
                    ll o = bz * sC + (ll)r * ldc + n;
                    if (flags & 1) {
                        if (flags & 32) { atomicAdd(C + o, n0v); atomicAdd(C + o + 1, n1v); }
                        else *(float2*)(C + o) = make_float2(n0v, n1v);
                    }
                    if (flags & 2) {
                        *(uint32_t*)(Ch + o) = packh2(n0v, n1v);
                        *(uint32_t*)(Cl + o) = packl2(n0v, n1v);
                    }
                }
                if (flags & 4) {
                    float t0v = diagT ? ((r == n)     ? diagc : 0.f) - a0  : alpha * a0;
                    float t1v = diagT ? ((r == n + 1) ? diagc : 0.f) - a1v : alpha * a1v;
                    bf16 h0, l0, h1, l1;
                    split2(t0v, h0, l0); split2(t1v, h1, l1);
                    ll ot0 = bz * sCT + (ll)n * ldct + r;
                    ll ot1 = bz * sCT + (ll)(n + 1) * ldct + r;
                    CTh[ot0] = h0; CTl[ot0] = l0;
                    CTh[ot1] = h1; CTl[ot1] = l1;
                }
            }
        }
    }
}

// ---------------- fused GEMM + row softmax (attn2) ----------------
__global__ void __launch_bounds__(256, 1) attn_gemm_softmax(
    const bf16* __restrict__ Ah, const bf16* __restrict__ Al,
    const bf16* __restrict__ Bh, const bf16* __restrict__ Bl,
    float* __restrict__ C32, bf16* __restrict__ Ch, bf16* __restrict__ Cl,
    ll sA, ll sB, ll sC)
{
    extern __shared__ char smem[];
    __shared__ float redm[2][32][4];
    __shared__ float reds[2][32][4];
    const int tid = threadIdx.x, wid = tid >> 5, lane = tid & 31;
    const int bz = blockIdx.y;
    const int m0 = blockIdx.x * 64;
    const int wm = (wid & 1) * 32;
    const int wn = (wid >> 1) * 64;
    uint32_t sb = smem_u32(smem);

    const bf16* pAh = Ah + bz * sA + (ll)m0 * 64;
    const bf16* pAl = Al + bz * sA + (ll)m0 * 64;
    const bf16* pBh = Bh + bz * sB;
    const bf16* pBl = Bl + bz * sB;

#pragma unroll
    for (int i = 0; i < 2; i++) {
        int idx = tid + i * 256;
        int r = idx >> 3, c = idx & 7;
        uint32_t so = SWZ128((uint32_t)(r * 128 + c * 16));
        cp16(sb + so, pAh + (ll)r * 64 + c * 8);
        cp16(sb + 8192 + so, pAl + (ll)r * 64 + c * 8);
    }
#pragma unroll
    for (int i = 0; i < 8; i++) {
        int idx = tid + i * 256;
        int r = idx >> 3, c = idx & 7;
        uint32_t so = SWZ128((uint32_t)(r * 128 + c * 16));
        cp16(sb + 16384 + so, pBh + (ll)r * 64 + c * 8);
        cp16(sb + 49152 + so, pBl + (ll)r * 64 + c * 8);
    }
    CP_COMMIT;

    float acc[2][8][4];
#pragma unroll
    for (int a = 0; a < 2; a++)
#pragma unroll
        for (int b = 0; b < 8; b++)
#pragma unroll
            for (int c = 0; c < 4; c++) acc[a][b][c] = 0.f;

    CP_WAIT0;
    __syncthreads();
#pragma unroll
    for (int ks = 0; ks < 4; ks++) {
        uint32_t aH[2][4], aL[2][4];
#pragma unroll
        for (int mi = 0; mi < 2; mi++) {
            int row = wm + mi * 16 + (lane & 15);
            int c16 = ks * 2 + (lane >> 4);
            uint32_t off = SWZ128((uint32_t)(row * 128 + c16 * 16));
            LDSM4(aH[mi], sb + off);
            LDSM4(aL[mi], sb + 8192 + off);
        }
        uint32_t bHf[8][2], bLf[8][2];
#pragma unroll
        for (int bj = 0; bj < 4; bj++) {
            int row = wn + bj * 16 + (lane & 15);
            int c16 = ks * 2 + (lane >> 4);
            uint32_t off = SWZ128((uint32_t)(row * 128 + c16 * 16));
            uint32_t t[4];
            LDSM4(t, sb + 16384 + off);
            bHf[bj * 2][0] = t[0]; bHf[bj * 2 + 1][0] = t[1];
            bHf[bj * 2][1] = t[2]; bHf[bj * 2 + 1][1] = t[3];
            LDSM4(t, sb + 49152 + off);
            bLf[bj * 2][0] = t[0]; bLf[bj * 2 + 1][0] = t[1];
            bLf[bj * 2][1] = t[2]; bLf[bj * 2 + 1][1] = t[3];
        }
#pragma unroll
        for (int mi = 0; mi < 2; mi++)
#pragma unroll
            for (int g = 0; g < 8; g++) MMA16816(acc[mi][g], aH[mi], bHf[g]);
#pragma unroll
        for (int mi = 0; mi < 2; mi++)
#pragma unroll
            for (int g = 0; g < 8; g++) MMA16816(acc[mi][g], aH[mi], bLf[g]);
#pragma unroll
        for (int mi = 0; mi < 2; mi++)
#pragma unroll
            for (int g = 0; g < 8; g++) MMA16816(acc[mi][g], aL[mi], bHf[g]);
    }

    float mx[2][2];
#pragma unroll
    for (int mi = 0; mi < 2; mi++)
#pragma unroll
        for (int half = 0; half < 2; half++) {
            float m = -1e30f;
#pragma unroll
            for (int g = 0; g < 8; g++) {
                m = fmaxf(m, acc[mi][g][half * 2]);
                m = fmaxf(m, acc[mi][g][half * 2 + 1]);
            }
            m = fmaxf(m, __shfl_xor_sync(0xffffffffu, m, 1));
            m = fmaxf(m, __shfl_xor_sync(0xffffffffu, m, 2));
            mx[mi][half] = m;
        }
    if ((lane & 3) == 0) {
#pragma unroll
        for (int mi = 0; mi < 2; mi++)
#pragma unroll
            for (int half = 0; half < 2; half++)
                redm[wid & 1][mi * 16 + (lane >> 2) + half * 8][wid >> 1] = mx[mi][half];
    }
    __syncthreads();
    float sm[2][2];
#pragma unroll
    for (int mi = 0; mi < 2; mi++)
#pragma unroll
        for (int half = 0; half < 2; half++) {
            int ri = mi * 16 + (lane >> 2) + half * 8;
            float m = fmaxf(fmaxf(redm[wid & 1][ri][0], redm[wid & 1][ri][1]),
                            fmaxf(redm[wid & 1][ri][2], redm[wid & 1][ri][3]));
            float s = 0.f;
#pragma unroll
            for (int g = 0; g < 8; g++) {
                float e0 = __expf(acc[mi][g][half * 2] - m);
                float e1 = __expf(acc[mi][g][half * 2 + 1] - m);
                acc[mi][g][half * 2] = e0; acc[mi][g][half * 2 + 1] = e1;
                s += e0 + e1;
            }
            s += __shfl_xor_sync(0xffffffffu, s, 1);
            s += __shfl_xor_sync(0xffffffffu, s, 2);
            sm[mi][half] = s;
        }
    if ((lane & 3) == 0) {
#pragma unroll
        for (int mi = 0; mi < 2; mi++)
#pragma unroll
            for (int half = 0; half < 2; half++)
                reds[wid & 1][mi * 16 + (lane >> 2) + half * 8][wid >> 1] = sm[mi][half];
    }
    __syncthreads();
#pragma unroll
    for (int mi = 0; mi < 2; mi++)
#pragma unroll
        for (int half = 0; half < 2; half++) {
            int ri = mi * 16 + (lane >> 2) + half * 8;
            float tot = reds[wid & 1][ri][0] + reds[wid & 1][ri][1]
                      + reds[wid & 1][ri][2] + reds[wid & 1][ri][3];
            float inv = 1.f / tot;
            int r = m0 + wm + ri;
#pragma unroll
            for (int g = 0; g < 8; g++) {
                int n = wn + g * 8 + (lane & 3) * 2;
                float v0 = acc[mi][g][half * 2] * inv;
                float v1 = acc[mi][g][half * 2 + 1] * inv;
                ll o = bz * sC + (ll)r * 256 + n;
                *(uint32_t*)(Ch + o) = packh2(v0, v1);
                *(uint32_t*)(Cl + o) = packl2(v0, v1);
                *(float2*)(C32 + o) = make_float2(v0, v1);
            }
        }
}

// ---------------- fused attn3 + softmax + @v -> avT (512 thr; 2-term) ----------------
#define VROW 272
__global__ void __launch_bounds__(512, 1) fa3_av(
    const bf16* __restrict__ Qh, const bf16* __restrict__ Ql,
    const bf16* __restrict__ Kh, const bf16* __restrict__ Kl,
    const bf16* __restrict__ Vth, const bf16* __restrict__ Vtl,
    bf16* __restrict__ AVTh, bf16* __restrict__ AVTl,
    ll sQ, ll sK, ll sVT, ll sAVT)
{
    extern __shared__ char smem[];
    __shared__ float Os[64 * 68];
    __shared__ float rsm[64];
    const int tid = threadIdx.x, wid = tid >> 5, lane = tid & 31;
    const int bz = blockIdx.y;
    const int m0 = blockIdx.x * 64;
    const int wm = (wid & 3) * 16;
    const int wn = (wid >> 2) * 32;
    uint32_t sb = smem_u32(smem);
    constexpr uint32_t ST0 = 16384;
    constexpr uint32_t OVT = 32768;
    constexpr uint32_t VLo = OVT + 64 * VROW;
    constexpr uint32_t STG = OVT + 2 * 64 * VROW;

    for (int i = tid; i < 64 * 68; i += 512) Os[i] = 0.f;
    if (tid < 64) rsm[tid] = 0.f;

    const bf16* pQh = Qh + bz * sQ + (ll)m0 * 64;
    const bf16* pKh = Kh + bz * sK;
    const bf16* pKl = Kl + bz * sK;
    const bf16* pVh = Vth + bz * sVT;
    const bf16* pVl = Vtl + bz * sVT;

    {
        int r = tid >> 3, c = tid & 7;
        uint32_t so = SWZ128((uint32_t)(r * 128 + c * 16));
        cp16(sb + so, pQh + (ll)r * 64 + c * 8);
    }
    {
        uint32_t s = sb + ST0;
#pragma unroll
        for (int i = 0; i < 2; i++) {
            int idx = tid + i * 512;
            int r = idx >> 3, c = idx & 7;
            uint32_t so = SWZ128((uint32_t)(r * 128 + c * 16));
            ll g = (ll)r * 64 + c * 8;
            cp16(s + so, pKh + g);
            cp16(s + 16384 + so, pKl + g);
        }
#pragma unroll
        for (int i = 0; i < 2; i++) {
            int idx = tid + i * 512;
            int r = idx >> 4, c = idx & 15;
            uint32_t so = (uint32_t)(r * VROW + c * 16);
            ll g = (ll)r * NTOK + c * 8;
            cp16(s + OVT + so, pVh + g);
            cp16(s + VLo + so, pVl + g);
        }
    }
    CP_COMMIT;

    float acc_o[8][4];
#pragma unroll
    for (int b = 0; b < 8; b++)
#pragma unroll
        for (int c = 0; c < 4; c++) acc_o[b][c] = 0.f;
    float rs[2] = {0.f, 0.f};

    for (int ck = 0; ck < 32; ck++) {
        CP_WAIT0;
        __syncthreads();
        if (ck + 1 < 32) {
            uint32_t s = sb + ST0 + ((ck + 1) & 1) * STG;
            int tok = (ck + 1) * 128;
#pragma unroll
            for (int i = 0; i < 2; i++) {
                int idx = tid + i * 512;
                int r = idx >> 3, c = idx & 7;
                uint32_t so = SWZ128((uint32_t)(r * 128 + c * 16));
                ll g = (ll)(tok + r) * 64 + c * 8;
                cp16(s + so, pKh + g);
                cp16(s + 16384 + so, pKl + g);
            }
#pragma unroll
            for (int i = 0; i < 2; i++) {
                int idx = tid + i * 512;
                int r = idx >> 4, c = idx & 15;
                uint32_t so = (uint32_t)(r * VROW + c * 16);
                ll g = (ll)r * NTOK + tok + c * 8;
                cp16(s + OVT + so, pVh + g);
                cp16(s + VLo + so, pVl + g);
            }
            CP_COMMIT;
        }
        uint32_t s = sb + ST0 + (ck & 1) * STG;

        float accl[4][4];
#pragma unroll
        for (int b = 0; b < 4; b++)
#pragma unroll
            for (int c = 0; c < 4; c++) accl[b][c] = 0.f;
#pragma unroll
        for (int ks = 0; ks < 4; ks++) {
            int c16 = ks * 2 + (lane >> 4);
            uint32_t aH[4];
            {
                int row = wm + (lane & 15);
                uint32_t off = SWZ128((uint32_t)(row * 128 + c16 * 16));
                LDSM4(aH, sb + off);
            }
            uint32_t bHf[4][2], bLf[4][2];
#pragma unroll
            for (int bj = 0; bj < 2; bj++) {
                int row = wn + bj * 16 + (lane & 15);
                uint32_t off = SWZ128((uint32_t)(row * 128 + c16 * 16));
                uint32_t t[4];
                LDSM4(t, s + off);
                bHf[bj * 2][0] = t[0]; bHf[bj * 2 + 1][0] = t[1];
                bHf[bj * 2][1] = t[2]; bHf[bj * 2 + 1][1] = t[3];
                LDSM4(t, s + 16384 + off);
                bLf[bj * 2][0] = t[0]; bLf[bj * 2 + 1][0] = t[1];
                bLf[bj * 2][1] = t[2]; bLf[bj * 2 + 1][1] = t[3];
            }
#pragma unroll
            for (int g = 0; g < 4; g++) MMA16816(accl[g], aH, bHf[g]);
#pragma unroll
            for (int g = 0; g < 4; g++) MMA16816(accl[g], aH, bLf[g]);
        }
#pragma unroll
        for (int half = 0; half < 2; half++) {
            float srow = 0.f;
#pragma unroll
            for (int g = 0; g < 4; g++) {
                float e0 = __expf(accl[g][half * 2]);
                float e1 = __expf(accl[g][half * 2 + 1]);
                accl[g][half * 2] = e0;
                accl[g][half * 2 + 1] = e1;
                srow += e0 + e1;
            }
            rs[half] += srow;
        }
#pragma unroll
        for (int kk = 0; kk < 2; kk++) {
            uint32_t aPh[4];
            aPh[0] = packh2(accl[2 * kk][0], accl[2 * kk][1]);
            aPh[1] = packh2(accl[2 * kk][2], accl[2 * kk][3]);
            aPh[2] = packh2(accl[2 * kk + 1][0], accl[2 * kk + 1][1]);
            aPh[3] = packh2(accl[2 * kk + 1][2], accl[2 * kk + 1][3]);
#pragma unroll
            for (int bj = 0; bj < 4; bj++) {
                uint32_t addr = s + OVT + (uint32_t)((bj * 16 + (lane & 15)) * VROW)
                              + (uint32_t)((wn + kk * 16) * 2 + (lane >> 4) * 16);
                uint32_t t[4], u[4];
                LDSM4(t, addr);
                LDSM4(u, addr + 64 * VROW);
                uint32_t bh0[2] = {t[0], t[2]}, bh1[2] = {t[1], t[3]};
                uint32_t bl0[2] = {u[0], u[2]}, bl1[2] = {u[1], u[3]};
                MMA16816(acc_o[2 * bj],     aPh, bh0);
                MMA16816(acc_o[2 * bj],     aPh, bl0);
                MMA16816(acc_o[2 * bj + 1], aPh, bh1);
                MMA16816(acc_o[2 * bj + 1], aPh, bl1);
            }
        }
    }

#pragma unroll
    for (int half = 0; half < 2; half++) {
        float v = rs[half];
        v += __shfl_xor_sync(0xffffffffu, v, 1);
        v += __shfl_xor_sync(0xffffffffu, v, 2);
        if ((lane & 3) == 0)
            atomicAdd(&rsm[wm + (lane >> 2) + half * 8], v);
    }
#pragma unroll
    for (int g = 0; g < 8; g++) {
        int r0 = wm + (lane >> 2);
        int c = g * 8 + (lane & 3) * 2;
        atomicAdd(&Os[r0 * 68 + c],           acc_o[g][0]);
        atomicAdd(&Os[r0 * 68 + c + 1],       acc_o[g][1]);
        atomicAdd(&Os[(r0 + 8) * 68 + c],     acc_o[g][2]);
        atomicAdd(&Os[(r0 + 8) * 68 + c + 1], acc_o[g][3]);
    }
    __syncthreads();
#pragma unroll
    for (int i = 0; i < 8; i++) {
        int idx = tid + i * 512;
        int r = idx >> 6, d = idx & 63;
        float val = Os[r * 68 + d] / rsm[r];
        bf16 hh, lo; split2(val, hh, lo);
        ll o = bz * sAVT + (ll)d * MLM + (m0 + r);
        AVTh[o] = hh; AVTl[o] = lo;
    }
}

// ---------------- fused attn1 + softmax + P@zav + conv -> y (512 thr; 2-term both GEMMs) ----------------
#define ZROW 528
__global__ void __launch_bounds__(512, 1) attn1_outh(
    const bf16* __restrict__ Ah,
    const bf16* __restrict__ Bh, const bf16* __restrict__ Bl,
    const bf16* __restrict__ Zh, const bf16* __restrict__ Zl,
    const float* __restrict__ Vv, const float* __restrict__ kern,
    bf16* __restrict__ Yh, bf16* __restrict__ Yl,
    ll sA, ll sB, ll sZ, ll sV, int bzoff)
{
    extern __shared__ char smem[];
    __shared__ float redm[4][16][4];
    __shared__ float reds[4][16][4];
    __shared__ float khs[33];
    const int tid = threadIdx.x, wid = tid >> 5, lane = tid & 31;
    const int bz = blockIdx.y + bzoff;
    const int m0 = blockIdx.x * 64;
    const int wm = (wid & 3) * 16;
    const int wn = (wid >> 2) * 64;
    const int b_ = bz >> 3, h_ = bz & 7;
    uint32_t sb = smem_u32(smem);
    constexpr uint32_t OZH = 81920;
    constexpr uint32_t OZL = OZH + 64 * ZROW;
    constexpr uint32_t OO  = OZL + 64 * ZROW;
    constexpr uint32_t OV  = OO + 64 * 68 * 4;
    float* Os = (float*)(smem + OO);
    float* sv = (float*)(smem + OV);

    if (tid < 33) khs[tid] = kern[h_ * 33 + tid];

    const bf16* pAh = Ah + bz * sA + (ll)m0 * 64;
    const bf16* pBh = Bh + bz * sB;
    const bf16* pBl = Bl + bz * sB;
    const bf16* pZh = Zh + bz * sZ;
    const bf16* pZl = Zl + bz * sZ;
    const float* pV = Vv + bz * sV;

    {
        int r = tid >> 3, c = tid & 7;
        uint32_t so = SWZ128((uint32_t)(r * 128 + c * 16));
        cp16(sb + so, pAh + (ll)r * 64 + c * 8);
    }
#pragma unroll
    for (int i = 0; i < 4; i++) {
        int idx = tid + i * 512;
        int r = idx >> 3, c = idx & 7;
        uint32_t so = SWZ128((uint32_t)(r * 128 + c * 16));
        cp16(sb + 16384 + so, pBh + (ll)r * 64 + c * 8);
        cp16(sb + 49152 + so, pBl + (ll)r * 64 + c * 8);
    }
#pragma unroll
    for (int i = 0; i < 4; i++) {
        int idx = tid + i * 512;
        int r = idx >> 5, c = idx & 31;
        uint32_t so = (uint32_t)(r * ZROW + c * 16);
        cp16(sb + OZH + so, pZh + (ll)r * 256 + c * 8);
        cp16(sb + OZL + so, pZl + (ll)r * 256 + c * 8);
    }
#pragma unroll
    for (int i = 0; i < 3; i++) {
        int idx = tid + i * 512;
        int r = idx >> 4, c = idx & 15;
        int tt = m0 - 16 + r;
        if (tt >= 0 && tt < NTOK)
            cp16(sb + OV + (uint32_t)(r * 256 + c * 16), pV + (ll)tt * 64 + c * 4);
        else
            *(float4*)(smem + OV + r * 256 + c * 16) = make_float4(0.f, 0.f, 0.f, 0.f);
    }
    CP_COMMIT;
#pragma unroll
    for (int i = 0; i < 9; i++) {
        int idx = tid + i * 512;
        if (idx < 64 * 68) Os[idx] = 0.f;
    }

    float acc[8][4];
#pragma unroll
    for (int b = 0; b < 8; b++)
#pragma unroll
        for (int c = 0; c < 4; c++) acc[b][c] = 0.f;

    CP_WAIT0;
    __syncthreads();
#pragma unroll
    for (int ks = 0; ks < 4; ks++) {
        uint32_t aH[4];
        {
            int row = wm + (lane & 15);
            int c16 = ks * 2 + (lane >> 4);
            uint32_t off = SWZ128((uint32_t)(row * 128 + c16 * 16));
            LDSM4(aH, sb + off);
        }
        uint32_t bHf[8][2], bLf[8][2];
#pragma unroll
        for (int bj = 0; bj < 4; bj++) {
            int row = wn + bj * 16 + (lane & 15);
            int c16 = ks * 2 + (lane >> 4);
            uint32_t off = SWZ128((uint32_t)(row * 128 + c16 * 16));
            uint32_t t[4];
            LDSM4(t, sb + 16384 + off);
            bHf[bj * 2][0] = t[0]; bHf[bj * 2 + 1][0] = t[1];
            bHf[bj * 2][1] = t[2]; bHf[bj * 2 + 1][1] = t[3];
            LDSM4(t, sb + 49152 + off);
            bLf[bj * 2][0] = t[0]; bLf[bj * 2 + 1][0] = t[1];
            bLf[bj * 2][1] = t[2]; bLf[bj * 2 + 1][1] = t[3];
        }
#pragma unroll
        for (int g = 0; g < 8; g++) MMA16816(acc[g], aH, bHf[g]);
#pragma unroll
        for (int g = 0; g < 8; g++) MMA16816(acc[g], aH, bLf[g]);
    }

    float mx[2];
#pragma unroll
    for (int half = 0; half < 2; half++) {
        float m = -1e30f;
#pragma unroll
        for (int g = 0; g < 8; g++) {
            m = fmaxf(m, acc[g][half * 2]);
            m = fmaxf(m, acc[g][half * 2 + 1]);
        }
        m = fmaxf(m, __shfl_xor_sync(0xffffffffu, m, 1));
        m = fmaxf(m, __shfl_xor_sync(0xffffffffu, m, 2));
        mx[half] = m;
    }
    if ((lane & 3) == 0) {
#pragma unroll
        for (int half = 0; half < 2; half++)
            redm[wid & 3][(lane >> 2) + half * 8][wid >> 2] = mx[half];
    }
    __syncthreads();
    float sm[2];
#pragma unroll
    for (int half = 0; half < 2; half++) {
        int ri = (lane >> 2) + half * 8;
        float m = fmaxf(fmaxf(redm[wid & 3][ri][0], redm[wid & 3][ri][1]),
                        fmaxf(redm[wid & 3][ri][2], redm[wid & 3][ri][3]));
        float s = 0.f;
#pragma unroll
        for (int g = 0; g < 8; g++) {
            float e0 = __expf(acc[g][half * 2] - m);
            float e1 = __expf(acc[g][half * 2 + 1] - m);
            acc[g][half * 2] = e0; acc[g][half * 2 + 1] = e1;
            s += e0 + e1;
        }
        s += __shfl_xor_sync(0xffffffffu, s, 1);
        s += __shfl_xor_sync(0xffffffffu, s, 2);
        sm[half] = s;
    }
    if ((lane & 3) == 0) {
#pragma unroll
        for (int half = 0; half < 2; half++)
            reds[wid & 3][(lane >> 2) + half * 8][wid >> 2] = sm[half];
    }
    __syncthreads();
#pragma unroll
    for (int half = 0; half < 2; half++) {
        int ri = (lane >> 2) + half * 8;
        float tot = reds[wid & 3][ri][0] + reds[wid & 3][ri][1]
                  + reds[wid & 3][ri][2] + reds[wid & 3][ri][3];
        float inv = 1.f / tot;
#pragma unroll
        for (int g = 0; g < 8; g++) {
            acc[g][half * 2]     *= inv;
            acc[g][half * 2 + 1] *= inv;
        }
    }

    float acc_o[8][4];
#pragma unroll
    for (int b = 0; b < 8; b++)
#pragma unroll
        for (int c = 0; c < 4; c++) acc_o[b][c] = 0.f;

    // P @ zav: 2-term (Ph·zh + Ph·zl; P_lo dropped — validated by fa3 evidence)
#pragma unroll
    for (int ks = 0; ks < 4; ks++) {
        uint32_t aPh[4];
        aPh[0] = packh2(acc[2 * ks][0], acc[2 * ks][1]);
        aPh[1] = packh2(acc[2 * ks][2], acc[2 * ks][3]);
        aPh[2] = packh2(acc[2 * ks + 1][0], acc[2 * ks + 1][1]);
        aPh[3] = packh2(acc[2 * ks + 1][2], acc[2 * ks + 1][3]);
#pragma unroll
        for (int bj = 0; bj < 4; bj++) {
            uint32_t addr = sb + OZH + (uint32_t)((bj * 16 + (lane & 15)) * ZROW)
                          + (uint32_t)((wn + ks * 16) * 2 + (lane >> 4) * 16);
            uint32_t t[4], u[4];
            LDSM4(t, addr);
            LDSM4(u, addr + (OZL - OZH));
            uint32_t bh0[2] = {t[0], t[2]}, bh1[2] = {t[1], t[3]};
            uint32_t bl0[2] = {u[0], u[2]}, bl1[2] = {u[1], u[3]};
            MMA16816(acc_o[2 * bj],     aPh, bh0);
            MMA16816(acc_o[2 * bj],     aPh, bl0);
            MMA16816(acc_o[2 * bj + 1], aPh, bh1);
            MMA16816(acc_o[2 * bj + 1], aPh, bl1);
        }
    }

#pragma unroll
    for (int g = 0; g < 8; g++) {
        int r0 = wm + (lane >> 2);
        int c = g * 8 + (lane & 3) * 2;
        atomicAdd(&Os[r0 * 68 + c],           acc_o[g][0]);
        atomicAdd(&Os[r0 * 68 + c + 1],       acc_o[g][1]);
        atomicAdd(&Os[(r0 + 8) * 68 + c],     acc_o[g][2]);
        atomicAdd(&Os[(r0 + 8) * 68 + c + 1], acc_o[g][3]);
    }
    __syncthreads();
#pragma unroll
    for (int i = 0; i < 8; i++) {
        int idx = tid + i * 512;
        int r = idx >> 6, d = idx & 63;
        float s = Os[r * 68 + d];
#pragma unroll
        for (int j = 0; j < 33; j++)
            s = fmaf(sv[(r + j) * 64 + d], khs[j], s);
        ll yo = ((ll)(b_ * NTOK + m0 + r)) * INNER + h_ * 64 + d;
        bf16 hh, lo; split2(s, hh, lo);
        Yh[yo] = hh; Yl[yo] = lo;
    }
}

// ---------------- elementwise kernels ----------------
__global__ void split_f32(const float* __restrict__ in, bf16* __restrict__ oh,
                          bf16* __restrict__ ol, ll n)
{
    ll i = (ll)blockIdx.x * 256 + threadIdx.x;
    if (i >= n) return;
    bf16 h, l; split2(in[i], h, l);
    oh[i] = h; ol[i] = l;
}

__global__ void transpose_split(const float* __restrict__ in, bf16* __restrict__ oh,
                                bf16* __restrict__ ol, int R, int C, ll sIn, ll sOut,
                                const float* __restrict__ nrmp, float dc, int usediag)
{
    __shared__ float t[32][33];
    ll b = blockIdx.z;
    const float* ip = in + b * sIn;
    int c0 = blockIdx.x * 32, r0 = blockIdx.y * 32;
    int tx = threadIdx.x, ty = threadIdx.y;
#pragma unroll
    for (int i = 0; i < 4; i++)
        t[ty + i * 8][tx] = ip[(ll)(r0 + ty + i * 8) * C + c0 + tx];
    __syncthreads();
    float alpha = nrmp ? 1.f / (nrmp[0] * nrmp[1]) : 1.f;
#pragma unroll
    for (int i = 0; i < 4; i++) {
        int cg = c0 + ty + i * 8, rg = r0 + tx;
        float v = t[tx][ty + i * 8];
        v = usediag ? ((rg == cg ? dc : 0.f) - v) : alpha * v;
        ll o = b * sOut + (ll)cg * R + rg;
        bf16 h, l; split2(v, h, l);
        oh[o] = h; ol[o] = l;
    }
}

__global__ void scale_split(const float* __restrict__ in, bf16* __restrict__ oh,
                            bf16* __restrict__ ol, ll n, const float* __restrict__ nrmp)
{
    ll i = (ll)blockIdx.x * 256 + threadIdx.x;
    if (i >= n) return;
    float inv = 1.f / (nrmp[0] * nrmp[1]);
    bf16 h, l; split2(in[i] * inv, h, l);
    oh[i] = h; ol[i] = l;
}

__global__ void landmark_split_bf(const bf16* __restrict__ xh, const bf16* __restrict__ xl,
                                  bf16* __restrict__ oh, bf16* __restrict__ ol)
{
    ll idx = (ll)blockIdx.x * 256 + threadIdx.x;
    if (idx >= SZ_LM) return;
    int d = (int)(idx & 63);
    int mi = (int)((idx >> 6) & 255);
    ll bh = idx >> 14;
    ll base = (bh * NTOK + (ll)mi * LGRP) * DH + d;
    float s = 0.f;
#pragma unroll
    for (int t = 0; t < LGRP; t++) {
        ll o = base + (ll)t * DH;
        s += __bfloat162float(xh[o]) + __bfloat162float(xl[o]);
    }
    bf16 h, l; split2(s * (1.f / LGRP), h, l);
    oh[idx] = h; ol[idx] = l;
}

__global__ void norm_init_kernel(float* nrm) { nrm[0] = 0.f; nrm[1] = 0.f; }

__global__ void pinv_norm_kernel(const float* __restrict__ x, float* __restrict__ nrm)
{
    int r = threadIdx.x;
    const float* xb = x + (ll)blockIdx.x * MLM * MLM;
    float rs = 0.f, cs = 0.f;
    for (int j = 0; j < MLM; j++) {
        rs += fabsf(xb[(ll)r * MLM + j]);
        cs += fabsf(xb[(ll)j * MLM + r]);
    }
    __shared__ float s1[256], s2[256];
    s1[r] = rs; s2[r] = cs; __syncthreads();
    for (int s = 128; s > 0; s >>= 1) {
        if (r < s) { s1[r] = fmaxf(s1[r], s1[r + s]); s2[r] = fmaxf(s2[r], s2[r + s]); }
        __syncthreads();
    }
    if (r == 0) {
        atomicMax((int*)&nrm[0], __float_as_int(s1[0]));
        atomicMax((int*)&nrm[1], __float_as_int(s2[0]));
    }
}

// ---------------- host ----------------
template<int TM, int TN, bool SPLIT, int NT>
static inline void tcg(cudaStream_t st,
                       const bf16* Ah, const bf16* Al, const bf16* Bh, const bf16* Bl,
                       float* C, bf16* Ch, bf16* Cl, bf16* CTh, bf16* CTl,
                       const float* bias,
                       int M, int N, int K, int Kc, int ldc, int ldct,
                       ll sA, ll sB, ll sC, ll sCT, int batch, int kz,
                       float alpha, float diagc, int flags)
{
    dim3 grid(N / TN, M / TM, batch * kz);
    size_t sm = 2 * (size_t)((SPLIT ? 2 : 1) * (TM + TN) * 128);
    gemm_mma<TM, TN, SPLIT, NT><<<grid, NT, sm, st>>>(Ah, Al, Bh, Bl, C, Ch, Cl, CTh, CTl, bias,
                                                      K, Kc, batch, ldc, ldct, sA, sB, sC, sCT,
                                                      alpha, diagc, flags);
}

extern "C" void kernel_launch(void* const* d_in, const int* in_sizes, int n_in,
                              void* d_out, int out_size)
{
    const float* x     = (const float*)d_in[0];
    const float* w_qkv = (const float*)d_in[1];
    const float* w_out = (const float*)d_in[2];
    const float* b_out = (const float*)d_in[3];
    const float* res_k = (const float*)d_in[4];
    float* out = (float*)d_out;

    const int A1O_SMEM = 81920 + 2 * 64 * ZROW + 64 * 68 * 4 + 96 * 64 * 4;
    const int FA3_SMEM = 16384 + 2 * (32768 + 2 * 64 * VROW);

    cudaFuncSetAttribute(gemm_mma<128, 128, true, 512>, cudaFuncAttributeMaxDynamicSharedMemorySize, 131072);
    cudaFuncSetAttribute(gemm_mma<64, 128, true, 256>,  cudaFuncAttributeMaxDynamicSharedMemorySize, 98304);
    cudaFuncSetAttribute(gemm_mma<64, 128, false, 256>, cudaFuncAttributeMaxDynamicSharedMemorySize, 49152);
    cudaFuncSetAttribute(gemm_mma<64, 64, true, 256>,   cudaFuncAttributeMaxDynamicSharedMemorySize, 65536);
    cudaFuncSetAttribute(attn_gemm_softmax, cudaFuncAttributeMaxDynamicSharedMemorySize, 81920);
    cudaFuncSetAttribute(attn1_outh, cudaFuncAttributeMaxDynamicSharedMemorySize, A1O_SMEM);
    cudaFuncSetAttribute(fa3_av, cudaFuncAttributeMaxDynamicSharedMemorySize, FA3_SMEM);

    float* F;  cudaGetSymbolAddress((void**)&F, g_f32);
    bf16*  Bp; cudaGetSymbolAddress((void**)&Bp, g_bf);
    float* nrm; cudaGetSymbolAddress((void**)&nrm, g_norm);

    const ll SH = (ll)NTOK * DH, SL = (ll)MLM * DH;
    const ll SA2 = (ll)MLM * MLM;

    cudaStream_t s0 = 0;
    cudaStream_t s2 = g_ctx.s2;

    // fork s2 immediately: weight transposes on s2, x split on s0
    cudaEventRecord(g_ctx.e0, s0);
    cudaStreamWaitEvent(s2, g_ctx.e0, 0);
    {
        dim3 blk(32, 8);
        transpose_split<<<dim3(3 * INNER / 32, DIM / 32, 1), blk, 0, s2>>>(
            w_qkv, Bp + B_WQTH, Bp + B_WQTL, DIM, 3 * INNER, 0, 0, nullptr, 0.f, 0);
        cudaEventRecord(g_ctx.e5, s2);   // wqkv transpose done
        transpose_split<<<dim3(DIM / 32, INNER / 32, 1), blk, 0, s2>>>(
            w_out, Bp + B_WOTH, Bp + B_WOTL, INNER, DIM, 0, 0, nullptr, 0.f, 0);
    }
    split_f32<<<(int)((SZ_Y + 255) / 256), 256, 0, s0>>>(x, Bp + B_XH, Bp + B_XL, SZ_Y);
    cudaStreamWaitEvent(s0, g_ctx.e5, 0);

    // 1a. qkv GEMM, q+k columns (N=1024)
    tcg<128, 128, true, 512>(s0, Bp + B_XH, Bp + B_XL, Bp + B_WQTH, Bp + B_WQTL,
                             nullptr, nullptr, nullptr, nullptr, nullptr, nullptr,
                             BB * NTOK, 2 * INNER, DIM, DIM, 0, 0,
                             0, 0, 0, 0, 1, 1, 1.f, 0.f, 64);
    cudaEventRecord(g_ctx.e1, s0);

    // s2 (after w_out transpose + e1): landmarks, attn2, pinv — concurrent with qkv_v + fa3 on s0
    cudaStreamWaitEvent(s2, g_ctx.e1, 0);
    landmark_split_bf<<<(int)((SZ_LM + 255) / 256), 256, 0, s2>>>(Bp + B_QH, Bp + B_QL, Bp + B_QLMH, Bp + B_QLML);
    landmark_split_bf<<<(int)((SZ_LM + 255) / 256), 256, 0, s2>>>(Bp + B_KH, Bp + B_KL, Bp + B_KLMH, Bp + B_KLML);
    attn_gemm_softmax<<<dim3(MLM / 64, BH), 256, 81920, s2>>>(
        Bp + B_QLMH, Bp + B_QLML, Bp + B_KLMH, Bp + B_KLML,
        F + F_A2, Bp + B_A2H, Bp + B_A2L, SL, SL, SA2);
    cudaEventRecord(g_ctx.e5, s2);   // landmarks+attn2 done (reuse e5; prior use consumed)

    norm_init_kernel<<<1, 1, 0, s2>>>(nrm);
    pinv_norm_kernel<<<BH, 256, 0, s2>>>(F + F_A2, nrm);
    {
        int blocks = (int)((SZ_A2 + 255) / 256);
        scale_split<<<blocks, 256, 0, s2>>>(F + F_A2, Bp + B_Z0TH, Bp + B_Z0TL, SZ_A2, nrm);
        transpose_split<<<dim3(8, 8, BH), dim3(32, 8), 0, s2>>>(
            F + F_A2, Bp + B_Z0H, Bp + B_Z0L, MLM, MLM, SA2, SA2, nrm, 0.f, 0);
    }

    bf16 *zch = Bp + B_Z0H,  *zcl = Bp + B_Z0L,  *zcth = Bp + B_Z0TH, *zctl = Bp + B_Z0TL;
    bf16 *znh = Bp + B_Z1H,  *znl = Bp + B_Z1L,  *znth = Bp + B_Z1TH, *zntl = Bp + B_Z1TL;

    for (int it = 0; it < 6; it++) {
#define PINV_STEP(S) \
        tcg<64, 128, S, 256>(s2, Bp + B_A2H, Bp + B_A2L, zcth, zctl, \
                    nullptr, Bp + B_XZH, Bp + B_XZL, Bp + B_T1TH, Bp + B_T1TL, nullptr, \
                    MLM, MLM, MLM, MLM, MLM, MLM, SA2, SA2, SA2, SA2, BH, 1, 1.f, 7.f, 2|4|8|16); \
        tcg<64, 128, S, 256>(s2, Bp + B_XZH, Bp + B_XZL, Bp + B_T1TH, Bp + B_T1TL, \
                    nullptr, nullptr, nullptr, Bp + B_T2TH, Bp + B_T2TL, nullptr, \
                    MLM, MLM, MLM, MLM, MLM, MLM, SA2, SA2, 0, SA2, BH, 1, 1.f, 15.f, 4|8); \
        tcg<64, 128, S, 256>(s2, Bp + B_XZH, Bp + B_XZL, Bp + B_T2TH, Bp + B_T2TL, \
                    nullptr, nullptr, nullptr, Bp + B_T3TH, Bp + B_T3TL, nullptr, \
                    MLM, MLM, MLM, MLM, MLM, MLM, SA2, SA2, 0, SA2, BH, 1, 1.f, 13.f, 4|8); \
        tcg<64, 128, S, 256>(s2, zch, zcl, Bp + B_T3TH, Bp + B_T3TL, \
                    nullptr, znh, znl, znth, zntl, nullptr, \
                    MLM, MLM, MLM, MLM, MLM, MLM, SA2, SA2, SA2, SA2, BH, 1, 0.25f, 0.f, 2|4);
        if (it < 5) { PINV_STEP(false) } else { PINV_STEP(true) }
#undef PINV_STEP
        bf16* t;
        t = zch;  zch  = znh;  znh  = t;   t = zcl;  zcl  = znl;  znl  = t;
        t = zcth; zcth = znth; znth = t;   t = zctl; zctl = zntl; zntl = t;
    }
    cudaEventRecord(g_ctx.e2, s2);

    // 1b. qkv GEMM, v columns (N=512, n_base=1024) — concurrent with landmarks/attn2/pinv
    tcg<128, 128, true, 512>(s0, Bp + B_XH, Bp + B_XL,
                             Bp + B_WQTH + (ll)2 * INNER * DIM, Bp + B_WQTL + (ll)2 * INNER * DIM,
                             nullptr, nullptr, nullptr, nullptr, nullptr, nullptr,
                             BB * NTOK, INNER, DIM, DIM, 0, 2 * INNER,
                             0, 0, 0, 0, 1, 1, 1.f, 0.f, 64);

    // 3. fa3 (s0) needs q-landmarks (s2) + k/v (s0)
    cudaStreamWaitEvent(s0, g_ctx.e5, 0);
    fa3_av<<<dim3(MLM / 64, BH), 512, FA3_SMEM, s0>>>(
        Bp + B_QLMH, Bp + B_QLML, Bp + B_KH, Bp + B_KL,
        Bp + B_VTH, Bp + B_VTL, Bp + B_AVTH, Bp + B_AVTL,
        SL, SH, SH, SL);

    // join pinv
    cudaStreamWaitEvent(s0, g_ctx.e2, 0);

    // 4. zav^T = (z @ av)^T
    tcg<64, 64, true, 256>(s0, zch, zcl, Bp + B_AVTH, Bp + B_AVTL,
                           nullptr, nullptr, nullptr, Bp + B_ZVTH, Bp + B_ZVTL, nullptr,
                           MLM, DH, MLM, MLM, DH, MLM, SA2, SL, 0, SL, BH, 1, 1.f, 0.f, 4);

    // 5. a1o chunk0 then chunk1; out-proj chunk0 on s2 overlaps chunk1
    attn1_outh<<<dim3(NTOK / 64, 16), 512, A1O_SMEM, s0>>>(
        Bp + B_QH, Bp + B_KLMH, Bp + B_KLML,
        Bp + B_ZVTH, Bp + B_ZVTL, F + F_V, res_k,
        Bp + B_YH, Bp + B_YL, SH, SL, SL, SH, 0);
    cudaEventRecord(g_ctx.e3, s0);

    attn1_outh<<<dim3(NTOK / 64, 16), 512, A1O_SMEM, s0>>>(
        Bp + B_QH, Bp + B_KLMH, Bp + B_KLML,
        Bp + B_ZVTH, Bp + B_ZVTL, F + F_V, res_k,
        Bp + B_YH, Bp + B_YL, SH, SL, SL, SH, 16);

    cudaStreamWaitEvent(s2, g_ctx.e3, 0);
    tcg<128, 128, true, 512>(s2, Bp + B_YH, Bp + B_YL, Bp + B_WOTH, Bp + B_WOTL,
                             out, nullptr, nullptr, nullptr, nullptr, b_out,
                             2 * NTOK, DIM, INNER, INNER, DIM, 0, 0, 0, 0, 0, 1, 1, 1.f, 0.f, 1);
    cudaEventRecord(g_ctx.e4, s2);

    tcg<128, 128, true, 512>(s0, Bp + B_YH + (ll)2 * NTOK * INNER, Bp + B_YL + (ll)2 * NTOK * INNER,
                             Bp + B_WOTH, Bp + B_WOTL,
                             out + (ll)2 * NTOK * DIM, nullptr, nullptr, nullptr, nullptr, b_out,
                             2 * NTOK, DIM, INNER, INNER, DIM, 0, 0, 0, 0, 0, 1, 1, 1.f, 0.f, 1);

    cudaStreamWaitEvent(s0, g_ctx.e4, 0);
}

// round 12
// speedup vs baseline: 1.0032x; 1.0032x over previous
#include <cuda_runtime.h>
#include <cuda_bf16.h>
#include <cstdint>

typedef __nv_bfloat16 bf16;
typedef long long ll;

#define BB    4
#define NTOK  4096
#define DIM   512
#define H     8
#define DH    64
#define MLM   256
#define LGRP  16
#define BH    32
#define INNER 512

// ---------------- sizes ----------------
static const ll SZ_Y     = (ll)BB*NTOK*INNER;
static const ll SZ_HEADS = (ll)BH*NTOK*DH;
static const ll SZ_LM    = (ll)BH*MLM*DH;
static const ll SZ_A2    = (ll)BH*MLM*MLM;

// fp32 scratch
static const ll F_V    = 0;
static const ll F_A2   = F_V    + SZ_HEADS;
static const ll F_TOTAL= F_A2   + SZ_A2;

// bf16 scratch
static const ll B_XH   = 0;
static const ll B_XL   = B_XH   + SZ_Y;
static const ll B_WQTH = B_XL   + SZ_Y;
static const ll B_WQTL = B_WQTH + (ll)DIM*3*INNER;
static const ll B_WOTH = B_WQTL + (ll)DIM*3*INNER;
static const ll B_WOTL = B_WOTH + (ll)DIM*INNER;
static const ll B_QH   = B_WOTL + (ll)DIM*INNER;
static const ll B_QL   = B_QH   + SZ_HEADS;
static const ll B_KH   = B_QL   + SZ_HEADS;
static const ll B_KL   = B_KH   + SZ_HEADS;
static const ll B_VTH  = B_KL   + SZ_HEADS;
static const ll B_VTL  = B_VTH  + SZ_HEADS;
static const ll B_QLMH = B_VTL  + SZ_HEADS;
static const ll B_QLML = B_QLMH + SZ_LM;
static const ll B_KLMH = B_QLML + SZ_LM;
static const ll B_KLML = B_KLMH + SZ_LM;
static const ll B_A2H  = B_KLML + SZ_LM;
static const ll B_A2L  = B_A2H  + SZ_A2;
static const ll B_Z0H  = B_A2L  + SZ_A2;
static const ll B_Z0L  = B_Z0H  + SZ_A2;
static const ll B_Z0TH = B_Z0L  + SZ_A2;
static const ll B_Z0TL = B_Z0TH + SZ_A2;
static const ll B_Z1H  = B_Z0TL + SZ_A2;
static const ll B_Z1L  = B_Z1H  + SZ_A2;
static const ll B_Z1TH = B_Z1L  + SZ_A2;
static const ll B_Z1TL = B_Z1TH + SZ_A2;
static const ll B_XZH  = B_Z1TL + SZ_A2;
static const ll B_XZL  = B_XZH  + SZ_A2;
static const ll B_T1TH = B_XZL  + SZ_A2;
static const ll B_T1TL = B_T1TH + SZ_A2;
static const ll B_T2TH = B_T1TL + SZ_A2;
static const ll B_T2TL = B_T2TH + SZ_A2;
static const ll B_T3TH = B_T2TL + SZ_A2;
static const ll B_T3TL = B_T3TH + SZ_A2;
static const ll B_AVTH = B_T3TL + SZ_A2;
static const ll B_AVTL = B_AVTH + SZ_LM;
static const ll B_ZVTH = B_AVTL + SZ_LM;
static const ll B_ZVTL = B_ZVTH + SZ_LM;
static const ll B_YH   = B_ZVTL + SZ_LM;
static const ll B_YL   = B_YH   + SZ_Y;
static const ll B_TOTAL= B_YL   + SZ_Y;

__device__ __align__(16) float g_f32[F_TOTAL];
__device__ __align__(16) bf16  g_bf[B_TOTAL];
__device__ float g_norm[2];

// ---------------- stream/event context ----------------
struct StreamCtx {
    cudaStream_t s2;
    cudaEvent_t e0, e1, e2, e3, e4;
    StreamCtx() {
        cudaStreamCreateWithFlags(&s2, cudaStreamNonBlocking);
        cudaEventCreateWithFlags(&e0, cudaEventDisableTiming);
        cudaEventCreateWithFlags(&e1, cudaEventDisableTiming);
        cudaEventCreateWithFlags(&e2, cudaEventDisableTiming);
        cudaEventCreateWithFlags(&e3, cudaEventDisableTiming);
        cudaEventCreateWithFlags(&e4, cudaEventDisableTiming);
    }
};
static StreamCtx g_ctx;

// ---------------- helpers ----------------
__device__ __forceinline__ uint32_t smem_u32(const void* p) {
    uint32_t a;
    asm("{ .reg .u64 t; cvta.to.shared.u64 t, %1; cvt.u32.u64 %0, t; }" : "=r"(a) : "l"(p));
    return a;
}
__device__ __forceinline__ void cp16(uint32_t s, const void* g) {
    asm volatile("cp.async.cg.shared.global [%0], [%1], 16;" :: "r"(s), "l"(g));
}
#define CP_COMMIT asm volatile("cp.async.commit_group;" ::: "memory")
#define CP_WAIT0  asm volatile("cp.async.wait_group 0;" ::: "memory")

#define LDSM4(R, A) \
    asm volatile("ldmatrix.sync.aligned.m8n8.x4.shared.b16 {%0,%1,%2,%3}, [%4];" \
        : "=r"((R)[0]), "=r"((R)[1]), "=r"((R)[2]), "=r"((R)[3]) : "r"(A))

#define MMA16816(D, Aa, Bb) \
    asm volatile("mma.sync.aligned.m16n8k16.row.col.f32.bf16.bf16.f32 " \
        "{%0,%1,%2,%3}, {%4,%5,%6,%7}, {%8,%9}, {%0,%1,%2,%3};" \
        : "+f"((D)[0]), "+f"((D)[1]), "+f"((D)[2]), "+f"((D)[3]) \
        : "r"((Aa)[0]), "r"((Aa)[1]), "r"((Aa)[2]), "r"((Aa)[3]), \
          "r"((Bb)[0]), "r"((Bb)[1]))

#define SWZ128(o) ((o) ^ (((o) >> 3) & 0x70))

__device__ __forceinline__ void split2(float v, bf16& h, bf16& l) {
    h = __float2bfloat16(v);
    l = __float2bfloat16(v - __bfloat162float(h));
}
__device__ __forceinline__ uint32_t packh2(float a, float b) {
    __nv_bfloat162 p; p.x = __float2bfloat16(a); p.y = __float2bfloat16(b);
    return *(uint32_t*)&p;
}
__device__ __forceinline__ uint32_t packl2(float a, float b) {
    __nv_bfloat162 p;
    p.x = __float2bfloat16(a - __bfloat162float(__float2bfloat16(a)));
    p.y = __float2bfloat16(b - __bfloat162float(__float2bfloat16(b)));
    return *(uint32_t*)&p;
}

// ---------------- generic split-bf16 HMMA NT GEMM ----------------
template<int TM, int TN, bool SPLIT, int NT>
__device__ __forceinline__ void load_stage(uint32_t sbase,
    const bf16* pAh, const bf16* pAl, const bf16* pBh, const bf16* pBl,
    int K, int k0, int tid)
{
    constexpr uint32_t OAL = TM * 128;
    constexpr uint32_t OBH = (SPLIT ? 2 : 1) * TM * 128;
    constexpr uint32_t OBL = OBH + TN * 128;
#pragma unroll
    for (int i = 0; i < TM * 8 / NT; i++) {
        int idx = tid + i * NT;
        int r = idx >> 3, c = idx & 7;
        uint32_t so = SWZ128((uint32_t)(r * 128 + c * 16));
        ll go = (ll)r * K + k0 + c * 8;
        cp16(sbase + so, pAh + go);
        if (SPLIT) cp16(sbase + OAL + so, pAl + go);
    }
#pragma unroll
    for (int i = 0; i < TN * 8 / NT; i++) {
        int idx = tid + i * NT;
        int r = idx >> 3, c = idx & 7;
        uint32_t so = SWZ128((uint32_t)(r * 128 + c * 16));
        ll go = (ll)r * K + k0 + c * 8;
        cp16(sbase + OBH + so, pBh + go);
        if (SPLIT) cp16(sbase + OBL + so, pBl + go);
    }
}

template<int TM, int TN, bool SPLIT, int NT>
__global__ void __launch_bounds__(NT, (NT == 256 && TM == 64) ? 2 : 1) gemm_mma(
    const bf16* __restrict__ Ah, const bf16* __restrict__ Al,
    const bf16* __restrict__ Bh, const bf16* __restrict__ Bl,
    float* __restrict__ C, bf16* __restrict__ Ch, bf16* __restrict__ Cl,
    bf16* __restrict__ CTh, bf16* __restrict__ CTl,
    const float* __restrict__ bias,
    int K, int Kc, int nbatch, int ldc, int ldct,
    ll sA, ll sB, ll sC, ll sCT,
    float alpha, float diagc, int flags)
{
    extern __shared__ char smem[];
    constexpr int WR = (NT == 512) ? 4 : 2;
    constexpr int MI = TM / WR / 16;
    constexpr int NG = TN / 4 / 8;
    constexpr uint32_t OBH = (SPLIT ? 2 : 1) * TM * 128;
    constexpr uint32_t OBL = OBH + TN * 128;
    constexpr int STAGE = (SPLIT ? 2 : 1) * (TM + TN) * 128;

    const int tid = threadIdx.x, wid = tid >> 5, lane = tid & 31;
    const int bz = blockIdx.z % nbatch;
    const int koff = (blockIdx.z / nbatch) * Kc;
    const int m0 = blockIdx.y * TM, n0 = blockIdx.x * TN;
    const int wm = (wid % WR) * (TM / WR);
    const int wn = (wid / WR) * (TN / 4);
    uint32_t sb = smem_u32(smem);

    const bf16* pAh = Ah + bz * sA + (ll)m0 * K + koff;
    const bf16* pAl = SPLIT ? (Al + bz * sA + (ll)m0 * K + koff) : pAh;
    const bf16* pBh = Bh + bz * sB + (ll)n0 * K + koff;
    const bf16* pBl = SPLIT ? (Bl + bz * sB + (ll)n0 * K + koff) : pBh;

    float acc[MI][NG][4];
#pragma unroll
    for (int a = 0; a < MI; a++)
#pragma unroll
        for (int b = 0; b < NG; b++)
#pragma unroll
            for (int c = 0; c < 4; c++) acc[a][b][c] = 0.f;

    const int nch = Kc >> 6;
    load_stage<TM, TN, SPLIT, NT>(sb, pAh, pAl, pBh, pBl, K, 0, tid);
    CP_COMMIT;

    for (int ck = 0; ck < nch; ck++) {
        CP_WAIT0;
        __syncthreads();
        if (ck + 1 < nch) {
            load_stage<TM, TN, SPLIT, NT>(sb + ((ck + 1) & 1) * STAGE, pAh, pAl, pBh, pBl, K, (ck + 1) * 64, tid);
            CP_COMMIT;
        }
        uint32_t s = sb + (ck & 1) * STAGE;
#pragma unroll
        for (int ks = 0; ks < 4; ks++) {
            uint32_t aH[MI][4], aL[MI][4];
#pragma unroll
            for (int mi = 0; mi < MI; mi++) {
                int row = wm + mi * 16 + (lane & 15);
                int c16 = ks * 2 + (lane >> 4);
                uint32_t off = SWZ128((uint32_t)(row * 128 + c16 * 16));
                LDSM4(aH[mi], s + off);
                if (SPLIT) LDSM4(aL[mi], s + TM * 128 + off);
            }
            uint32_t bH[NG][2], bL[NG][2];
#pragma unroll
            for (int bj = 0; bj < NG / 2; bj++) {
                int row = wn + bj * 16 + (lane & 15);
                int c16 = ks * 2 + (lane >> 4);
                uint32_t off = SWZ128((uint32_t)(row * 128 + c16 * 16));
                uint32_t t[4];
                LDSM4(t, s + OBH + off);
                bH[bj * 2][0] = t[0]; bH[bj * 2 + 1][0] = t[1];
                bH[bj * 2][1] = t[2]; bH[bj * 2 + 1][1] = t[3];
                if (SPLIT) {
                    LDSM4(t, s + OBL + off);
                    bL[bj * 2][0] = t[0]; bL[bj * 2 + 1][0] = t[1];
                    bL[bj * 2][1] = t[2]; bL[bj * 2 + 1][1] = t[3];
                }
            }
#pragma unroll
            for (int mi = 0; mi < MI; mi++)
#pragma unroll
                for (int g = 0; g < NG; g++) MMA16816(acc[mi][g], aH[mi], bH[g]);
            if (SPLIT) {
#pragma unroll
                for (int mi = 0; mi < MI; mi++)
#pragma unroll
                    for (int g = 0; g < NG; g++) MMA16816(acc[mi][g], aH[mi], bL[g]);
#pragma unroll
                for (int mi = 0; mi < MI; mi++)
#pragma unroll
                    for (int g = 0; g < NG; g++) MMA16816(acc[mi][g], aL[mi], bH[g]);
            }
        }
    }

    const bool diagT = (flags & 8) != 0;
    const bool diagN = diagT && !(flags & 16);
#pragma unroll
    for (int mi = 0; mi < MI; mi++) {
#pragma unroll
        for (int g = 0; g < NG; g++) {
#pragma unroll
            for (int half = 0; half < 2; half++) {
                int r = m0 + wm + mi * 16 + (lane >> 2) + half * 8;
                int n = n0 + wn + g * 8 + (lane & 3) * 2;
                float a0 = acc[mi][g][half * 2 + 0];
                float a1v = acc[mi][g][half * 2 + 1];
                if (flags & 64) {
                    int nq = n + ldct;
                    int sel = nq >> 9;
                    int hh = (nq >> 6) & 7;
                    int d  = nq & 63;
                    int b  = r >> 12, t = r & 4095;
                    ll hidx = ((ll)((b << 3) + hh) * NTOK + t) * 64 + d;
                    if (sel == 0) {
                        *(uint32_t*)(g_bf + B_QH + hidx) = packh2(a0 * 0.125f, a1v * 0.125f);
                        *(uint32_t*)(g_bf + B_QL + hidx) = packl2(a0 * 0.125f, a1v * 0.125f);
                    } else if (sel == 1) {
                        *(uint32_t*)(g_bf + B_KH + hidx) = packh2(a0, a1v);
                        *(uint32_t*)(g_bf + B_KL + hidx) = packl2(a0, a1v);
                    } else {
                        *(float2*)(g_f32 + F_V + hidx) = make_float2(a0, a1v);
                        bf16 h0, l0, h1, l1;
                        split2(a0, h0, l0); split2(a1v, h1, l1);
                        ll vt = ((ll)((b << 3) + hh) * 64 + d) * NTOK + t;
                        g_bf[B_VTH + vt] = h0;        g_bf[B_VTL + vt] = l0;
                        g_bf[B_VTH + vt + NTOK] = h1; g_bf[B_VTL + vt + NTOK] = l1;
                    }
                    continue;
                }
                if (flags & 3) {
                    float n0v = diagN ? ((r == n)     ? diagc : 0.f) - a0  : alpha * a0;
                    float n1v = diagN ? ((r == n + 1) ? diagc : 0.f) - a1v : alpha * a1v;
                    if (bias) { n0v += bias[n]; n1v += bias[n + 1]; }
                    ll o = bz * sC + (ll)r * ldc + n;
                    if (flags & 1) {
                        if (flags & 32) { atomicAdd(C + o, n0v); atomicAdd(C + o + 1, n1v); }
                        else *(float2*)(C + o) = make_float2(n0v, n1v);
                    }
                    if (flags & 2) {
                        *(uint32_t*)(Ch + o) = packh2(n0v, n1v);
                        *(uint32_t*)(Cl + o) = packl2(n0v, n1v);
                    }
                }
                if (flags & 4) {
                    float t0v = diagT ? ((r == n)     ? diagc : 0.f) - a0  : alpha * a0;
                    float t1v = diagT ? ((r == n + 1) ? diagc : 0.f) - a1v : alpha * a1v;
                    bf16 h0, l0, h1, l1;
                    split2(t0v, h0, l0); split2(t1v, h1, l1);
                    ll ot0 = bz * sCT + (ll)n * ldct + r;
                    ll ot1 = bz * sCT + (ll)(n + 1) * ldct + r;
                    CTh[ot0] = h0; CTl[ot0] = l0;
                    CTh[ot1] = h1; CTl[ot1] = l1;
                }
            }
        }
    }
}

// ---------------- fused GEMM + row softmax (attn2) ----------------
__global__ void __launch_bounds__(256, 1) attn_gemm_softmax(
    const bf16* __restrict__ Ah, const bf16* __restrict__ Al,
    const bf16* __restrict__ Bh, const bf16* __restrict__ Bl,
    float* __restrict__ C32, bf16* __restrict__ Ch, bf16* __restrict__ Cl,
    ll sA, ll sB, ll sC)
{
    extern __shared__ char smem[];
    __shared__ float redm[2][32][4];
    __shared__ float reds[2][32][4];
    const int tid = threadIdx.x, wid = tid >> 5, lane = tid & 31;
    const int bz = blockIdx.y;
    const int m0 = blockIdx.x * 64;
    const int wm = (wid & 1) * 32;
    const int wn = (wid >> 1) * 64;
    uint32_t sb = smem_u32(smem);

    const bf16* pAh = Ah + bz * sA + (ll)m0 * 64;
    const bf16* pAl = Al + bz * sA + (ll)m0 * 64;
    const bf16* pBh = Bh + bz * sB;
    const bf16* pBl = Bl + bz * sB;

#pragma unroll
    for (int i = 0; i < 2; i++) {
        int idx = tid + i * 256;
        int r = idx >> 3, c = idx & 7;
        uint32_t so = SWZ128((uint32_t)(r * 128 + c * 16));
        cp16(sb + so, pAh + (ll)r * 64 + c * 8);
        cp16(sb + 8192 + so, pAl + (ll)r * 64 + c * 8);
    }
#pragma unroll
    for (int i = 0; i < 8; i++) {
        int idx = tid + i * 256;
        int r = idx >> 3, c = idx & 7;
        uint32_t so = SWZ128((uint32_t)(r * 128 + c * 16));
        cp16(sb + 16384 + so, pBh + (ll)r * 64 + c * 8);
        cp16(sb + 49152 + so, pBl + (ll)r * 64 + c * 8);
    }
    CP_COMMIT;

    float acc[2][8][4];
#pragma unroll
    for (int a = 0; a < 2; a++)
#pragma unroll
        for (int b = 0; b < 8; b++)
#pragma unroll
            for (int c = 0; c < 4; c++) acc[a][b][c] = 0.f;

    CP_WAIT0;
    __syncthreads();
#pragma unroll
    for (int ks = 0; ks < 4; ks++) {
        uint32_t aH[2][4], aL[2][4];
#pragma unroll
        for (int mi = 0; mi < 2; mi++) {
            int row = wm + mi * 16 + (lane & 15);
            int c16 = ks * 2 + (lane >> 4);
            uint32_t off = SWZ128((uint32_t)(row * 128 + c16 * 16));
            LDSM4(aH[mi], sb + off);
            LDSM4(aL[mi], sb + 8192 + off);
        }
        uint32_t bHf[8][2], bLf[8][2];
#pragma unroll
        for (int bj = 0; bj < 4; bj++) {
            int row = wn + bj * 16 + (lane & 15);
            int c16 = ks * 2 + (lane >> 4);
            uint32_t off = SWZ128((uint32_t)(row * 128 + c16 * 16));
            uint32_t t[4];
            LDSM4(t, sb + 16384 + off);
            bHf[bj * 2][0] = t[0]; bHf[bj * 2 + 1][0] = t[1];
            bHf[bj * 2][1] = t[2]; bHf[bj * 2 + 1][1] = t[3];
            LDSM4(t, sb + 49152 + off);
            bLf[bj * 2][0] = t[0]; bLf[bj * 2 + 1][0] = t[1];
            bLf[bj * 2][1] = t[2]; bLf[bj * 2 + 1][1] = t[3];
        }
#pragma unroll
        for (int mi = 0; mi < 2; mi++)
#pragma unroll
            for (int g = 0; g < 8; g++) MMA16816(acc[mi][g], aH[mi], bHf[g]);
#pragma unroll
        for (int mi = 0; mi < 2; mi++)
#pragma unroll
            for (int g = 0; g < 8; g++) MMA16816(acc[mi][g], aH[mi], bLf[g]);
#pragma unroll
        for (int mi = 0; mi < 2; mi++)
#pragma unroll
            for (int g = 0; g < 8; g++) MMA16816(acc[mi][g], aL[mi], bHf[g]);
    }

    float mx[2][2];
#pragma unroll
    for (int mi = 0; mi < 2; mi++)
#pragma unroll
        for (int half = 0; half < 2; half++) {
            float m = -1e30f;
#pragma unroll
            for (int g = 0; g < 8; g++) {
                m = fmaxf(m, acc[mi][g][half * 2]);
                m = fmaxf(m, acc[mi][g][half * 2 + 1]);
            }
            m = fmaxf(m, __shfl_xor_sync(0xffffffffu, m, 1));
            m = fmaxf(m, __shfl_xor_sync(0xffffffffu, m, 2));
            mx[mi][half] = m;
        }
    if ((lane & 3) == 0) {
#pragma unroll
        for (int mi = 0; mi < 2; mi++)
#pragma unroll
            for (int half = 0; half < 2; half++)
                redm[wid & 1][mi * 16 + (lane >> 2) + half * 8][wid >> 1] = mx[mi][half];
    }
    __syncthreads();
    float sm[2][2];
#pragma unroll
    for (int mi = 0; mi < 2; mi++)
#pragma unroll
        for (int half = 0; half < 2; half++) {
            int ri = mi * 16 + (lane >> 2) + half * 8;
            float m = fmaxf(fmaxf(redm[wid & 1][ri][0], redm[wid & 1][ri][1]),
                            fmaxf(redm[wid & 1][ri][2], redm[wid & 1][ri][3]));
            float s = 0.f;
#pragma unroll
            for (int g = 0; g < 8; g++) {
                float e0 = __expf(acc[mi][g][half * 2] - m);
                float e1 = __expf(acc[mi][g][half * 2 + 1] - m);
                acc[mi][g][half * 2] = e0; acc[mi][g][half * 2 + 1] = e1;
                s += e0 + e1;
            }
            s += __shfl_xor_sync(0xffffffffu, s, 1);
            s += __shfl_xor_sync(0xffffffffu, s, 2);
            sm[mi][half] = s;
        }
    if ((lane & 3) == 0) {
#pragma unroll
        for (int mi = 0; mi < 2; mi++)
#pragma unroll
            for (int half = 0; half < 2; half++)
                reds[wid & 1][mi * 16 + (lane >> 2) + half * 8][wid >> 1] = sm[mi][half];
    }
    __syncthreads();
#pragma unroll
    for (int mi = 0; mi < 2; mi++)
#pragma unroll
        for (int half = 0; half < 2; half++) {
            int ri = mi * 16 + (lane >> 2) + half * 8;
            float tot = reds[wid & 1][ri][0] + reds[wid & 1][ri][1]
                      + reds[wid & 1][ri][2] + reds[wid & 1][ri][3];
            float inv = 1.f / tot;
            int r = m0 + wm + ri;
#pragma unroll
            for (int g = 0; g < 8; g++) {
                int n = wn + g * 8 + (lane & 3) * 2;
                float v0 = acc[mi][g][half * 2] * inv;
                float v1 = acc[mi][g][half * 2 + 1] * inv;
                ll o = bz * sC + (ll)r * 256 + n;
                *(uint32_t*)(Ch + o) = packh2(v0, v1);
                *(uint32_t*)(Cl + o) = packl2(v0, v1);
                *(float2*)(C32 + o) = make_float2(v0, v1);
            }
        }
}

// ---------------- fused attn3 + softmax + @v -> avT (512 thr; 2-term) ----------------
#define VROW 272
__global__ void __launch_bounds__(512, 1) fa3_av(
    const bf16* __restrict__ Qh, const bf16* __restrict__ Ql,
    const bf16* __restrict__ Kh, const bf16* __restrict__ Kl,
    const bf16* __restrict__ Vth, const bf16* __restrict__ Vtl,
    bf16* __restrict__ AVTh, bf16* __restrict__ AVTl,
    ll sQ, ll sK, ll sVT, ll sAVT)
{
    extern __shared__ char smem[];
    __shared__ float Os[64 * 68];
    __shared__ float rsm[64];
    const int tid = threadIdx.x, wid = tid >> 5, lane = tid & 31;
    const int bz = blockIdx.y;
    const int m0 = blockIdx.x * 64;
    const int wm = (wid & 3) * 16;
    const int wn = (wid >> 2) * 32;
    uint32_t sb = smem_u32(smem);
    constexpr uint32_t ST0 = 16384;
    constexpr uint32_t OVT = 32768;
    constexpr uint32_t VLo = OVT + 64 * VROW;
    constexpr uint32_t STG = OVT + 2 * 64 * VROW;

    for (int i = tid; i < 64 * 68; i += 512) Os[i] = 0.f;
    if (tid < 64) rsm[tid] = 0.f;

    const bf16* pQh = Qh + bz * sQ + (ll)m0 * 64;
    const bf16* pKh = Kh + bz * sK;
    const bf16* pKl = Kl + bz * sK;
    const bf16* pVh = Vth + bz * sVT;
    const bf16* pVl = Vtl + bz * sVT;

    {
        int r = tid >> 3, c = tid & 7;
        uint32_t so = SWZ128((uint32_t)(r * 128 + c * 16));
        cp16(sb + so, pQh + (ll)r * 64 + c * 8);
    }
    {
        uint32_t s = sb + ST0;
#pragma unroll
        for (int i = 0; i < 2; i++) {
            int idx = tid + i * 512;
            int r = idx >> 3, c = idx & 7;
            uint32_t so = SWZ128((uint32_t)(r * 128 + c * 16));
            ll g = (ll)r * 64 + c * 8;
            cp16(s + so, pKh + g);
            cp16(s + 16384 + so, pKl + g);
        }
#pragma unroll
        for (int i = 0; i < 2; i++) {
            int idx = tid + i * 512;
            int r = idx >> 4, c = idx & 15;
            uint32_t so = (uint32_t)(r * VROW + c * 16);
            ll g = (ll)r * NTOK + c * 8;
            cp16(s + OVT + so, pVh + g);
            cp16(s + VLo + so, pVl + g);
        }
    }
    CP_COMMIT;

    float acc_o[8][4];
#pragma unroll
    for (int b = 0; b < 8; b++)
#pragma unroll
        for (int c = 0; c < 4; c++) acc_o[b][c] = 0.f;
    float rs[2] = {0.f, 0.f};

    for (int ck = 0; ck < 32; ck++) {
        CP_WAIT0;
        __syncthreads();
        if (ck + 1 < 32) {
            uint32_t s = sb + ST0 + ((ck + 1) & 1) * STG;
            int tok = (ck + 1) * 128;
#pragma unroll
            for (int i = 0; i < 2; i++) {
                int idx = tid + i * 512;
                int r = idx >> 3, c = idx & 7;
                uint32_t so = SWZ128((uint32_t)(r * 128 + c * 16));
                ll g = (ll)(tok + r) * 64 + c * 8;
                cp16(s + so, pKh + g);
                cp16(s + 16384 + so, pKl + g);
            }
#pragma unroll
            for (int i = 0; i < 2; i++) {
                int idx = tid + i * 512;
                int r = idx >> 4, c = idx & 15;
                uint32_t so = (uint32_t)(r * VROW + c * 16);
                ll g = (ll)r * NTOK + tok + c * 8;
                cp16(s + OVT + so, pVh + g);
                cp16(s + VLo + so, pVl + g);
            }
            CP_COMMIT;
        }
        uint32_t s = sb + ST0 + (ck & 1) * STG;

        float accl[4][4];
#pragma unroll
        for (int b = 0; b < 4; b++)
#pragma unroll
            for (int c = 0; c < 4; c++) accl[b][c] = 0.f;
#pragma unroll
        for (int ks = 0; ks < 4; ks++) {
            int c16 = ks * 2 + (lane >> 4);
            uint32_t aH[4];
            {
                int row = wm + (lane & 15);
                uint32_t off = SWZ128((uint32_t)(row * 128 + c16 * 16));
                LDSM4(aH, sb + off);
            }
            uint32_t bHf[4][2], bLf[4][2];
#pragma unroll
            for (int bj = 0; bj < 2; bj++) {
                int row = wn + bj * 16 + (lane & 15);
                uint32_t off = SWZ128((uint32_t)(row * 128 + c16 * 16));
                uint32_t t[4];
                LDSM4(t, s + off);
                bHf[bj * 2][0] = t[0]; bHf[bj * 2 + 1][0] = t[1];
                bHf[bj * 2][1] = t[2]; bHf[bj * 2 + 1][1] = t[3];
                LDSM4(t, s + 16384 + off);
                bLf[bj * 2][0] = t[0]; bLf[bj * 2 + 1][0] = t[1];
                bLf[bj * 2][1] = t[2]; bLf[bj * 2 + 1][1] = t[3];
            }
#pragma unroll
            for (int g = 0; g < 4; g++) MMA16816(accl[g], aH, bHf[g]);
#pragma unroll
            for (int g = 0; g < 4; g++) MMA16816(accl[g], aH, bLf[g]);
        }
#pragma unroll
        for (int half = 0; half < 2; half++) {
            float srow = 0.f;
#pragma unroll
            for (int g = 0; g < 4; g++) {
                float e0 = __expf(accl[g][half * 2]);
                float e1 = __expf(accl[g][half * 2 + 1]);
                accl[g][half * 2] = e0;
                accl[g][half * 2 + 1] = e1;
                srow += e0 + e1;
            }
            rs[half] += srow;
        }
#pragma unroll
        for (int kk = 0; kk < 2; kk++) {
            uint32_t aPh[4];
            aPh[0] = packh2(accl[2 * kk][0], accl[2 * kk][1]);
            aPh[1] = packh2(accl[2 * kk][2], accl[2 * kk][3]);
            aPh[2] = packh2(accl[2 * kk + 1][0], accl[2 * kk + 1][1]);
            aPh[3] = packh2(accl[2 * kk + 1][2], accl[2 * kk + 1][3]);
#pragma unroll
            for (int bj = 0; bj < 4; bj++) {
                uint32_t addr = s + OVT + (uint32_t)((bj * 16 + (lane & 15)) * VROW)
                              + (uint32_t)((wn + kk * 16) * 2 + (lane >> 4) * 16);
                uint32_t t[4], u[4];
                LDSM4(t, addr);
                LDSM4(u, addr + 64 * VROW);
                uint32_t bh0[2] = {t[0], t[2]}, bh1[2] = {t[1], t[3]};
                uint32_t bl0[2] = {u[0], u[2]}, bl1[2] = {u[1], u[3]};
                MMA16816(acc_o[2 * bj],     aPh, bh0);
                MMA16816(acc_o[2 * bj],     aPh, bl0);
                MMA16816(acc_o[2 * bj + 1], aPh, bh1);
                MMA16816(acc_o[2 * bj + 1], aPh, bl1);
            }
        }
    }

#pragma unroll
    for (int half = 0; half < 2; half++) {
        float v = rs[half];
        v += __shfl_xor_sync(0xffffffffu, v, 1);
        v += __shfl_xor_sync(0xffffffffu, v, 2);
        if ((lane & 3) == 0)
            atomicAdd(&rsm[wm + (lane >> 2) + half * 8], v);
    }
#pragma unroll
    for (int g = 0; g < 8; g++) {
        int r0 = wm + (lane >> 2);
        int c = g * 8 + (lane & 3) * 2;
        atomicAdd(&Os[r0 * 68 + c],           acc_o[g][0]);
        atomicAdd(&Os[r0 * 68 + c + 1],       acc_o[g][1]);
        atomicAdd(&Os[(r0 + 8) * 68 + c],     acc_o[g][2]);
        atomicAdd(&Os[(r0 + 8) * 68 + c + 1], acc_o[g][3]);
    }
    __syncthreads();
#pragma unroll
    for (int i = 0; i < 8; i++) {
        int idx = tid + i * 512;
        int r = idx >> 6, d = idx & 63;
        float val = Os[r * 68 + d] / rsm[r];
        bf16 hh, lo; split2(val, hh, lo);
        ll o = bz * sAVT + (ll)d * MLM + (m0 + r);
        AVTh[o] = hh; AVTl[o] = lo;
    }
}

// ---------------- fused attn1 + softmax + P@zav + conv -> y (512 thr; 2-term both GEMMs) ----------------
#define ZROW 528
__global__ void __launch_bounds__(512, 1) attn1_outh(
    const bf16* __restrict__ Ah,
    const bf16* __restrict__ Bh, const bf16* __restrict__ Bl,
    const bf16* __restrict__ Zh, const bf16* __restrict__ Zl,
    const float* __restrict__ Vv, const float* __restrict__ kern,
    bf16* __restrict__ Yh, bf16* __restrict__ Yl,
    ll sA, ll sB, ll sZ, ll sV, int bzoff)
{
    extern __shared__ char smem[];
    __shared__ float redm[4][16][4];
    __shared__ float reds[4][16][4];
    __shared__ float khs[33];
    const int tid = threadIdx.x, wid = tid >> 5, lane = tid & 31;
    const int bz = blockIdx.y + bzoff;
    const int m0 = blockIdx.x * 64;
    const int wm = (wid & 3) * 16;
    const int wn = (wid >> 2) * 64;
    const int b_ = bz >> 3, h_ = bz & 7;
    uint32_t sb = smem_u32(smem);
    constexpr uint32_t OZH = 81920;
    constexpr uint32_t OZL = OZH + 64 * ZROW;
    constexpr uint32_t OO  = OZL + 64 * ZROW;
    constexpr uint32_t OV  = OO + 64 * 68 * 4;
    float* Os = (float*)(smem + OO);
    float* sv = (float*)(smem + OV);

    if (tid < 33) khs[tid] = kern[h_ * 33 + tid];

    const bf16* pAh = Ah + bz * sA + (ll)m0 * 64;
    const bf16* pBh = Bh + bz * sB;
    const bf16* pBl = Bl + bz * sB;
    const bf16* pZh = Zh + bz * sZ;
    const bf16* pZl = Zl + bz * sZ;
    const float* pV = Vv + bz * sV;

    {
        int r = tid >> 3, c = tid & 7;
        uint32_t so = SWZ128((uint32_t)(r * 128 + c * 16));
        cp16(sb + so, pAh + (ll)r * 64 + c * 8);
    }
#pragma unroll
    for (int i = 0; i < 4; i++) {
        int idx = tid + i * 512;
        int r = idx >> 3, c = idx & 7;
        uint32_t so = SWZ128((uint32_t)(r * 128 + c * 16));
        cp16(sb + 16384 + so, pBh + (ll)r * 64 + c * 8);
        cp16(sb + 49152 + so, pBl + (ll)r * 64 + c * 8);
    }
#pragma unroll
    for (int i = 0; i < 4; i++) {
        int idx = tid + i * 512;
        int r = idx >> 5, c = idx & 31;
        uint32_t so = (uint32_t)(r * ZROW + c * 16);
        cp16(sb + OZH + so, pZh + (ll)r * 256 + c * 8);
        cp16(sb + OZL + so, pZl + (ll)r * 256 + c * 8);
    }
#pragma unroll
    for (int i = 0; i < 3; i++) {
        int idx = tid + i * 512;
        int r = idx >> 4, c = idx & 15;
        int tt = m0 - 16 + r;
        if (tt >= 0 && tt < NTOK)
            cp16(sb + OV + (uint32_t)(r * 256 + c * 16), pV + (ll)tt * 64 + c * 4);
        else
            *(float4*)(smem + OV + r * 256 + c * 16) = make_float4(0.f, 0.f, 0.f, 0.f);
    }
    CP_COMMIT;
#pragma unroll
    for (int i = 0; i < 9; i++) {
        int idx = tid + i * 512;
        if (idx < 64 * 68) Os[idx] = 0.f;
    }

    float acc[8][4];
#pragma unroll
    for (int b = 0; b < 8; b++)
#pragma unroll
        for (int c = 0; c < 4; c++) acc[b][c] = 0.f;

    CP_WAIT0;
    __syncthreads();
#pragma unroll
    for (int ks = 0; ks < 4; ks++) {
        uint32_t aH[4];
        {
            int row = wm + (lane & 15);
            int c16 = ks * 2 + (lane >> 4);
            uint32_t off = SWZ128((uint32_t)(row * 128 + c16 * 16));
            LDSM4(aH, sb + off);
        }
        uint32_t bHf[8][2], bLf[8][2];
#pragma unroll
        for (int bj = 0; bj < 4; bj++) {
            int row = wn + bj * 16 + (lane & 15);
            int c16 = ks * 2 + (lane >> 4);
            uint32_t off = SWZ128((uint32_t)(row * 128 + c16 * 16));
            uint32_t t[4];
            LDSM4(t, sb + 16384 + off);
            bHf[bj * 2][0] = t[0]; bHf[bj * 2 + 1][0] = t[1];
            bHf[bj * 2][1] = t[2]; bHf[bj * 2 + 1][1] = t[3];
            LDSM4(t, sb + 49152 + off);
            bLf[bj * 2][0] = t[0]; bLf[bj * 2 + 1][0] = t[1];
            bLf[bj * 2][1] = t[2]; bLf[bj * 2 + 1][1] = t[3];
        }
#pragma unroll
        for (int g = 0; g < 8; g++) MMA16816(acc[g], aH, bHf[g]);
#pragma unroll
        for (int g = 0; g < 8; g++) MMA16816(acc[g], aH, bLf[g]);
    }

    float mx[2];
#pragma unroll
    for (int half = 0; half < 2; half++) {
        float m = -1e30f;
#pragma unroll
        for (int g = 0; g < 8; g++) {
            m = fmaxf(m, acc[g][half * 2]);
            m = fmaxf(m, acc[g][half * 2 + 1]);
        }
        m = fmaxf(m, __shfl_xor_sync(0xffffffffu, m, 1));
        m = fmaxf(m, __shfl_xor_sync(0xffffffffu, m, 2));
        mx[half] = m;
    }
    if ((lane & 3) == 0) {
#pragma unroll
        for (int half = 0; half < 2; half++)
            redm[wid & 3][(lane >> 2) + half * 8][wid >> 2] = mx[half];
    }
    __syncthreads();
    float sm[2];
#pragma unroll
    for (int half = 0; half < 2; half++) {
        int ri = (lane >> 2) + half * 8;
        float m = fmaxf(fmaxf(redm[wid & 3][ri][0], redm[wid & 3][ri][1]),
                        fmaxf(redm[wid & 3][ri][2], redm[wid & 3][ri][3]));
        float s = 0.f;
#pragma unroll
        for (int g = 0; g < 8; g++) {
            float e0 = __expf(acc[g][half * 2] - m);
            float e1 = __expf(acc[g][half * 2 + 1] - m);
            acc[g][half * 2] = e0; acc[g][half * 2 + 1] = e1;
            s += e0 + e1;
        }
        s += __shfl_xor_sync(0xffffffffu, s, 1);
        s += __shfl_xor_sync(0xffffffffu, s, 2);
        sm[half] = s;
    }
    if ((lane & 3) == 0) {
#pragma unroll
        for (int half = 0; half < 2; half++)
            reds[wid & 3][(lane >> 2) + half * 8][wid >> 2] = sm[half];
    }
    __syncthreads();
#pragma unroll
    for (int half = 0; half < 2; half++) {
        int ri = (lane >> 2) + half * 8;
        float tot = reds[wid & 3][ri][0] + reds[wid & 3][ri][1]
                  + reds[wid & 3][ri][2] + reds[wid & 3][ri][3];
        float inv = 1.f / tot;
#pragma unroll
        for (int g = 0; g < 8; g++) {
            acc[g][half * 2]     *= inv;
            acc[g][half * 2 + 1] *= inv;
        }
    }

    float acc_o[8][4];
#pragma unroll
    for (int b = 0; b < 8; b++)
#pragma unroll
        for (int c = 0; c < 4; c++) acc_o[b][c] = 0.f;

    // P @ zav: 2-term (Ph·zh + Ph·zl; P_lo dropped — validated numerics from R11)
#pragma unroll
    for (int ks = 0; ks < 4; ks++) {
        uint32_t aPh[4];
        aPh[0] = packh2(acc[2 * ks][0], acc[2 * ks][1]);
        aPh[1] = packh2(acc[2 * ks][2], acc[2 * ks][3]);
        aPh[2] = packh2(acc[2 * ks + 1][0], acc[2 * ks + 1][1]);
        aPh[3] = packh2(acc[2 * ks + 1][2], acc[2 * ks + 1][3]);
#pragma unroll
        for (int bj = 0; bj < 4; bj++) {
            uint32_t addr = sb + OZH + (uint32_t)((bj * 16 + (lane & 15)) * ZROW)
                          + (uint32_t)((wn + ks * 16) * 2 + (lane >> 4) * 16);
            uint32_t t[4], u[4];
            LDSM4(t, addr);
            LDSM4(u, addr + (OZL - OZH));
            uint32_t bh0[2] = {t[0], t[2]}, bh1[2] = {t[1], t[3]};
            uint32_t bl0[2] = {u[0], u[2]}, bl1[2] = {u[1], u[3]};
            MMA16816(acc_o[2 * bj],     aPh, bh0);
            MMA16816(acc_o[2 * bj],     aPh, bl0);
            MMA16816(acc_o[2 * bj + 1], aPh, bh1);
            MMA16816(acc_o[2 * bj + 1], aPh, bl1);
        }
    }

#pragma unroll
    for (int g = 0; g < 8; g++) {
        int r0 = wm + (lane >> 2);
        int c = g * 8 + (lane & 3) * 2;
        atomicAdd(&Os[r0 * 68 + c],           acc_o[g][0]);
        atomicAdd(&Os[r0 * 68 + c + 1],       acc_o[g][1]);
        atomicAdd(&Os[(r0 + 8) * 68 + c],     acc_o[g][2]);
        atomicAdd(&Os[(r0 + 8) * 68 + c + 1], acc_o[g][3]);
    }
    __syncthreads();
#pragma unroll
    for (int i = 0; i < 8; i++) {
        int idx = tid + i * 512;
        int r = idx >> 6, d = idx & 63;
        float s = Os[r * 68 + d];
#pragma unroll
        for (int j = 0; j < 33; j++)
            s = fmaf(sv[(r + j) * 64 + d], khs[j], s);
        ll yo = ((ll)(b_ * NTOK + m0 + r)) * INNER + h_ * 64 + d;
        bf16 hh, lo; split2(s, hh, lo);
        Yh[yo] = hh; Yl[yo] = lo;
    }
}

// ---------------- elementwise kernels ----------------
__global__ void split_f32(const float* __restrict__ in, bf16* __restrict__ oh,
                          bf16* __restrict__ ol, ll n)
{
    ll i = (ll)blockIdx.x * 256 + threadIdx.x;
    if (i >= n) return;
    bf16 h, l; split2(in[i], h, l);
    oh[i] = h; ol[i] = l;
}

__global__ void transpose_split(const float* __restrict__ in, bf16* __restrict__ oh,
                                bf16* __restrict__ ol, int R, int C, ll sIn, ll sOut,
                                const float* __restrict__ nrmp, float dc, int usediag)
{
    __shared__ float t[32][33];
    ll b = blockIdx.z;
    const float* ip = in + b * sIn;
    int c0 = blockIdx.x * 32, r0 = blockIdx.y * 32;
    int tx = threadIdx.x, ty = threadIdx.y;
#pragma unroll
    for (int i = 0; i < 4; i++)
        t[ty + i * 8][tx] = ip[(ll)(r0 + ty + i * 8) * C + c0 + tx];
    __syncthreads();
    float alpha = nrmp ? 1.f / (nrmp[0] * nrmp[1]) : 1.f;
#pragma unroll
    for (int i = 0; i < 4; i++) {
        int cg = c0 + ty + i * 8, rg = r0 + tx;
        float v = t[tx][ty + i * 8];
        v = usediag ? ((rg == cg ? dc : 0.f) - v) : alpha * v;
        ll o = b * sOut + (ll)cg * R + rg;
        bf16 h, l; split2(v, h, l);
        oh[o] = h; ol[o] = l;
    }
}

__global__ void scale_split(const float* __restrict__ in, bf16* __restrict__ oh,
                            bf16* __restrict__ ol, ll n, const float* __restrict__ nrmp)
{
    ll i = (ll)blockIdx.x * 256 + threadIdx.x;
    if (i >= n) return;
    float inv = 1.f / (nrmp[0] * nrmp[1]);
    bf16 h, l; split2(in[i] * inv, h, l);
    oh[i] = h; ol[i] = l;
}

__global__ void landmark_split_bf(const bf16* __restrict__ xh, const bf16* __restrict__ xl,
                                  bf16* __restrict__ oh, bf16* __restrict__ ol)
{
    ll idx = (ll)blockIdx.x * 256 + threadIdx.x;
    if (idx >= SZ_LM) return;
    int d = (int)(idx & 63);
    int mi = (int)((idx >> 6) & 255);
    ll bh = idx >> 14;
    ll base = (bh * NTOK + (ll)mi * LGRP) * DH + d;
    float s = 0.f;
#pragma unroll
    for (int t = 0; t < LGRP; t++) {
        ll o = base + (ll)t * DH;
        s += __bfloat162float(xh[o]) + __bfloat162float(xl[o]);
    }
    bf16 h, l; split2(s * (1.f / LGRP), h, l);
    oh[idx] = h; ol[idx] = l;
}

__global__ void norm_init_kernel(float* nrm) { nrm[0] = 0.f; nrm[1] = 0.f; }

__global__ void pinv_norm_kernel(const float* __restrict__ x, float* __restrict__ nrm)
{
    int r = threadIdx.x;
    const float* xb = x + (ll)blockIdx.x * MLM * MLM;
    float rs = 0.f, cs = 0.f;
    for (int j = 0; j < MLM; j++) {
        rs += fabsf(xb[(ll)r * MLM + j]);
        cs += fabsf(xb[(ll)j * MLM + r]);
    }
    __shared__ float s1[256], s2[256];
    s1[r] = rs; s2[r] = cs; __syncthreads();
    for (int s = 128; s > 0; s >>= 1) {
        if (r < s) { s1[r] = fmaxf(s1[r], s1[r + s]); s2[r] = fmaxf(s2[r], s2[r + s]); }
        __syncthreads();
    }
    if (r == 0) {
        atomicMax((int*)&nrm[0], __float_as_int(s1[0]));
        atomicMax((int*)&nrm[1], __float_as_int(s2[0]));
    }
}

// ---------------- host ----------------
template<int TM, int TN, bool SPLIT, int NT>
static inline void tcg(cudaStream_t st,
                       const bf16* Ah, const bf16* Al, const bf16* Bh, const bf16* Bl,
                       float* C, bf16* Ch, bf16* Cl, bf16* CTh, bf16* CTl,
                       const float* bias,
                       int M, int N, int K, int Kc, int ldc, int ldct,
                       ll sA, ll sB, ll sC, ll sCT, int batch, int kz,
                       float alpha, float diagc, int flags)
{
    dim3 grid(N / TN, M / TM, batch * kz);
    size_t sm = 2 * (size_t)((SPLIT ? 2 : 1) * (TM + TN) * 128);
    gemm_mma<TM, TN, SPLIT, NT><<<grid, NT, sm, st>>>(Ah, Al, Bh, Bl, C, Ch, Cl, CTh, CTl, bias,
                                                      K, Kc, batch, ldc, ldct, sA, sB, sC, sCT,
                                                      alpha, diagc, flags);
}

extern "C" void kernel_launch(void* const* d_in, const int* in_sizes, int n_in,
                              void* d_out, int out_size)
{
    const float* x     = (const float*)d_in[0];
    const float* w_qkv = (const float*)d_in[1];
    const float* w_out = (const float*)d_in[2];
    const float* b_out = (const float*)d_in[3];
    const float* res_k = (const float*)d_in[4];
    float* out = (float*)d_out;

    const int A1O_SMEM = 81920 + 2 * 64 * ZROW + 64 * 68 * 4 + 96 * 64 * 4;
    const int FA3_SMEM = 16384 + 2 * (32768 + 2 * 64 * VROW);

    cudaFuncSetAttribute(gemm_mma<128, 128, true, 512>, cudaFuncAttributeMaxDynamicSharedMemorySize, 131072);
    cudaFuncSetAttribute(gemm_mma<64, 128, true, 256>,  cudaFuncAttributeMaxDynamicSharedMemorySize, 98304);
    cudaFuncSetAttribute(gemm_mma<64, 128, false, 256>, cudaFuncAttributeMaxDynamicSharedMemorySize, 49152);
    cudaFuncSetAttribute(gemm_mma<64, 64, true, 256>,   cudaFuncAttributeMaxDynamicSharedMemorySize, 65536);
    cudaFuncSetAttribute(attn_gemm_softmax, cudaFuncAttributeMaxDynamicSharedMemorySize, 81920);
    cudaFuncSetAttribute(attn1_outh, cudaFuncAttributeMaxDynamicSharedMemorySize, A1O_SMEM);
    cudaFuncSetAttribute(fa3_av, cudaFuncAttributeMaxDynamicSharedMemorySize, FA3_SMEM);

    float* F;  cudaGetSymbolAddress((void**)&F, g_f32);
    bf16*  Bp; cudaGetSymbolAddress((void**)&Bp, g_bf);
    float* nrm; cudaGetSymbolAddress((void**)&nrm, g_norm);

    const ll SH = (ll)NTOK * DH, SL = (ll)MLM * DH;
    const ll SA2 = (ll)MLM * MLM;

    cudaStream_t s0 = 0;
    cudaStream_t s2 = g_ctx.s2;

    // prep on s0 (R10 layout)
    {
        dim3 blk(32, 8);
        transpose_split<<<dim3(3 * INNER / 32, DIM / 32, 1), blk, 0, s0>>>(
            w_qkv, Bp + B_WQTH, Bp + B_WQTL, DIM, 3 * INNER, 0, 0, nullptr, 0.f, 0);
        split_f32<<<(int)((SZ_Y + 255) / 256), 256, 0, s0>>>(x, Bp + B_XH, Bp + B_XL, SZ_Y);
    }

    // fork s2: w_out transpose overlaps qkv
    cudaEventRecord(g_ctx.e0, s0);
    cudaStreamWaitEvent(s2, g_ctx.e0, 0);
    transpose_split<<<dim3(DIM / 32, INNER / 32, 1), dim3(32, 8), 0, s2>>>(
        w_out, Bp + B_WOTH, Bp + B_WOTL, INNER, DIM, 0, 0, nullptr, 0.f, 0);

    // 1a. qkv GEMM, q+k columns only (N=1024, n_base=0)
    tcg<128, 128, true, 512>(s0, Bp + B_XH, Bp + B_XL, Bp + B_WQTH, Bp + B_WQTL,
                             nullptr, nullptr, nullptr, nullptr, nullptr, nullptr,
                             BB * NTOK, 2 * INNER, DIM, DIM, 0, 0,
                             0, 0, 0, 0, 1, 1, 1.f, 0.f, 64);

    landmark_split_bf<<<(int)((SZ_LM + 255) / 256), 256, 0, s0>>>(Bp + B_QH, Bp + B_QL, Bp + B_QLMH, Bp + B_QLML);
    landmark_split_bf<<<(int)((SZ_LM + 255) / 256), 256, 0, s0>>>(Bp + B_KH, Bp + B_KL, Bp + B_KLMH, Bp + B_KLML);

    // 2. attn2 fused (+fp32 for pinv init)
    attn_gemm_softmax<<<dim3(MLM / 64, BH), 256, 81920, s0>>>(
        Bp + B_QLMH, Bp + B_QLML, Bp + B_KLMH, Bp + B_KLML,
        F + F_A2, Bp + B_A2H, Bp + B_A2L, SL, SL, SA2);

    // fork s2: pinv starts now (before v-columns of qkv)
    cudaEventRecord(g_ctx.e1, s0);
    cudaStreamWaitEvent(s2, g_ctx.e1, 0);

    norm_init_kernel<<<1, 1, 0, s2>>>(nrm);
    pinv_norm_kernel<<<BH, 256, 0, s2>>>(F + F_A2, nrm);
    {
        int blocks = (int)((SZ_A2 + 255) / 256);
        scale_split<<<blocks, 256, 0, s2>>>(F + F_A2, Bp + B_Z0TH, Bp + B_Z0TL, SZ_A2, nrm);
        transpose_split<<<dim3(8, 8, BH), dim3(32, 8), 0, s2>>>(
            F + F_A2, Bp + B_Z0H, Bp + B_Z0L, MLM, MLM, SA2, SA2, nrm, 0.f, 0);
    }

    bf16 *zch = Bp + B_Z0H,  *zcl = Bp + B_Z0L,  *zcth = Bp + B_Z0TH, *zctl = Bp + B_Z0TL;
    bf16 *znh = Bp + B_Z1H,  *znl = Bp + B_Z1L,  *znth = Bp + B_Z1TH, *zntl = Bp + B_Z1TL;

    for (int it = 0; it < 6; it++) {
#define PINV_STEP(S) \
        tcg<64, 128, S, 256>(s2, Bp + B_A2H, Bp + B_A2L, zcth, zctl, \
                    nullptr, Bp + B_XZH, Bp + B_XZL, Bp + B_T1TH, Bp + B_T1TL, nullptr, \
                    MLM, MLM, MLM, MLM, MLM, MLM, SA2, SA2, SA2, SA2, BH, 1, 1.f, 7.f, 2|4|8|16); \
        tcg<64, 128, S, 256>(s2, Bp + B_XZH, Bp + B_XZL, Bp + B_T1TH, Bp + B_T1TL, \
                    nullptr, nullptr, nullptr, Bp + B_T2TH, Bp + B_T2TL, nullptr, \
                    MLM, MLM, MLM, MLM, MLM, MLM, SA2, SA2, 0, SA2, BH, 1, 1.f, 15.f, 4|8); \
        tcg<64, 128, S, 256>(s2, Bp + B_XZH, Bp + B_XZL, Bp + B_T2TH, Bp + B_T2TL, \
                    nullptr, nullptr, nullptr, Bp + B_T3TH, Bp + B_T3TL, nullptr, \
                    MLM, MLM, MLM, MLM, MLM, MLM, SA2, SA2, 0, SA2, BH, 1, 1.f, 13.f, 4|8); \
        tcg<64, 128, S, 256>(s2, zch, zcl, Bp + B_T3TH, Bp + B_T3TL, \
                    nullptr, znh, znl, znth, zntl, nullptr, \
                    MLM, MLM, MLM, MLM, MLM, MLM, SA2, SA2, SA2, SA2, BH, 1, 0.25f, 0.f, 2|4);
        if (it < 5) { PINV_STEP(false) } else { PINV_STEP(true) }
#undef PINV_STEP
        bf16* t;
        t = zch;  zch  = znh;  znh  = t;   t = zcl;  zcl  = znl;  znl  = t;
        t = zcth; zcth = znth; znth = t;   t = zctl; zctl = zntl; zntl = t;
    }
    cudaEventRecord(g_ctx.e2, s2);

    // 1b. qkv GEMM, v columns (N=512, n_base=1024 via ldct) — concurrent with pinv
    tcg<128, 128, true, 512>(s0, Bp + B_XH, Bp + B_XL,
                             Bp + B_WQTH + (ll)2 * INNER * DIM, Bp + B_WQTL + (ll)2 * INNER * DIM,
                             nullptr, nullptr, nullptr, nullptr, nullptr, nullptr,
                             BB * NTOK, INNER, DIM, DIM, 0, 2 * INNER,
                             0, 0, 0, 0, 1, 1, 1.f, 0.f, 64);

    // 3. fa3 (s0), concurrent with pinv (s2)
    fa3_av<<<dim3(MLM / 64, BH), 512, FA3_SMEM, s0>>>(
        Bp + B_QLMH, Bp + B_QLML, Bp + B_KH, Bp + B_KL,
        Bp + B_VTH, Bp + B_VTL, Bp + B_AVTH, Bp + B_AVTL,
        SL, SH, SH, SL);

    // join pinv
    cudaStreamWaitEvent(s0, g_ctx.e2, 0);

    // 4. zav^T = (z @ av)^T
    tcg<64, 64, true, 256>(s0, zch, zcl, Bp + B_AVTH, Bp + B_AVTL,
                           nullptr, nullptr, nullptr, Bp + B_ZVTH, Bp + B_ZVTL, nullptr,
                           MLM, DH, MLM, MLM, DH, MLM, SA2, SL, 0, SL, BH, 1, 1.f, 0.f, 4);

    // 5. a1o chunk0 (bz 0..15) then chunk1; out-proj chunk0 overlaps chunk1 on s2
    attn1_outh<<<dim3(NTOK / 64, 16), 512, A1O_SMEM, s0>>>(
        Bp + B_QH, Bp + B_KLMH, Bp + B_KLML,
        Bp + B_ZVTH, Bp + B_ZVTL, F + F_V, res_k,
        Bp + B_YH, Bp + B_YL, SH, SL, SL, SH, 0);
    cudaEventRecord(g_ctx.e3, s0);

    attn1_outh<<<dim3(NTOK / 64, 16), 512, A1O_SMEM, s0>>>(
        Bp + B_QH, Bp + B_KLMH, Bp + B_KLML,
        Bp + B_ZVTH, Bp + B_ZVTL, F + F_V, res_k,
        Bp + B_YH, Bp + B_YL, SH, SL, SL, SH, 16);

    cudaStreamWaitEvent(s2, g_ctx.e3, 0);
    // out-proj rows 0..8191 on s2
    tcg<128, 128, true, 512>(s2, Bp + B_YH, Bp + B_YL, Bp + B_WOTH, Bp + B_WOTL,
                             out, nullptr, nullptr, nullptr, nullptr, b_out,
                             2 * NTOK, DIM, INNER, INNER, DIM, 0, 0, 0, 0, 0, 1, 1, 1.f, 0.f, 1);
    cudaEventRecord(g_ctx.e4, s2);

    // out-proj rows 8192..16383 on s0
    tcg<128, 128, true, 512>(s0, Bp + B_YH + (ll)2 * NTOK * INNER, Bp + B_YL + (ll)2 * NTOK * INNER,
                             Bp + B_WOTH, Bp + B_WOTL,
                             out + (ll)2 * NTOK * DIM, nullptr, nullptr, nullptr, nullptr, b_out,
                             2 * NTOK, DIM, INNER, INNER, DIM, 0, 0, 0, 0, 0, 1, 1, 1.f, 0.f, 1);

    // final join
    cudaStreamWaitEvent(s0, g_ctx.e4, 0);
}

// round 14
// speedup vs baseline: 1.0580x; 1.0546x over previous
#include <cuda_runtime.h>
#include <cuda_bf16.h>
#include <cstdint>

typedef __nv_bfloat16 bf16;
typedef long long ll;

#define BB    4
#define NTOK  4096
#define DIM   512
#define H     8
#define DH    64
#define MLM   256
#define LGRP  16
#define BH    32
#define INNER 512

// ---------------- sizes ----------------
static const ll SZ_Y     = (ll)BB*NTOK*INNER;
static const ll SZ_HEADS = (ll)BH*NTOK*DH;
static const ll SZ_LM    = (ll)BH*MLM*DH;
static const ll SZ_A2    = (ll)BH*MLM*MLM;

// fp32 scratch
static const ll F_V    = 0;
static const ll F_A2   = F_V    + SZ_HEADS;
static const ll F_TOTAL= F_A2   + SZ_A2;

// bf16 scratch
static const ll B_XH   = 0;
static const ll B_XL   = B_XH   + SZ_Y;
static const ll B_WQTH = B_XL   + SZ_Y;
static const ll B_WQTL = B_WQTH + (ll)DIM*3*INNER;
static const ll B_WOTH = B_WQTL + (ll)DIM*3*INNER;
static const ll B_WOTL = B_WOTH + (ll)DIM*INNER;
static const ll B_QH   = B_WOTL + (ll)DIM*INNER;
static const ll B_QL   = B_QH   + SZ_HEADS;
static const ll B_KH   = B_QL   + SZ_HEADS;
static const ll B_KL   = B_KH   + SZ_HEADS;
static const ll B_VTH  = B_KL   + SZ_HEADS;
static const ll B_VTL  = B_VTH  + SZ_HEADS;
static const ll B_QLMH = B_VTL  + SZ_HEADS;
static const ll B_QLML = B_QLMH + SZ_LM;
static const ll B_KLMH = B_QLML + SZ_LM;
static const ll B_KLML = B_KLMH + SZ_LM;
static const ll B_A2H  = B_KLML + SZ_LM;
static const ll B_A2L  = B_A2H  + SZ_A2;
static const ll B_Z0H  = B_A2L  + SZ_A2;
static const ll B_Z0L  = B_Z0H  + SZ_A2;
static const ll B_Z0TH = B_Z0L  + SZ_A2;
static const ll B_Z0TL = B_Z0TH + SZ_A2;
static const ll B_Z1H  = B_Z0TL + SZ_A2;
static const ll B_Z1L  = B_Z1H  + SZ_A2;
static const ll B_Z1TH = B_Z1L  + SZ_A2;
static const ll B_Z1TL = B_Z1TH + SZ_A2;
static const ll B_XZH  = B_Z1TL + SZ_A2;
static const ll B_XZL  = B_XZH  + SZ_A2;
static const ll B_T1TH = B_XZL  + SZ_A2;
static const ll B_T1TL = B_T1TH + SZ_A2;
static const ll B_T2TH = B_T1TL + SZ_A2;
static const ll B_T2TL = B_T2TH + SZ_A2;
static const ll B_T3TH = B_T2TL + SZ_A2;
static const ll B_T3TL = B_T3TH + SZ_A2;
static const ll B_AVTH = B_T3TL + SZ_A2;
static const ll B_AVTL = B_AVTH + SZ_LM;
static const ll B_ZVTH = B_AVTL + SZ_LM;
static const ll B_ZVTL = B_ZVTH + SZ_LM;
static const ll B_YH   = B_ZVTL + SZ_LM;
static const ll B_YL   = B_YH   + SZ_Y;
static const ll B_TOTAL= B_YL   + SZ_Y;

__device__ __align__(16) float g_f32[F_TOTAL];
__device__ __align__(16) bf16  g_bf[B_TOTAL];
__device__ float g_norm[2];

// ---------------- stream/event context ----------------
struct StreamCtx {
    cudaStream_t s2;
    cudaEvent_t e0, e1, e2, e3, e4;
    StreamCtx() {
        cudaStreamCreateWithFlags(&s2, cudaStreamNonBlocking);
        cudaEventCreateWithFlags(&e0, cudaEventDisableTiming);
        cudaEventCreateWithFlags(&e1, cudaEventDisableTiming);
        cudaEventCreateWithFlags(&e2, cudaEventDisableTiming);
        cudaEventCreateWithFlags(&e3, cudaEventDisableTiming);
        cudaEventCreateWithFlags(&e4, cudaEventDisableTiming);
    }
};
static StreamCtx g_ctx;

// ---------------- helpers ----------------
__device__ __forceinline__ uint32_t smem_u32(const void* p) {
    uint32_t a;
    asm("{ .reg .u64 t; cvta.to.shared.u64 t, %1; cvt.u32.u64 %0, t; }" : "=r"(a) : "l"(p));
    return a;
}
__device__ __forceinline__ void cp16(uint32_t s, const void* g) {
    asm volatile("cp.async.cg.shared.global [%0], [%1], 16;" :: "r"(s), "l"(g));
}
#define CP_COMMIT asm volatile("cp.async.commit_group;" ::: "memory")
#define CP_WAIT0  asm volatile("cp.async.wait_group 0;" ::: "memory")

#define LDSM4(R, A) \
    asm volatile("ldmatrix.sync.aligned.m8n8.x4.shared.b16 {%0,%1,%2,%3}, [%4];" \
        : "=r"((R)[0]), "=r"((R)[1]), "=r"((R)[2]), "=r"((R)[3]) : "r"(A))

#define MMA16816(D, Aa, Bb) \
    asm volatile("mma.sync.aligned.m16n8k16.row.col.f32.bf16.bf16.f32 " \
        "{%0,%1,%2,%3}, {%4,%5,%6,%7}, {%8,%9}, {%0,%1,%2,%3};" \
        : "+f"((D)[0]), "+f"((D)[1]), "+f"((D)[2]), "+f"((D)[3]) \
        : "r"((Aa)[0]), "r"((Aa)[1]), "r"((Aa)[2]), "r"((Aa)[3]), \
          "r"((Bb)[0]), "r"((Bb)[1]))

#define SWZ128(o) ((o) ^ (((o) >> 3) & 0x70))

__device__ __forceinline__ void split2(float v, bf16& h, bf16& l) {
    h = __float2bfloat16(v);
    l = __float2bfloat16(v - __bfloat162float(h));
}
__device__ __forceinline__ uint32_t packh2(float a, float b) {
    __nv_bfloat162 p; p.x = __float2bfloat16(a); p.y = __float2bfloat16(b);
    return *(uint32_t*)&p;
}
__device__ __forceinline__ uint32_t packl2(float a, float b) {
    __nv_bfloat162 p;
    p.x = __float2bfloat16(a - __bfloat162float(__float2bfloat16(a)));
    p.y = __float2bfloat16(b - __bfloat162float(__float2bfloat16(b)));
    return *(uint32_t*)&p;
}

// ---------------- generic split-bf16 HMMA NT GEMM ----------------
// SPLIT modes: 0 = hi-only (1 MMA term), 1 = full split (3 terms),
//              2 = A-hi / B-split (2 terms: Ah*Bh + Ah*Bl)
template<int TM, int TN, int SPLIT>
__host__ __device__ constexpr int stage_bytes() {
    return ((SPLIT == 1) ? 2 * (TM + TN) : (SPLIT == 2) ? (TM + 2 * TN) : (TM + TN)) * 128;
}

template<int TM, int TN, int SPLIT, int NT>
__device__ __forceinline__ void load_stage(uint32_t sbase,
    const bf16* pAh, const bf16* pAl, const bf16* pBh, const bf16* pBl,
    int K, int k0, int tid)
{
    constexpr uint32_t OAL = TM * 128;
    constexpr uint32_t OBH = ((SPLIT == 1) ? 2 : 1) * TM * 128;
    constexpr uint32_t OBL = OBH + TN * 128;
#pragma unroll
    for (int i = 0; i < TM * 8 / NT; i++) {
        int idx = tid + i * NT;
        int r = idx >> 3, c = idx & 7;
        uint32_t so = SWZ128((uint32_t)(r * 128 + c * 16));
        ll go = (ll)r * K + k0 + c * 8;
        cp16(sbase + so, pAh + go);
        if (SPLIT == 1) cp16(sbase + OAL + so, pAl + go);
    }
#pragma unroll
    for (int i = 0; i < TN * 8 / NT; i++) {
        int idx = tid + i * NT;
        int r = idx >> 3, c = idx & 7;
        uint32_t so = SWZ128((uint32_t)(r * 128 + c * 16));
        ll go = (ll)r * K + k0 + c * 8;
        cp16(sbase + OBH + so, pBh + go);
        if (SPLIT >= 1) cp16(sbase + OBL + so, pBl + go);
    }
}

template<int TM, int TN, int SPLIT, int NT>
__global__ void __launch_bounds__(NT, (NT == 256 && TM == 64) ? 2 : 1) gemm_mma(
    const bf16* __restrict__ Ah, const bf16* __restrict__ Al,
    const bf16* __restrict__ Bh, const bf16* __restrict__ Bl,
    float* __restrict__ C, bf16* __restrict__ Ch, bf16* __restrict__ Cl,
    bf16* __restrict__ CTh, bf16* __restrict__ CTl,
    const float* __restrict__ bias,
    int K, int Kc, int nbatch, int ldc, int ldct,
    ll sA, ll sB, ll sC, ll sCT,
    float alpha, float diagc, int flags)
{
    extern __shared__ char smem[];
    constexpr int WR = (NT == 512) ? 4 : 2;
    constexpr int MI = TM / WR / 16;
    constexpr int NG = TN / 4 / 8;
    constexpr uint32_t OBH = ((SPLIT == 1) ? 2 : 1) * TM * 128;
    constexpr uint32_t OBL = OBH + TN * 128;
    constexpr int STAGE = stage_bytes<TM, TN, SPLIT>();

    const int tid = threadIdx.x, wid = tid >> 5, lane = tid & 31;
    const int bz = blockIdx.z % nbatch;
    const int koff = (blockIdx.z / nbatch) * Kc;
    const int m0 = blockIdx.y * TM, n0 = blockIdx.x * TN;
    const int wm = (wid % WR) * (TM / WR);
    const int wn = (wid / WR) * (TN / 4);
    uint32_t sb = smem_u32(smem);

    const bf16* pAh = Ah + bz * sA + (ll)m0 * K + koff;
    const bf16* pAl = (SPLIT == 1) ? (Al + bz * sA + (ll)m0 * K + koff) : pAh;
    const bf16* pBh = Bh + bz * sB + (ll)n0 * K + koff;
    const bf16* pBl = (SPLIT >= 1) ? (Bl + bz * sB + (ll)n0 * K + koff) : pBh;

    float acc[MI][NG][4];
#pragma unroll
    for (int a = 0; a < MI; a++)
#pragma unroll
        for (int b = 0; b < NG; b++)
#pragma unroll
            for (int c = 0; c < 4; c++) acc[a][b][c] = 0.f;

    const int nch = Kc >> 6;
    load_stage<TM, TN, SPLIT, NT>(sb, pAh, pAl, pBh, pBl, K, 0, tid);
    CP_COMMIT;

    for (int ck = 0; ck < nch; ck++) {
        CP_WAIT0;
        __syncthreads();
        if (ck + 1 < nch) {
            load_stage<TM, TN, SPLIT, NT>(sb + ((ck + 1) & 1) * STAGE, pAh, pAl, pBh, pBl, K, (ck + 1) * 64, tid);
            CP_COMMIT;
        }
        uint32_t s = sb + (ck & 1) * STAGE;
#pragma unroll
        for (int ks = 0; ks < 4; ks++) {
            uint32_t aH[MI][4], aL[MI][4];
#pragma unroll
            for (int mi = 0; mi < MI; mi++) {
                int row = wm + mi * 16 + (lane & 15);
                int c16 = ks * 2 + (lane >> 4);
                uint32_t off = SWZ128((uint32_t)(row * 128 + c16 * 16));
                LDSM4(aH[mi], s + off);
                if (SPLIT == 1) LDSM4(aL[mi], s + TM * 128 + off);
            }
            uint32_t bH[NG][2], bL[NG][2];
#pragma unroll
            for (int bj = 0; bj < NG / 2; bj++) {
                int row = wn + bj * 16 + (lane & 15);
                int c16 = ks * 2 + (lane >> 4);
                uint32_t off = SWZ128((uint32_t)(row * 128 + c16 * 16));
                uint32_t t[4];
                LDSM4(t, s + OBH + off);
                bH[bj * 2][0] = t[0]; bH[bj * 2 + 1][0] = t[1];
                bH[bj * 2][1] = t[2]; bH[bj * 2 + 1][1] = t[3];
                if (SPLIT >= 1) {
                    LDSM4(t, s + OBL + off);
                    bL[bj * 2][0] = t[0]; bL[bj * 2 + 1][0] = t[1];
                    bL[bj * 2][1] = t[2]; bL[bj * 2 + 1][1] = t[3];
                }
            }
#pragma unroll
            for (int mi = 0; mi < MI; mi++)
#pragma unroll
                for (int g = 0; g < NG; g++) MMA16816(acc[mi][g], aH[mi], bH[g]);
            if (SPLIT >= 1) {
#pragma unroll
                for (int mi = 0; mi < MI; mi++)
#pragma unroll
                    for (int g = 0; g < NG; g++) MMA16816(acc[mi][g], aH[mi], bL[g]);
            }
            if (SPLIT == 1) {
#pragma unroll
                for (int mi = 0; mi < MI; mi++)
#pragma unroll
                    for (int g = 0; g < NG; g++) MMA16816(acc[mi][g], aL[mi], bH[g]);
            }
        }
    }

    const bool diagT = (flags & 8) != 0;
    const bool diagN = diagT && !(flags & 16);
#pragma unroll
    for (int mi = 0; mi < MI; mi++) {
#pragma unroll
        for (int g = 0; g < NG; g++) {
#pragma unroll
            for (int half = 0; half < 2; half++) {
                int r = m0 + wm + mi * 16 + (lane >> 2) + half * 8;
                int n = n0 + wn + g * 8 + (lane & 3) * 2;
                float a0 = acc[mi][g][half * 2 + 0];
                float a1v = acc[mi][g][half * 2 + 1];
                if (flags & 64) {
                    int nq = n + ldct;
                    int sel = nq >> 9;
                    int hh = (nq >> 6) & 7;
                    int d  = nq & 63;
                    int b  = r >> 12, t = r & 4095;
                    ll hidx = ((ll)((b << 3) + hh) * NTOK + t) * 64 + d;
                    if (sel == 0) {
                        *(uint32_t*)(g_bf + B_QH + hidx) = packh2(a0 * 0.125f, a1v * 0.125f);
                        *(uint32_t*)(g_bf + B_QL + hidx) = packl2(a0 * 0.125f, a1v * 0.125f);
                    } else if (sel == 1) {
                        *(uint32_t*)(g_bf + B_KH + hidx) = packh2(a0, a1v);
                        *(uint32_t*)(g_bf + B_KL + hidx) = packl2(a0, a1v);
                    } else {
                        *(float2*)(g_f32 + F_V + hidx) = make_float2(a0, a1v);
                        bf16 h0, l0, h1, l1;
                        split2(a0, h0, l0); split2(a1v, h1, l1);
                        ll vt = ((ll)((b << 3) + hh) * 64 + d) * NTOK + t;
                        g_bf[B_VTH + vt] = h0;        g_bf[B_VTL + vt] = l0;
                        g_bf[B_VTH + vt + NTOK] = h1; g_bf[B_VTL + vt + NTOK] = l1;
                    }
                    continue;
                }
                if (flags & 3) {
                    float n0v = diagN ? ((r == n)     ? diagc : 0.f) - a0  : alpha * a0;
                    float n1v = diagN ? ((r == n + 1) ? diagc : 0.f) - a1v : alpha * a1v;
                    if (bias) { n0v += bias[n]; n1v += bias[n + 1]; }
                    ll o = bz * sC + (ll)r * ldc + n;
                    if (flags & 1) {
                        if (flags & 32) { atomicAdd(C + o, n0v); atomicAdd(C + o + 1, n1v); }
                        else *(float2*)(C + o) = make_float2(n0v, n1v);
                    }
                    if (flags & 2) {
                        *(uint32_t*)(Ch + o) = packh2(n0v, n1v);
                        *(uint32_t*)(Cl + o) = packl2(n0v, n1v);
                    }
                }
                if (flags & 4) {
                    float t0v = diagT ? ((r == n)     ? diagc : 0.f) - a0  : alpha * a0;
                    float t1v = diagT ? ((r == n + 1) ? diagc : 0.f) - a1v : alpha * a1v;
                    bf16 h0, l0, h1, l1;
                    split2(t0v, h0, l0); split2(t1v, h1, l1);
                    ll ot0 = bz * sCT + (ll)n * ldct + r;
                    ll ot1 = bz * sCT + (ll)(n + 1) * ldct + r;
                    CTh[ot0] = h0; CTl[ot0] = l0;
                    CTh[ot1] = h1; CTl[ot1] = l1;
                }
            }
        }
    }
}

// ---------------- fused GEMM + row softmax (attn2) ----------------
__global__ void __launch_bounds__(256, 1) attn_gemm_softmax(
    const bf16* __restrict__ Ah, const bf16* __restrict__ Al,
    const bf16* __restrict__ Bh, const bf16* __restrict__ Bl,
    float* __restrict__ C32, bf16* __restrict__ Ch, bf16* __restrict__ Cl,
    ll sA, ll sB, ll sC)
{
    extern __shared__ char smem[];
    __shared__ float redm[2][32][4];
    __shared__ float reds[2][32][4];
    const int tid = threadIdx.x, wid = tid >> 5, lane = tid & 31;
    const int bz = blockIdx.y;
    const int m0 = blockIdx.x * 64;
    const int wm = (wid & 1) * 32;
    const int wn = (wid >> 1) * 64;
    uint32_t sb = smem_u32(smem);

    const bf16* pAh = Ah + bz * sA + (ll)m0 * 64;
    const bf16* pAl = Al + bz * sA + (ll)m0 * 64;
    const bf16* pBh = Bh + bz * sB;
    const bf16* pBl = Bl + bz * sB;

#pragma unroll
    for (int i = 0; i < 2; i++) {
        int idx = tid + i * 256;
        int r = idx >> 3, c = idx & 7;
        uint32_t so = SWZ128((uint32_t)(r * 128 + c * 16));
        cp16(sb + so, pAh + (ll)r * 64 + c * 8);
        cp16(sb + 8192 + so, pAl + (ll)r * 64 + c * 8);
    }
#pragma unroll
    for (int i = 0; i < 8; i++) {
        int idx = tid + i * 256;
        int r = idx >> 3, c = idx & 7;
        uint32_t so = SWZ128((uint32_t)(r * 128 + c * 16));
        cp16(sb + 16384 + so, pBh + (ll)r * 64 + c * 8);
        cp16(sb + 49152 + so, pBl + (ll)r * 64 + c * 8);
    }
    CP_COMMIT;

    float acc[2][8][4];
#pragma unroll
    for (int a = 0; a < 2; a++)
#pragma unroll
        for (int b = 0; b < 8; b++)
#pragma unroll
            for (int c = 0; c < 4; c++) acc[a][b][c] = 0.f;

    CP_WAIT0;
    __syncthreads();
#pragma unroll
    for (int ks = 0; ks < 4; ks++) {
        uint32_t aH[2][4], aL[2][4];
#pragma unroll
        for (int mi = 0; mi < 2; mi++) {
            int row = wm + mi * 16 + (lane & 15);
            int c16 = ks * 2 + (lane >> 4);
            uint32_t off = SWZ128((uint32_t)(row * 128 + c16 * 16));
            LDSM4(aH[mi], sb + off);
            LDSM4(aL[mi], sb + 8192 + off);
        }
        uint32_t bHf[8][2], bLf[8][2];
#pragma unroll
        for (int bj = 0; bj < 4; bj++) {
            int row = wn + bj * 16 + (lane & 15);
            int c16 = ks * 2 + (lane >> 4);
            uint32_t off = SWZ128((uint32_t)(row * 128 + c16 * 16));
            uint32_t t[4];
            LDSM4(t, sb + 16384 + off);
            bHf[bj * 2][0] = t[0]; bHf[bj * 2 + 1][0] = t[1];
            bHf[bj * 2][1] = t[2]; bHf[bj * 2 + 1][1] = t[3];
            LDSM4(t, sb + 49152 + off);
            bLf[bj * 2][0] = t[0]; bLf[bj * 2 + 1][0] = t[1];
            bLf[bj * 2][1] = t[2]; bLf[bj * 2 + 1][1] = t[3];
        }
#pragma unroll
        for (int mi = 0; mi < 2; mi++)
#pragma unroll
            for (int g = 0; g < 8; g++) MMA16816(acc[mi][g], aH[mi], bHf[g]);
#pragma unroll
        for (int mi = 0; mi < 2; mi++)
#pragma unroll
            for (int g = 0; g < 8; g++) MMA16816(acc[mi][g], aH[mi], bLf[g]);
#pragma unroll
        for (int mi = 0; mi < 2; mi++)
#pragma unroll
            for (int g = 0; g < 8; g++) MMA16816(acc[mi][g], aL[mi], bHf[g]);
    }

    float mx[2][2];
#pragma unroll
    for (int mi = 0; mi < 2; mi++)
#pragma unroll
        for (int half = 0; half < 2; half++) {
            float m = -1e30f;
#pragma unroll
            for (int g = 0; g < 8; g++) {
                m = fmaxf(m, acc[mi][g][half * 2]);
                m = fmaxf(m, acc[mi][g][half * 2 + 1]);
            }
            m = fmaxf(m, __shfl_xor_sync(0xffffffffu, m, 1));
            m = fmaxf(m, __shfl_xor_sync(0xffffffffu, m, 2));
            mx[mi][half] = m;
        }
    if ((lane & 3) == 0) {
#pragma unroll
        for (int mi = 0; mi < 2; mi++)
#pragma unroll
            for (int half = 0; half < 2; half++)
                redm[wid & 1][mi * 16 + (lane >> 2) + half * 8][wid >> 1] = mx[mi][half];
    }
    __syncthreads();
    float sm[2][2];
#pragma unroll
    for (int mi = 0; mi < 2; mi++)
#pragma unroll
        for (int half = 0; half < 2; half++) {
            int ri = mi * 16 + (lane >> 2) + half * 8;
            float m = fmaxf(fmaxf(redm[wid & 1][ri][0], redm[wid & 1][ri][1]),
                            fmaxf(redm[wid & 1][ri][2], redm[wid & 1][ri][3]));
            float s = 0.f;
#pragma unroll
            for (int g = 0; g < 8; g++) {
                float e0 = __expf(acc[mi][g][half * 2] - m);
                float e1 = __expf(acc[mi][g][half * 2 + 1] - m);
                acc[mi][g][half * 2] = e0; acc[mi][g][half * 2 + 1] = e1;
                s += e0 + e1;
            }
            s += __shfl_xor_sync(0xffffffffu, s, 1);
            s += __shfl_xor_sync(0xffffffffu, s, 2);
            sm[mi][half] = s;
        }
    if ((lane & 3) == 0) {
#pragma unroll
        for (int mi = 0; mi < 2; mi++)
#pragma unroll
            for (int half = 0; half < 2; half++)
                reds[wid & 1][mi * 16 + (lane >> 2) + half * 8][wid >> 1] = sm[mi][half];
    }
    __syncthreads();
#pragma unroll
    for (int mi = 0; mi < 2; mi++)
#pragma unroll
        for (int half = 0; half < 2; half++) {
            int ri = mi * 16 + (lane >> 2) + half * 8;
            float tot = reds[wid & 1][ri][0] + reds[wid & 1][ri][1]
                      + reds[wid & 1][ri][2] + reds[wid & 1][ri][3];
            float inv = 1.f / tot;
            int r = m0 + wm + ri;
#pragma unroll
            for (int g = 0; g < 8; g++) {
                int n = wn + g * 8 + (lane & 3) * 2;
                float v0 = acc[mi][g][half * 2] * inv;
                float v1 = acc[mi][g][half * 2 + 1] * inv;
                ll o = bz * sC + (ll)r * 256 + n;
                *(uint32_t*)(Ch + o) = packh2(v0, v1);
                *(uint32_t*)(Cl + o) = packl2(v0, v1);
                *(float2*)(C32 + o) = make_float2(v0, v1);
            }
        }
}

// ---------------- fused attn3 + softmax + @v -> avT (512 thr; 2-term) ----------------
#define VROW 272
__global__ void __launch_bounds__(512, 1) fa3_av(
    const bf16* __restrict__ Qh, const bf16* __restrict__ Ql,
    const bf16* __restrict__ Kh, const bf16* __restrict__ Kl,
    const bf16* __restrict__ Vth, const bf16* __restrict__ Vtl,
    bf16* __restrict__ AVTh, bf16* __restrict__ AVTl,
    ll sQ, ll sK, ll sVT, ll sAVT)
{
    extern __shared__ char smem[];
    __shared__ float Os[64 * 68];
    __shared__ float rsm[64];
    const int tid = threadIdx.x, wid = tid >> 5, lane = tid & 31;
    const int bz = blockIdx.y;
    const int m0 = blockIdx.x * 64;
    const int wm = (wid & 3) * 16;
    const int wn = (wid >> 2) * 32;
    uint32_t sb = smem_u32(smem);
    constexpr uint32_t ST0 = 16384;
    constexpr uint32_t OVT = 32768;
    constexpr uint32_t VLo = OVT + 64 * VROW;
    constexpr uint32_t STG = OVT + 2 * 64 * VROW;

    for (int i = tid; i < 64 * 68; i += 512) Os[i] = 0.f;
    if (tid < 64) rsm[tid] = 0.f;

    const bf16* pQh = Qh + bz * sQ + (ll)m0 * 64;
    const bf16* pKh = Kh + bz * sK;
    const bf16* pKl = Kl + bz * sK;
    const bf16* pVh = Vth + bz * sVT;
    const bf16* pVl = Vtl + bz * sVT;

    {
        int r = tid >> 3, c = tid & 7;
        uint32_t so = SWZ128((uint32_t)(r * 128 + c * 16));
        cp16(sb + so, pQh + (ll)r * 64 + c * 8);
    }
    {
        uint32_t s = sb + ST0;
#pragma unroll
        for (int i = 0; i < 2; i++) {
            int idx = tid + i * 512;
            int r = idx >> 3, c = idx & 7;
            uint32_t so = SWZ128((uint32_t)(r * 128 + c * 16));
            ll g = (ll)r * 64 + c * 8;
            cp16(s + so, pKh + g);
            cp16(s + 16384 + so, pKl + g);
        }
#pragma unroll
        for (int i = 0; i < 2; i++) {
            int idx = tid + i * 512;
            int r = idx >> 4, c = idx & 15;
            uint32_t so = (uint32_t)(r * VROW + c * 16);
            ll g = (ll)r * NTOK + c * 8;
            cp16(s + OVT + so, pVh + g);
            cp16(s + VLo + so, pVl + g);
        }
    }
    CP_COMMIT;

    float acc_o[8][4];
#pragma unroll
    for (int b = 0; b < 8; b++)
#pragma unroll
        for (int c = 0; c < 4; c++) acc_o[b][c] = 0.f;
    float rs[2] = {0.f, 0.f};

    for (int ck = 0; ck < 32; ck++) {
        CP_WAIT0;
        __syncthreads();
        if (ck + 1 < 32) {
            uint32_t s = sb + ST0 + ((ck + 1) & 1) * STG;
            int tok = (ck + 1) * 128;
#pragma unroll
            for (int i = 0; i < 2; i++) {
                int idx = tid + i * 512;
                int r = idx >> 3, c = idx & 7;
                uint32_t so = SWZ128((uint32_t)(r * 128 + c * 16));
                ll g = (ll)(tok + r) * 64 + c * 8;
                cp16(s + so, pKh + g);
                cp16(s + 16384 + so, pKl + g);
            }
#pragma unroll
            for (int i = 0; i < 2; i++) {
                int idx = tid + i * 512;
                int r = idx >> 4, c = idx & 15;
                uint32_t so = (uint32_t)(r * VROW + c * 16);
                ll g = (ll)r * NTOK + tok + c * 8;
                cp16(s + OVT + so, pVh + g);
                cp16(s + VLo + so, pVl + g);
            }
            CP_COMMIT;
        }
        uint32_t s = sb + ST0 + (ck & 1) * STG;

        float accl[4][4];
#pragma unroll
        for (int b = 0; b < 4; b++)
#pragma unroll
            for (int c = 0; c < 4; c++) accl[b][c] = 0.f;
#pragma unroll
        for (int ks = 0; ks < 4; ks++) {
            int c16 = ks * 2 + (lane >> 4);
            uint32_t aH[4];
            {
                int row = wm + (lane & 15);
                uint32_t off = SWZ128((uint32_t)(row * 128 + c16 * 16));
                LDSM4(aH, sb + off);
            }
            uint32_t bHf[4][2], bLf[4][2];
#pragma unroll
            for (int bj = 0; bj < 2; bj++) {
                int row = wn + bj * 16 + (lane & 15);
                uint32_t off = SWZ128((uint32_t)(row * 128 + c16 * 16));
                uint32_t t[4];
                LDSM4(t, s + off);
                bHf[bj * 2][0] = t[0]; bHf[bj * 2 + 1][0] = t[1];
                bHf[bj * 2][1] = t[2]; bHf[bj * 2 + 1][1] = t[3];
                LDSM4(t, s + 16384 + off);
                bLf[bj * 2][0] = t[0]; bLf[bj * 2 + 1][0] = t[1];
                bLf[bj * 2][1] = t[2]; bLf[bj * 2 + 1][1] = t[3];
            }
#pragma unroll
            for (int g = 0; g < 4; g++) MMA16816(accl[g], aH, bHf[g]);
#pragma unroll
            for (int g = 0; g < 4; g++) MMA16816(accl[g], aH, bLf[g]);
        }
#pragma unroll
        for (int half = 0; half < 2; half++) {
            float srow = 0.f;
#pragma unroll
            for (int g = 0; g < 4; g++) {
                float e0 = __expf(accl[g][half * 2]);
                float e1 = __expf(accl[g][half * 2 + 1]);
                accl[g][half * 2] = e0;
                accl[g][half * 2 + 1] = e1;
                srow += e0 + e1;
            }
            rs[half] += srow;
        }
#pragma unroll
        for (int kk = 0; kk < 2; kk++) {
            uint32_t aPh[4];
            aPh[0] = packh2(accl[2 * kk][0], accl[2 * kk][1]);
            aPh[1] = packh2(accl[2 * kk][2], accl[2 * kk][3]);
            aPh[2] = packh2(accl[2 * kk + 1][0], accl[2 * kk + 1][1]);
            aPh[3] = packh2(accl[2 * kk + 1][2], accl[2 * kk + 1][3]);
#pragma unroll
            for (int bj = 0; bj < 4; bj++) {
                uint32_t addr = s + OVT + (uint32_t)((bj * 16 + (lane & 15)) * VROW)
                              + (uint32_t)((wn + kk * 16) * 2 + (lane >> 4) * 16);
                uint32_t t[4], u[4];
                LDSM4(t, addr);
                LDSM4(u, addr + 64 * VROW);
                uint32_t bh0[2] = {t[0], t[2]}, bh1[2] = {t[1], t[3]};
                uint32_t bl0[2] = {u[0], u[2]}, bl1[2] = {u[1], u[3]};
                MMA16816(acc_o[2 * bj],     aPh, bh0);
                MMA16816(acc_o[2 * bj],     aPh, bl0);
                MMA16816(acc_o[2 * bj + 1], aPh, bh1);
                MMA16816(acc_o[2 * bj + 1], aPh, bl1);
            }
        }
    }

#pragma unroll
    for (int half = 0; half < 2; half++) {
        float v = rs[half];
        v += __shfl_xor_sync(0xffffffffu, v, 1);
        v += __shfl_xor_sync(0xffffffffu, v, 2);
        if ((lane & 3) == 0)
            atomicAdd(&rsm[wm + (lane >> 2) + half * 8], v);
    }
#pragma unroll
    for (int g = 0; g < 8; g++) {
        int r0 = wm + (lane >> 2);
        int c = g * 8 + (lane & 3) * 2;
        atomicAdd(&Os[r0 * 68 + c],           acc_o[g][0]);
        atomicAdd(&Os[r0 * 68 + c + 1],       acc_o[g][1]);
        atomicAdd(&Os[(r0 + 8) * 68 + c],     acc_o[g][2]);
        atomicAdd(&Os[(r0 + 8) * 68 + c + 1], acc_o[g][3]);
    }
    __syncthreads();
#pragma unroll
    for (int i = 0; i < 8; i++) {
        int idx = tid + i * 512;
        int r = idx >> 6, d = idx & 63;
        float val = Os[r * 68 + d] / rsm[r];
        bf16 hh, lo; split2(val, hh, lo);
        ll o = bz * sAVT + (ll)d * MLM + (m0 + r);
        AVTh[o] = hh; AVTl[o] = lo;
    }
}

// ---------------- fused attn1 + softmax + P@zav + conv -> y (512 thr; 2-term both GEMMs) ----------------
#define ZROW 528
__global__ void __launch_bounds__(512, 1) attn1_outh(
    const bf16* __restrict__ Ah,
    const bf16* __restrict__ Bh, const bf16* __restrict__ Bl,
    const bf16* __restrict__ Zh, const bf16* __restrict__ Zl,
    const float* __restrict__ Vv, const float* __restrict__ kern,
    bf16* __restrict__ Yh, bf16* __restrict__ Yl,
    ll sA, ll sB, ll sZ, ll sV, int bzoff)
{
    extern __shared__ char smem[];
    __shared__ float redm[4][16][4];
    __shared__ float reds[4][16][4];
    __shared__ float khs[33];
    const int tid = threadIdx.x, wid = tid >> 5, lane = tid & 31;
    const int bz = blockIdx.y + bzoff;
    const int m0 = blockIdx.x * 64;
    const int wm = (wid & 3) * 16;
    const int wn = (wid >> 2) * 64;
    const int b_ = bz >> 3, h_ = bz & 7;
    uint32_t sb = smem_u32(smem);
    constexpr uint32_t OZH = 81920;
    constexpr uint32_t OZL = OZH + 64 * ZROW;
    constexpr uint32_t OO  = OZL + 64 * ZROW;
    constexpr uint32_t OV  = OO + 64 * 68 * 4;
    float* Os = (float*)(smem + OO);
    float* sv = (float*)(smem + OV);

    if (tid < 33) khs[tid] = kern[h_ * 33 + tid];

    const bf16* pAh = Ah + bz * sA + (ll)m0 * 64;
    const bf16* pBh = Bh + bz * sB;
    const bf16* pBl = Bl + bz * sB;
    const bf16* pZh = Zh + bz * sZ;
    const bf16* pZl = Zl + bz * sZ;
    const float* pV = Vv + bz * sV;

    {
        int r = tid >> 3, c = tid & 7;
        uint32_t so = SWZ128((uint32_t)(r * 128 + c * 16));
        cp16(sb + so, pAh + (ll)r * 64 + c * 8);
    }
#pragma unroll
    for (int i = 0; i < 4; i++) {
        int idx = tid + i * 512;
        int r = idx >> 3, c = idx & 7;
        uint32_t so = SWZ128((uint32_t)(r * 128 + c * 16));
        cp16(sb + 16384 + so, pBh + (ll)r * 64 + c * 8);
        cp16(sb + 49152 + so, pBl + (ll)r * 64 + c * 8);
    }
#pragma unroll
    for (int i = 0; i < 4; i++) {
        int idx = tid + i * 512;
        int r = idx >> 5, c = idx & 31;
        uint32_t so = (uint32_t)(r * ZROW + c * 16);
        cp16(sb + OZH + so, pZh + (ll)r * 256 + c * 8);
        cp16(sb + OZL + so, pZl + (ll)r * 256 + c * 8);
    }
#pragma unroll
    for (int i = 0; i < 3; i++) {
        int idx = tid + i * 512;
        int r = idx >> 4, c = idx & 15;
        int tt = m0 - 16 + r;
        if (tt >= 0 && tt < NTOK)
            cp16(sb + OV + (uint32_t)(r * 256 + c * 16), pV + (ll)tt * 64 + c * 4);
        else
            *(float4*)(smem + OV + r * 256 + c * 16) = make_float4(0.f, 0.f, 0.f, 0.f);
    }
    CP_COMMIT;
#pragma unroll
    for (int i = 0; i < 9; i++) {
        int idx = tid + i * 512;
        if (idx < 64 * 68) Os[idx] = 0.f;
    }

    float acc[8][4];
#pragma unroll
    for (int b = 0; b < 8; b++)
#pragma unroll
        for (int c = 0; c < 4; c++) acc[b][c] = 0.f;

    CP_WAIT0;
    __syncthreads();
#pragma unroll
    for (int ks = 0; ks < 4; ks++) {
        uint32_t aH[4];
        {
            int row = wm + (lane & 15);
            int c16 = ks * 2 + (lane >> 4);
            uint32_t off = SWZ128((uint32_t)(row * 128 + c16 * 16));
            LDSM4(aH, sb + off);
        }
        uint32_t bHf[8][2], bLf[8][2];
#pragma unroll
        for (int bj = 0; bj < 4; bj++) {
            int row = wn + bj * 16 + (lane & 15);
            int c16 = ks * 2 + (lane >> 4);
            uint32_t off = SWZ128((uint32_t)(row * 128 + c16 * 16));
            uint32_t t[4];
            LDSM4(t, sb + 16384 + off);
            bHf[bj * 2][0] = t[0]; bHf[bj * 2 + 1][0] = t[1];
            bHf[bj * 2][1] = t[2]; bHf[bj * 2 + 1][1] = t[3];
            LDSM4(t, sb + 49152 + off);
            bLf[bj * 2][0] = t[0]; bLf[bj * 2 + 1][0] = t[1];
            bLf[bj * 2][1] = t[2]; bLf[bj * 2 + 1][1] = t[3];
        }
#pragma unroll
        for (int g = 0; g < 8; g++) MMA16816(acc[g], aH, bHf[g]);
#pragma unroll
        for (int g = 0; g < 8; g++) MMA16816(acc[g], aH, bLf[g]);
    }

    float mx[2];
#pragma unroll
    for (int half = 0; half < 2; half++) {
        float m = -1e30f;
#pragma unroll
        for (int g = 0; g < 8; g++) {
            m = fmaxf(m, acc[g][half * 2]);
            m = fmaxf(m, acc[g][half * 2 + 1]);
        }
        m = fmaxf(m, __shfl_xor_sync(0xffffffffu, m, 1));
        m = fmaxf(m, __shfl_xor_sync(0xffffffffu, m, 2));
        mx[half] = m;
    }
    if ((lane & 3) == 0) {
#pragma unroll
        for (int half = 0; half < 2; half++)
            redm[wid & 3][(lane >> 2) + half * 8][wid >> 2] = mx[half];
    }
    __syncthreads();
    float sm[2];
#pragma unroll
    for (int half = 0; half < 2; half++) {
        int ri = (lane >> 2) + half * 8;
        float m = fmaxf(fmaxf(redm[wid & 3][ri][0], redm[wid & 3][ri][1]),
                        fmaxf(redm[wid & 3][ri][2], redm[wid & 3][ri][3]));
        float s = 0.f;
#pragma unroll
        for (int g = 0; g < 8; g++) {
            float e0 = __expf(acc[g][half * 2] - m);
            float e1 = __expf(acc[g][half * 2 + 1] - m);
            acc[g][half * 2] = e0; acc[g][half * 2 + 1] = e1;
            s += e0 + e1;
        }
        s += __shfl_xor_sync(0xffffffffu, s, 1);
        s += __shfl_xor_sync(0xffffffffu, s, 2);
        sm[half] = s;
    }
    if ((lane & 3) == 0) {
#pragma unroll
        for (int half = 0; half < 2; half++)
            reds[wid & 3][(lane >> 2) + half * 8][wid >> 2] = sm[half];
    }
    __syncthreads();
#pragma unroll
    for (int half = 0; half < 2; half++) {
        int ri = (lane >> 2) + half * 8;
        float tot = reds[wid & 3][ri][0] + reds[wid & 3][ri][1]
                  + reds[wid & 3][ri][2] + reds[wid & 3][ri][3];
        float inv = 1.f / tot;
#pragma unroll
        for (int g = 0; g < 8; g++) {
            acc[g][half * 2]     *= inv;
            acc[g][half * 2 + 1] *= inv;
        }
    }

    float acc_o[8][4];
#pragma unroll
    for (int b = 0; b < 8; b++)
#pragma unroll
        for (int c = 0; c < 4; c++) acc_o[b][c] = 0.f;

#pragma unroll
    for (int ks = 0; ks < 4; ks++) {
        uint32_t aPh[4];
        aPh[0] = packh2(acc[2 * ks][0], acc[2 * ks][1]);
        aPh[1] = packh2(acc[2 * ks][2], acc[2 * ks][3]);
        aPh[2] = packh2(acc[2 * ks + 1][0], acc[2 * ks + 1][1]);
        aPh[3] = packh2(acc[2 * ks + 1][2], acc[2 * ks + 1][3]);
#pragma unroll
        for (int bj = 0; bj < 4; bj++) {
            uint32_t addr = sb + OZH + (uint32_t)((bj * 16 + (lane & 15)) * ZROW)
                          + (uint32_t)((wn + ks * 16) * 2 + (lane >> 4) * 16);
            uint32_t t[4], u[4];
            LDSM4(t, addr);
            LDSM4(u, addr + (OZL - OZH));
            uint32_t bh0[2] = {t[0], t[2]}, bh1[2] = {t[1], t[3]};
            uint32_t bl0[2] = {u[0], u[2]}, bl1[2] = {u[1], u[3]};
            MMA16816(acc_o[2 * bj],     aPh, bh0);
            MMA16816(acc_o[2 * bj],     aPh, bl0);
            MMA16816(acc_o[2 * bj + 1], aPh, bh1);
            MMA16816(acc_o[2 * bj + 1], aPh, bl1);
        }
    }

#pragma unroll
    for (int g = 0; g < 8; g++) {
        int r0 = wm + (lane >> 2);
        int c = g * 8 + (lane & 3) * 2;
        atomicAdd(&Os[r0 * 68 + c],           acc_o[g][0]);
        atomicAdd(&Os[r0 * 68 + c + 1],       acc_o[g][1]);
        atomicAdd(&Os[(r0 + 8) * 68 + c],     acc_o[g][2]);
        atomicAdd(&Os[(r0 + 8) * 68 + c + 1], acc_o[g][3]);
    }
    __syncthreads();
#pragma unroll
    for (int i = 0; i < 8; i++) {
        int idx = tid + i * 512;
        int r = idx >> 6, d = idx & 63;
        float s = Os[r * 68 + d];
#pragma unroll
        for (int j = 0; j < 33; j++)
            s = fmaf(sv[(r + j) * 64 + d], khs[j], s);
        ll yo = ((ll)(b_ * NTOK + m0 + r)) * INNER + h_ * 64 + d;
        bf16 hh, lo; split2(s, hh, lo);
        Yh[yo] = hh; Yl[yo] = lo;
    }
}

// ---------------- elementwise kernels ----------------
__global__ void split_f32(const float* __restrict__ in, bf16* __restrict__ oh,
                          bf16* __restrict__ ol, ll n)
{
    ll i = (ll)blockIdx.x * 256 + threadIdx.x;
    if (i >= n) return;
    bf16 h, l; split2(in[i], h, l);
    oh[i] = h; ol[i] = l;
}

__global__ void transpose_split(const float* __restrict__ in, bf16* __restrict__ oh,
                                bf16* __restrict__ ol, int R, int C, ll sIn, ll sOut,
                                const float* __restrict__ nrmp, float dc, int usediag)
{
    __shared__ float t[32][33];
    ll b = blockIdx.z;
    const float* ip = in + b * sIn;
    int c0 = blockIdx.x * 32, r0 = blockIdx.y * 32;
    int tx = threadIdx.x, ty = threadIdx.y;
#pragma unroll
    for (int i = 0; i < 4; i++)
        t[ty + i * 8][tx] = ip[(ll)(r0 + ty + i * 8) * C + c0 + tx];
    __syncthreads();
    float alpha = nrmp ? 1.f / (nrmp[0] * nrmp[1]) : 1.f;
#pragma unroll
    for (int i = 0; i < 4; i++) {
        int cg = c0 + ty + i * 8, rg = r0 + tx;
        float v = t[tx][ty + i * 8];
        v = usediag ? ((rg == cg ? dc : 0.f) - v) : alpha * v;
        ll o = b * sOut + (ll)cg * R + rg;
        bf16 h, l; split2(v, h, l);
        oh[o] = h; ol[o] = l;
    }
}

__global__ void scale_split(const float* __restrict__ in, bf16* __restrict__ oh,
                            bf16* __restrict__ ol, ll n, const float* __restrict__ nrmp)
{
    ll i = (ll)blockIdx.x * 256 + threadIdx.x;
    if (i >= n) return;
    float inv = 1.f / (nrmp[0] * nrmp[1]);
    bf16 h, l; split2(in[i] * inv, h, l);
    oh[i] = h; ol[i] = l;
}

__global__ void landmark_split_bf(const bf16* __restrict__ xh, const bf16* __restrict__ xl,
                                  bf16* __restrict__ oh, bf16* __restrict__ ol)
{
    ll idx = (ll)blockIdx.x * 256 + threadIdx.x;
    if (idx >= SZ_LM) return;
    int d = (int)(idx & 63);
    int mi = (int)((idx >> 6) & 255);
    ll bh = idx >> 14;
    ll base = (bh * NTOK + (ll)mi * LGRP) * DH + d;
    float s = 0.f;
#pragma unroll
    for (int t = 0; t < LGRP; t++) {
        ll o = base + (ll)t * DH;
        s += __bfloat162float(xh[o]) + __bfloat162float(xl[o]);
    }
    bf16 h, l; split2(s * (1.f / LGRP), h, l);
    oh[idx] = h; ol[idx] = l;
}

__global__ void norm_init_kernel(float* nrm) { nrm[0] = 0.f; nrm[1] = 0.f; }

__global__ void pinv_norm_kernel(const float* __restrict__ x, float* __restrict__ nrm)
{
    int r = threadIdx.x;
    const float* xb = x + (ll)blockIdx.x * MLM * MLM;
    float rs = 0.f, cs = 0.f;
    for (int j = 0; j < MLM; j++) {
        rs += fabsf(xb[(ll)r * MLM + j]);
        cs += fabsf(xb[(ll)j * MLM + r]);
    }
    __shared__ float s1[256], s2[256];
    s1[r] = rs; s2[r] = cs; __syncthreads();
    for (int s = 128; s > 0; s >>= 1) {
        if (r < s) { s1[r] = fmaxf(s1[r], s1[r + s]); s2[r] = fmaxf(s2[r], s2[r + s]); }
        __syncthreads();
    }
    if (r == 0) {
        atomicMax((int*)&nrm[0], __float_as_int(s1[0]));
        atomicMax((int*)&nrm[1], __float_as_int(s2[0]));
    }
}

// ---------------- host ----------------
template<int TM, int TN, int SPLIT, int NT>
static inline void tcg(cudaStream_t st,
                       const bf16* Ah, const bf16* Al, const bf16* Bh, const bf16* Bl,
                       float* C, bf16* Ch, bf16* Cl, bf16* CTh, bf16* CTl,
                       const float* bias,
                       int M, int N, int K, int Kc, int ldc, int ldct,
                       ll sA, ll sB, ll sC, ll sCT, int batch, int kz,
                       float alpha, float diagc, int flags)
{
    dim3 grid(N / TN, M / TM, batch * kz);
    size_t sm = 2 * (size_t)stage_bytes<TM, TN, SPLIT>();
    gemm_mma<TM, TN, SPLIT, NT><<<grid, NT, sm, st>>>(Ah, Al, Bh, Bl, C, Ch, Cl, CTh, CTl, bias,
                                                      K, Kc, batch, ldc, ldct, sA, sB, sC, sCT,
                                                      alpha, diagc, flags);
}

extern "C" void kernel_launch(void* const* d_in, const int* in_sizes, int n_in,
                              void* d_out, int out_size)
{
    const float* x     = (const float*)d_in[0];
    const float* w_qkv = (const float*)d_in[1];
    const float* w_out = (const float*)d_in[2];
    const float* b_out = (const float*)d_in[3];
    const float* res_k = (const float*)d_in[4];
    float* out = (float*)d_out;

    const int A1O_SMEM = 81920 + 2 * 64 * ZROW + 64 * 68 * 4 + 96 * 64 * 4;
    const int FA3_SMEM = 16384 + 2 * (32768 + 2 * 64 * VROW);

    cudaFuncSetAttribute(gemm_mma<128, 128, 1, 512>, cudaFuncAttributeMaxDynamicSharedMemorySize, 131072);
    cudaFuncSetAttribute(gemm_mma<128, 128, 2, 512>, cudaFuncAttributeMaxDynamicSharedMemorySize, 98304);
    cudaFuncSetAttribute(gemm_mma<64, 128, 1, 256>,  cudaFuncAttributeMaxDynamicSharedMemorySize, 98304);
    cudaFuncSetAttribute(gemm_mma<64, 128, 0, 256>,  cudaFuncAttributeMaxDynamicSharedMemorySize, 49152);
    cudaFuncSetAttribute(gemm_mma<64, 64, 1, 256>,   cudaFuncAttributeMaxDynamicSharedMemorySize, 65536);
    cudaFuncSetAttribute(attn_gemm_softmax, cudaFuncAttributeMaxDynamicSharedMemorySize, 81920);
    cudaFuncSetAttribute(attn1_outh, cudaFuncAttributeMaxDynamicSharedMemorySize, A1O_SMEM);
    cudaFuncSetAttribute(fa3_av, cudaFuncAttributeMaxDynamicSharedMemorySize, FA3_SMEM);

    float* F;  cudaGetSymbolAddress((void**)&F, g_f32);
    bf16*  Bp; cudaGetSymbolAddress((void**)&Bp, g_bf);
    float* nrm; cudaGetSymbolAddress((void**)&nrm, g_norm);

    const ll SH = (ll)NTOK * DH, SL = (ll)MLM * DH;
    const ll SA2 = (ll)MLM * MLM;

    cudaStream_t s0 = 0;
    cudaStream_t s2 = g_ctx.s2;

    // prep on s0 (R10 layout)
    {
        dim3 blk(32, 8);
        transpose_split<<<dim3(3 * INNER / 32, DIM / 32, 1), blk, 0, s0>>>(
            w_qkv, Bp + B_WQTH, Bp + B_WQTL, DIM, 3 * INNER, 0, 0, nullptr, 0.f, 0);
        split_f32<<<(int)((SZ_Y + 255) / 256), 256, 0, s0>>>(x, Bp + B_XH, Bp + B_XL, SZ_Y);
    }

    // fork s2: w_out transpose overlaps qkv
    cudaEventRecord(g_ctx.e0, s0);
    cudaStreamWaitEvent(s2, g_ctx.e0, 0);
    transpose_split<<<dim3(DIM / 32, INNER / 32, 1), dim3(32, 8), 0, s2>>>(
        w_out, Bp + B_WOTH, Bp + B_WOTL, INNER, DIM, 0, 0, nullptr, 0.f, 0);

    // 1a. qkv GEMM, q+k columns only — 2-term (x hi-only; softmax downstream washes x_lo)
    tcg<128, 128, 2, 512>(s0, Bp + B_XH, Bp + B_XL, Bp + B_WQTH, Bp + B_WQTL,
                          nullptr, nullptr, nullptr, nullptr, nullptr, nullptr,
                          BB * NTOK, 2 * INNER, DIM, DIM, 0, 0,
                          0, 0, 0, 0, 1, 1, 1.f, 0.f, 64);

    landmark_split_bf<<<(int)((SZ_LM + 255) / 256), 256, 0, s0>>>(Bp + B_QH, Bp + B_QL, Bp + B_QLMH, Bp + B_QLML);
    landmark_split_bf<<<(int)((SZ_LM + 255) / 256), 256, 0, s0>>>(Bp + B_KH, Bp + B_KL, Bp + B_KLMH, Bp + B_KLML);

    // 2. attn2 fused (+fp32 for pinv init)
    attn_gemm_softmax<<<dim3(MLM / 64, BH), 256, 81920, s0>>>(
        Bp + B_QLMH, Bp + B_QLML, Bp + B_KLMH, Bp + B_KLML,
        F + F_A2, Bp + B_A2H, Bp + B_A2L, SL, SL, SA2);

    // fork s2: pinv starts now (before v-columns of qkv)
    cudaEventRecord(g_ctx.e1, s0);
    cudaStreamWaitEvent(s2, g_ctx.e1, 0);

    norm_init_kernel<<<1, 1, 0, s2>>>(nrm);
    pinv_norm_kernel<<<BH, 256, 0, s2>>>(F + F_A2, nrm);
    {
        int blocks = (int)((SZ_A2 + 255) / 256);
        scale_split<<<blocks, 256, 0, s2>>>(F + F_A2, Bp + B_Z0TH, Bp + B_Z0TL, SZ_A2, nrm);
        transpose_split<<<dim3(8, 8, BH), dim3(32, 8), 0, s2>>>(
            F + F_A2, Bp + B_Z0H, Bp + B_Z0L, MLM, MLM, SA2, SA2, nrm, 0.f, 0);
    }

    bf16 *zch = Bp + B_Z0H,  *zcl = Bp + B_Z0L,  *zcth = Bp + B_Z0TH, *zctl = Bp + B_Z0TL;
    bf16 *znh = Bp + B_Z1H,  *znl = Bp + B_Z1L,  *znth = Bp + B_Z1TH, *zntl = Bp + B_Z1TL;

    for (int it = 0; it < 6; it++) {
#define PINV_STEP(S) \
        tcg<64, 128, S, 256>(s2, Bp + B_A2H, Bp + B_A2L, zcth, zctl, \
                    nullptr, Bp + B_XZH, Bp + B_XZL, Bp + B_T1TH, Bp + B_T1TL, nullptr, \
                    MLM, MLM, MLM, MLM, MLM, MLM, SA2, SA2, SA2, SA2, BH, 1, 1.f, 7.f, 2|4|8|16); \
        tcg<64, 128, S, 256>(s2, Bp + B_XZH, Bp + B_XZL, Bp + B_T1TH, Bp + B_T1TL, \
                    nullptr, nullptr, nullptr, Bp + B_T2TH, Bp + B_T2TL, nullptr, \
                    MLM, MLM, MLM, MLM, MLM, MLM, SA2, SA2, 0, SA2, BH, 1, 1.f, 15.f, 4|8); \
        tcg<64, 128, S, 256>(s2, Bp + B_XZH, Bp + B_XZL, Bp + B_T2TH, Bp + B_T2TL, \
                    nullptr, nullptr, nullptr, Bp + B_T3TH, Bp + B_T3TL, nullptr, \
                    MLM, MLM, MLM, MLM, MLM, MLM, SA2, SA2, 0, SA2, BH, 1, 1.f, 13.f, 4|8); \
        tcg<64, 128, S, 256>(s2, zch, zcl, Bp + B_T3TH, Bp + B_T3TL, \
                    nullptr, znh, znl, znth, zntl, nullptr, \
                    MLM, MLM, MLM, MLM, MLM, MLM, SA2, SA2, SA2, SA2, BH, 1, 0.25f, 0.f, 2|4);
        if (it < 5) { PINV_STEP(0) } else { PINV_STEP(1) }
#undef PINV_STEP
        bf16* t;
        t = zch;  zch  = znh;  znh  = t;   t = zcl;  zcl  = znl;  znl  = t;
        t = zcth; zcth = znth; znth = t;   t = zctl; zctl = zntl; zntl = t;
    }
    cudaEventRecord(g_ctx.e2, s2);

    // 1b. qkv GEMM, v columns (N=512, n_base=1024 via ldct) — 3-term, concurrent with pinv
    tcg<128, 128, 1, 512>(s0, Bp + B_XH, Bp + B_XL,
                          Bp + B_WQTH + (ll)2 * INNER * DIM, Bp + B_WQTL + (ll)2 * INNER * DIM,
                          nullptr, nullptr, nullptr, nullptr, nullptr, nullptr,
                          BB * NTOK, INNER, DIM, DIM, 0, 2 * INNER,
                          0, 0, 0, 0, 1, 1, 1.f, 0.f, 64);

    // 3. fa3 (s0), concurrent with pinv (s2)
    fa3_av<<<dim3(MLM / 64, BH), 512, FA3_SMEM, s0>>>(
        Bp + B_QLMH, Bp + B_QLML, Bp + B_KH, Bp + B_KL,
        Bp + B_VTH, Bp + B_VTL, Bp + B_AVTH, Bp + B_AVTL,
        SL, SH, SH, SL);

    // join pinv
    cudaStreamWaitEvent(s0, g_ctx.e2, 0);

    // 4. zav^T = (z @ av)^T
    tcg<64, 64, 1, 256>(s0, zch, zcl, Bp + B_AVTH, Bp + B_AVTL,
                        nullptr, nullptr, nullptr, Bp + B_ZVTH, Bp + B_ZVTL, nullptr,
                        MLM, DH, MLM, MLM, DH, MLM, SA2, SL, 0, SL, BH, 1, 1.f, 0.f, 4);

    // 5. a1o chunk0 (bz 0..15) then chunk1; out-proj chunk0 overlaps chunk1 on s2
    attn1_outh<<<dim3(NTOK / 64, 16), 512, A1O_SMEM, s0>>>(
        Bp + B_QH, Bp + B_KLMH, Bp + B_KLML,
        Bp + B_ZVTH, Bp + B_ZVTL, F + F_V, res_k,
        Bp + B_YH, Bp + B_YL, SH, SL, SL, SH, 0);
    cudaEventRecord(g_ctx.e3, s0);

    attn1_outh<<<dim3(NTOK / 64, 16), 512, A1O_SMEM, s0>>>(
        Bp + B_QH, Bp + B_KLMH, Bp + B_KLML,
        Bp + B_ZVTH, Bp + B_ZVTL, F + F_V, res_k,
        Bp + B_YH, Bp + B_YL, SH, SL, SL, SH, 16);

    cudaStreamWaitEvent(s2, g_ctx.e3, 0);
    // out-proj rows 0..8191 on s2 (3-term, precision-critical)
    tcg<128, 128, 1, 512>(s2, Bp + B_YH, Bp + B_YL, Bp + B_WOTH, Bp + B_WOTL,
                          out, nullptr, nullptr, nullptr, nullptr, b_out,
                          2 * NTOK, DIM, INNER, INNER, DIM, 0, 0, 0, 0, 0, 1, 1, 1.f, 0.f, 1);
    cudaEventRecord(g_ctx.e4, s2);

    // out-proj rows 8192..16383 on s0
    tcg<128, 128, 1, 512>(s0, Bp + B_YH + (ll)2 * NTOK * INNER, Bp + B_YL + (ll)2 * NTOK * INNER,
                          Bp + B_WOTH, Bp + B_WOTL,
                          out + (ll)2 * NTOK * DIM, nullptr, nullptr, nullptr, nullptr, b_out,
                          2 * NTOK, DIM, INNER, INNER, DIM, 0, 0, 0, 0, 0, 1, 1, 1.f, 0.f, 1);

    // final join
    cudaStreamWaitEvent(s0, g_ctx.e4, 0);
}

// round 15
// speedup vs baseline: 1.0738x; 1.0150x over previous
#include <cuda_runtime.h>
#include <cuda_bf16.h>
#include <cstdint>

typedef __nv_bfloat16 bf16;
typedef long long ll;

#define BB    4
#define NTOK  4096
#define DIM   512
#define H     8
#define DH    64
#define MLM   256
#define LGRP  16
#define BH    32
#define INNER 512

// ---------------- sizes ----------------
static const ll SZ_Y     = (ll)BB*NTOK*INNER;
static const ll SZ_HEADS = (ll)BH*NTOK*DH;
static const ll SZ_LM    = (ll)BH*MLM*DH;
static const ll SZ_A2    = (ll)BH*MLM*MLM;

// fp32 scratch
static const ll F_V    = 0;
static const ll F_A2   = F_V    + SZ_HEADS;
static const ll F_TOTAL= F_A2   + SZ_A2;

// bf16 scratch
static const ll B_XH   = 0;
static const ll B_XL   = B_XH   + SZ_Y;
static const ll B_WQTH = B_XL   + SZ_Y;
static const ll B_WQTL = B_WQTH + (ll)DIM*3*INNER;
static const ll B_WOTH = B_WQTL + (ll)DIM*3*INNER;
static const ll B_WOTL = B_WOTH + (ll)DIM*INNER;
static const ll B_QH   = B_WOTL + (ll)DIM*INNER;
static const ll B_QL   = B_QH   + SZ_HEADS;
static const ll B_KH   = B_QL   + SZ_HEADS;
static const ll B_KL   = B_KH   + SZ_HEADS;
static const ll B_VTH  = B_KL   + SZ_HEADS;
static const ll B_VTL  = B_VTH  + SZ_HEADS;
static const ll B_QLMH = B_VTL  + SZ_HEADS;
static const ll B_QLML = B_QLMH + SZ_LM;
static const ll B_KLMH = B_QLML + SZ_LM;
static const ll B_KLML = B_KLMH + SZ_LM;
static const ll B_A2H  = B_KLML + SZ_LM;
static const ll B_A2L  = B_A2H  + SZ_A2;
static const ll B_Z0H  = B_A2L  + SZ_A2;
static const ll B_Z0L  = B_Z0H  + SZ_A2;
static const ll B_Z0TH = B_Z0L  + SZ_A2;
static const ll B_Z0TL = B_Z0TH + SZ_A2;
static const ll B_Z1H  = B_Z0TL + SZ_A2;
static const ll B_Z1L  = B_Z1H  + SZ_A2;
static const ll B_Z1TH = B_Z1L  + SZ_A2;
static const ll B_Z1TL = B_Z1TH + SZ_A2;
static const ll B_XZH  = B_Z1TL + SZ_A2;
static const ll B_XZL  = B_XZH  + SZ_A2;
static const ll B_T1TH = B_XZL  + SZ_A2;
static const ll B_T1TL = B_T1TH + SZ_A2;
static const ll B_T2TH = B_T1TL + SZ_A2;
static const ll B_T2TL = B_T2TH + SZ_A2;
static const ll B_T3TH = B_T2TL + SZ_A2;
static const ll B_T3TL = B_T3TH + SZ_A2;
static const ll B_AVTH = B_T3TL + SZ_A2;
static const ll B_AVTL = B_AVTH + SZ_LM;
static const ll B_ZVTH = B_AVTL + SZ_LM;
static const ll B_ZVTL = B_ZVTH + SZ_LM;
static const ll B_YH   = B_ZVTL + SZ_LM;
static const ll B_YL   = B_YH   + SZ_Y;
static const ll B_TOTAL= B_YL   + SZ_Y;

__device__ __align__(16) float g_f32[F_TOTAL];
__device__ __align__(16) bf16  g_bf[B_TOTAL];
__device__ float g_norm[2];

// ---------------- stream/event context ----------------
struct StreamCtx {
    cudaStream_t s2;
    cudaEvent_t e0, e1, e2, e3, e4;
    StreamCtx() {
        cudaStreamCreateWithFlags(&s2, cudaStreamNonBlocking);
        cudaEventCreateWithFlags(&e0, cudaEventDisableTiming);
        cudaEventCreateWithFlags(&e1, cudaEventDisableTiming);
        cudaEventCreateWithFlags(&e2, cudaEventDisableTiming);
        cudaEventCreateWithFlags(&e3, cudaEventDisableTiming);
        cudaEventCreateWithFlags(&e4, cudaEventDisableTiming);
    }
};
static StreamCtx g_ctx;

// ---------------- helpers ----------------
__device__ __forceinline__ uint32_t smem_u32(const void* p) {
    uint32_t a;
    asm("{ .reg .u64 t; cvta.to.shared.u64 t, %1; cvt.u32.u64 %0, t; }" : "=r"(a) : "l"(p));
    return a;
}
__device__ __forceinline__ void cp16(uint32_t s, const void* g) {
    asm volatile("cp.async.cg.shared.global [%0], [%1], 16;" :: "r"(s), "l"(g));
}
#define CP_COMMIT asm volatile("cp.async.commit_group;" ::: "memory")
#define CP_WAIT0  asm volatile("cp.async.wait_group 0;" ::: "memory")

#define LDSM4(R, A) \
    asm volatile("ldmatrix.sync.aligned.m8n8.x4.shared.b16 {%0,%1,%2,%3}, [%4];" \
        : "=r"((R)[0]), "=r"((R)[1]), "=r"((R)[2]), "=r"((R)[3]) : "r"(A))

#define MMA16816(D, Aa, Bb) \
    asm volatile("mma.sync.aligned.m16n8k16.row.col.f32.bf16.bf16.f32 " \
        "{%0,%1,%2,%3}, {%4,%5,%6,%7}, {%8,%9}, {%0,%1,%2,%3};" \
        : "+f"((D)[0]), "+f"((D)[1]), "+f"((D)[2]), "+f"((D)[3]) \
        : "r"((Aa)[0]), "r"((Aa)[1]), "r"((Aa)[2]), "r"((Aa)[3]), \
          "r"((Bb)[0]), "r"((Bb)[1]))

#define SWZ128(o) ((o) ^ (((o) >> 3) & 0x70))

__device__ __forceinline__ void split2(float v, bf16& h, bf16& l) {
    h = __float2bfloat16(v);
    l = __float2bfloat16(v - __bfloat162float(h));
}
__device__ __forceinline__ uint32_t packh2(float a, float b) {
    __nv_bfloat162 p; p.x = __float2bfloat16(a); p.y = __float2bfloat16(b);
    return *(uint32_t*)&p;
}
__device__ __forceinline__ uint32_t packl2(float a, float b) {
    __nv_bfloat162 p;
    p.x = __float2bfloat16(a - __bfloat162float(__float2bfloat16(a)));
    p.y = __float2bfloat16(b - __bfloat162float(__float2bfloat16(b)));
    return *(uint32_t*)&p;
}

// ---------------- generic split-bf16 HMMA NT GEMM ----------------
// SPLIT modes: 0 = hi-only, 1 = full split (3 terms), 2 = A-hi/B-split (2 terms)
template<int TM, int TN, int SPLIT>
__host__ __device__ constexpr int stage_bytes() {
    return ((SPLIT == 1) ? 2 * (TM + TN) : (SPLIT == 2) ? (TM + 2 * TN) : (TM + TN)) * 128;
}

template<int TM, int TN, int SPLIT, int NT>
__device__ __forceinline__ void load_stage(uint32_t sbase,
    const bf16* pAh, const bf16* pAl, const bf16* pBh, const bf16* pBl,
    int K, int k0, int tid)
{
    constexpr uint32_t OAL = TM * 128;
    constexpr uint32_t OBH = ((SPLIT == 1) ? 2 : 1) * TM * 128;
    constexpr uint32_t OBL = OBH + TN * 128;
#pragma unroll
    for (int i = 0; i < TM * 8 / NT; i++) {
        int idx = tid + i * NT;
        int r = idx >> 3, c = idx & 7;
        uint32_t so = SWZ128((uint32_t)(r * 128 + c * 16));
        ll go = (ll)r * K + k0 + c * 8;
        cp16(sbase + so, pAh + go);
        if (SPLIT == 1) cp16(sbase + OAL + so, pAl + go);
    }
#pragma unroll
    for (int i = 0; i < TN * 8 / NT; i++) {
        int idx = tid + i * NT;
        int r = idx >> 3, c = idx & 7;
        uint32_t so = SWZ128((uint32_t)(r * 128 + c * 16));
        ll go = (ll)r * K + k0 + c * 8;
        cp16(sbase + OBH + so, pBh + go);
        if (SPLIT >= 1) cp16(sbase + OBL + so, pBl + go);
    }
}

template<int TM, int TN, int SPLIT, int NT>
__global__ void __launch_bounds__(NT, (NT == 256 && TM == 64) ? 2 : 1) gemm_mma(
    const bf16* __restrict__ Ah, const bf16* __restrict__ Al,
    const bf16* __restrict__ Bh, const bf16* __restrict__ Bl,
    float* __restrict__ C, bf16* __restrict__ Ch, bf16* __restrict__ Cl,
    bf16* __restrict__ CTh, bf16* __restrict__ CTl,
    const float* __restrict__ bias,
    int K, int Kc, int nbatch, int ldc, int ldct,
    ll sA, ll sB, ll sC, ll sCT,
    float alpha, float diagc, int flags)
{
    extern __shared__ char smem[];
    constexpr int WR = (NT == 512) ? 4 : 2;
    constexpr int MI = TM / WR / 16;
    constexpr int NG = TN / 4 / 8;
    constexpr uint32_t OBH = ((SPLIT == 1) ? 2 : 1) * TM * 128;
    constexpr uint32_t OBL = OBH + TN * 128;
    constexpr int STAGE = stage_bytes<TM, TN, SPLIT>();

    const int tid = threadIdx.x, wid = tid >> 5, lane = tid & 31;
    const int bz = blockIdx.z % nbatch;
    const int koff = (blockIdx.z / nbatch) * Kc;
    const int m0 = blockIdx.y * TM, n0 = blockIdx.x * TN;
    const int wm = (wid % WR) * (TM / WR);
    const int wn = (wid / WR) * (TN / 4);
    uint32_t sb = smem_u32(smem);

    const bf16* pAh = Ah + bz * sA + (ll)m0 * K + koff;
    const bf16* pAl = (SPLIT == 1) ? (Al + bz * sA + (ll)m0 * K + koff) : pAh;
    const bf16* pBh = Bh + bz * sB + (ll)n0 * K + koff;
    const bf16* pBl = (SPLIT >= 1) ? (Bl + bz * sB + (ll)n0 * K + koff) : pBh;

    float acc[MI][NG][4];
#pragma unroll
    for (int a = 0; a < MI; a++)
#pragma unroll
        for (int b = 0; b < NG; b++)
#pragma unroll
            for (int c = 0; c < 4; c++) acc[a][b][c] = 0.f;

    const int nch = Kc >> 6;
    load_stage<TM, TN, SPLIT, NT>(sb, pAh, pAl, pBh, pBl, K, 0, tid);
    CP_COMMIT;

    for (int ck = 0; ck < nch; ck++) {
        CP_WAIT0;
        __syncthreads();
        if (ck + 1 < nch) {
            load_stage<TM, TN, SPLIT, NT>(sb + ((ck + 1) & 1) * STAGE, pAh, pAl, pBh, pBl, K, (ck + 1) * 64, tid);
            CP_COMMIT;
        }
        uint32_t s = sb + (ck & 1) * STAGE;
#pragma unroll
        for (int ks = 0; ks < 4; ks++) {
            uint32_t aH[MI][4], aL[MI][4];
#pragma unroll
            for (int mi = 0; mi < MI; mi++) {
                int row = wm + mi * 16 + (lane & 15);
                int c16 = ks * 2 + (lane >> 4);
                uint32_t off = SWZ128((uint32_t)(row * 128 + c16 * 16));
                LDSM4(aH[mi], s + off);
                if (SPLIT == 1) LDSM4(aL[mi], s + TM * 128 + off);
            }
            uint32_t bH[NG][2], bL[NG][2];
#pragma unroll
            for (int bj = 0; bj < NG / 2; bj++) {
                int row = wn + bj * 16 + (lane & 15);
                int c16 = ks * 2 + (lane >> 4);
                uint32_t off = SWZ128((uint32_t)(row * 128 + c16 * 16));
                uint32_t t[4];
                LDSM4(t, s + OBH + off);
                bH[bj * 2][0] = t[0]; bH[bj * 2 + 1][0] = t[1];
                bH[bj * 2][1] = t[2]; bH[bj * 2 + 1][1] = t[3];
                if (SPLIT >= 1) {
                    LDSM4(t, s + OBL + off);
                    bL[bj * 2][0] = t[0]; bL[bj * 2 + 1][0] = t[1];
                    bL[bj * 2][1] = t[2]; bL[bj * 2 + 1][1] = t[3];
                }
            }
#pragma unroll
            for (int mi = 0; mi < MI; mi++)
#pragma unroll
                for (int g = 0; g < NG; g++) MMA16816(acc[mi][g], aH[mi], bH[g]);
            if (SPLIT >= 1) {
#pragma unroll
                for (int mi = 0; mi < MI; mi++)
#pragma unroll
                    for (int g = 0; g < NG; g++) MMA16816(acc[mi][g], aH[mi], bL[g]);
            }
            if (SPLIT == 1) {
#pragma unroll
                for (int mi = 0; mi < MI; mi++)
#pragma unroll
                    for (int g = 0; g < NG; g++) MMA16816(acc[mi][g], aL[mi], bH[g]);
            }
        }
    }

    const bool diagT = (flags & 8) != 0;
    const bool diagN = diagT && !(flags & 16);
#pragma unroll
    for (int mi = 0; mi < MI; mi++) {
#pragma unroll
        for (int g = 0; g < NG; g++) {
#pragma unroll
            for (int half = 0; half < 2; half++) {
                int r = m0 + wm + mi * 16 + (lane >> 2) + half * 8;
                int n = n0 + wn + g * 8 + (lane & 3) * 2;
                float a0 = acc[mi][g][half * 2 + 0];
                float a1v = acc[mi][g][half * 2 + 1];
                if (flags & 64) {
                    int nq = n + ldct;
                    int sel = nq >> 9;
                    int hh = (nq >> 6) & 7;
                    int d  = nq & 63;
                    int b  = r >> 12, t = r & 4095;
                    ll hidx = ((ll)((b << 3) + hh) * NTOK + t) * 64 + d;
                    if (sel == 0) {
                        *(uint32_t*)(g_bf + B_QH + hidx) = packh2(a0 * 0.125f, a1v * 0.125f);
                        *(uint32_t*)(g_bf + B_QL + hidx) = packl2(a0 * 0.125f, a1v * 0.125f);
                    } else if (sel == 1) {
                        *(uint32_t*)(g_bf + B_KH + hidx) = packh2(a0, a1v);
                        *(uint32_t*)(g_bf + B_KL + hidx) = packl2(a0, a1v);
                    } else {
                        *(float2*)(g_f32 + F_V + hidx) = make_float2(a0, a1v);
                        bf16 h0, l0, h1, l1;
                        split2(a0, h0, l0); split2(a1v, h1, l1);
                        ll vt = ((ll)((b << 3) + hh) * 64 + d) * NTOK + t;
                        g_bf[B_VTH + vt] = h0;        g_bf[B_VTL + vt] = l0;
                        g_bf[B_VTH + vt + NTOK] = h1; g_bf[B_VTL + vt + NTOK] = l1;
                    }
                    continue;
                }
                if (flags & 3) {
                    float n0v = diagN ? ((r == n)     ? diagc : 0.f) - a0  : alpha * a0;
                    float n1v = diagN ? ((r == n + 1) ? diagc : 0.f) - a1v : alpha * a1v;
                    if (bias) { n0v += bias[n]; n1v += bias[n + 1]; }
                    ll o = bz * sC + (ll)r * ldc + n;
                    if (flags & 1) {
                        if (flags & 32) { atomicAdd(C + o, n0v); atomicAdd(C + o + 1, n1v); }
                        else *(float2*)(C + o) = make_float2(n0v, n1v);
                    }
                    if (flags & 2) {
                        *(uint32_t*)(Ch + o) = packh2(n0v, n1v);
                        *(uint32_t*)(Cl + o) = packl2(n0v, n1v);
                    }
                }
                if (flags & 4) {
                    float t0v = diagT ? ((r == n)     ? diagc : 0.f) - a0  : alpha * a0;
                    float t1v = diagT ? ((r == n + 1) ? diagc : 0.f) - a1v : alpha * a1v;
                    bf16 h0, l0, h1, l1;
                    split2(t0v, h0, l0); split2(t1v, h1, l1);
                    ll ot0 = bz * sCT + (ll)n * ldct + r;
                    ll ot1 = bz * sCT + (ll)(n + 1) * ldct + r;
                    CTh[ot0] = h0; CTl[ot0] = l0;
                    CTh[ot1] = h1; CTl[ot1] = l1;
                }
            }
        }
    }
}

// ---------------- fused GEMM + row softmax (attn2) ----------------
__global__ void __launch_bounds__(256, 1) attn_gemm_softmax(
    const bf16* __restrict__ Ah, const bf16* __restrict__ Al,
    const bf16* __restrict__ Bh, const bf16* __restrict__ Bl,
    float* __restrict__ C32, bf16* __restrict__ Ch, bf16* __restrict__ Cl,
    ll sA, ll sB, ll sC)
{
    extern __shared__ char smem[];
    __shared__ float redm[2][32][4];
    __shared__ float reds[2][32][4];
    const int tid = threadIdx.x, wid = tid >> 5, lane = tid & 31;
    const int bz = blockIdx.y;
    const int m0 = blockIdx.x * 64;
    const int wm = (wid & 1) * 32;
    const int wn = (wid >> 1) * 64;
    uint32_t sb = smem_u32(smem);

    const bf16* pAh = Ah + bz * sA + (ll)m0 * 64;
    const bf16* pAl = Al + bz * sA + (ll)m0 * 64;
    const bf16* pBh = Bh + bz * sB;
    const bf16* pBl = Bl + bz * sB;

#pragma unroll
    for (int i = 0; i < 2; i++) {
        int idx = tid + i * 256;
        int r = idx >> 3, c = idx & 7;
        uint32_t so = SWZ128((uint32_t)(r * 128 + c * 16));
        cp16(sb + so, pAh + (ll)r * 64 + c * 8);
        cp16(sb + 8192 + so, pAl + (ll)r * 64 + c * 8);
    }
#pragma unroll
    for (int i = 0; i < 8; i++) {
        int idx = tid + i * 256;
        int r = idx >> 3, c = idx & 7;
        uint32_t so = SWZ128((uint32_t)(r * 128 + c * 16));
        cp16(sb + 16384 + so, pBh + (ll)r * 64 + c * 8);
        cp16(sb + 49152 + so, pBl + (ll)r * 64 + c * 8);
    }
    CP_COMMIT;

    float acc[2][8][4];
#pragma unroll
    for (int a = 0; a < 2; a++)
#pragma unroll
        for (int b = 0; b < 8; b++)
#pragma unroll
            for (int c = 0; c < 4; c++) acc[a][b][c] = 0.f;

    CP_WAIT0;
    __syncthreads();
#pragma unroll
    for (int ks = 0; ks < 4; ks++) {
        uint32_t aH[2][4], aL[2][4];
#pragma unroll
        for (int mi = 0; mi < 2; mi++) {
            int row = wm + mi * 16 + (lane & 15);
            int c16 = ks * 2 + (lane >> 4);
            uint32_t off = SWZ128((uint32_t)(row * 128 + c16 * 16));
            LDSM4(aH[mi], sb + off);
            LDSM4(aL[mi], sb + 8192 + off);
        }
        uint32_t bHf[8][2], bLf[8][2];
#pragma unroll
        for (int bj = 0; bj < 4; bj++) {
            int row = wn + bj * 16 + (lane & 15);
            int c16 = ks * 2 + (lane >> 4);
            uint32_t off = SWZ128((uint32_t)(row * 128 + c16 * 16));
            uint32_t t[4];
            LDSM4(t, sb + 16384 + off);
            bHf[bj * 2][0] = t[0]; bHf[bj * 2 + 1][0] = t[1];
            bHf[bj * 2][1] = t[2]; bHf[bj * 2 + 1][1] = t[3];
            LDSM4(t, sb + 49152 + off);
            bLf[bj * 2][0] = t[0]; bLf[bj * 2 + 1][0] = t[1];
            bLf[bj * 2][1] = t[2]; bLf[bj * 2 + 1][1] = t[3];
        }
#pragma unroll
        for (int mi = 0; mi < 2; mi++)
#pragma unroll
            for (int g = 0; g < 8; g++) MMA16816(acc[mi][g], aH[mi], bHf[g]);
#pragma unroll
        for (int mi = 0; mi < 2; mi++)
#pragma unroll
            for (int g = 0; g < 8; g++) MMA16816(acc[mi][g], aH[mi], bLf[g]);
#pragma unroll
        for (int mi = 0; mi < 2; mi++)
#pragma unroll
            for (int g = 0; g < 8; g++) MMA16816(acc[mi][g], aL[mi], bHf[g]);
    }

    float mx[2][2];
#pragma unroll
    for (int mi = 0; mi < 2; mi++)
#pragma unroll
        for (int half = 0; half < 2; half++) {
            float m = -1e30f;
#pragma unroll
            for (int g = 0; g < 8; g++) {
                m = fmaxf(m, acc[mi][g][half * 2]);
                m = fmaxf(m, acc[mi][g][half * 2 + 1]);
            }
            m = fmaxf(m, __shfl_xor_sync(0xffffffffu, m, 1));
            m = fmaxf(m, __shfl_xor_sync(0xffffffffu, m, 2));
            mx[mi][half] = m;
        }
    if ((lane & 3) == 0) {
#pragma unroll
        for (int mi = 0; mi < 2; mi++)
#pragma unroll
            for (int half = 0; half < 2; half++)
                redm[wid & 1][mi * 16 + (lane >> 2) + half * 8][wid >> 1] = mx[mi][half];
    }
    __syncthreads();
    float sm[2][2];
#pragma unroll
    for (int mi = 0; mi < 2; mi++)
#pragma unroll
        for (int half = 0; half < 2; half++) {
            int ri = mi * 16 + (lane >> 2) + half * 8;
            float m = fmaxf(fmaxf(redm[wid & 1][ri][0], redm[wid & 1][ri][1]),
                            fmaxf(redm[wid & 1][ri][2], redm[wid & 1][ri][3]));
            float s = 0.f;
#pragma unroll
            for (int g = 0; g < 8; g++) {
                float e0 = __expf(acc[mi][g][half * 2] - m);
                float e1 = __expf(acc[mi][g][half * 2 + 1] - m);
                acc[mi][g][half * 2] = e0; acc[mi][g][half * 2 + 1] = e1;
                s += e0 + e1;
            }
            s += __shfl_xor_sync(0xffffffffu, s, 1);
            s += __shfl_xor_sync(0xffffffffu, s, 2);
            sm[mi][half] = s;
        }
    if ((lane & 3) == 0) {
#pragma unroll
        for (int mi = 0; mi < 2; mi++)
#pragma unroll
            for (int half = 0; half < 2; half++)
                reds[wid & 1][mi * 16 + (lane >> 2) + half * 8][wid >> 1] = sm[mi][half];
    }
    __syncthreads();
#pragma unroll
    for (int mi = 0; mi < 2; mi++)
#pragma unroll
        for (int half = 0; half < 2; half++) {
            int ri = mi * 16 + (lane >> 2) + half * 8;
            float tot = reds[wid & 1][ri][0] + reds[wid & 1][ri][1]
                      + reds[wid & 1][ri][2] + reds[wid & 1][ri][3];
            float inv = 1.f / tot;
            int r = m0 + wm + ri;
#pragma unroll
            for (int g = 0; g < 8; g++) {
                int n = wn + g * 8 + (lane & 3) * 2;
                float v0 = acc[mi][g][half * 2] * inv;
                float v1 = acc[mi][g][half * 2 + 1] * inv;
                ll o = bz * sC + (ll)r * 256 + n;
                *(uint32_t*)(Ch + o) = packh2(v0, v1);
                *(uint32_t*)(Cl + o) = packl2(v0, v1);
                *(float2*)(C32 + o) = make_float2(v0, v1);
            }
        }
}

// ---------------- fused attn3 + softmax + @v -> avT (512 thr; 1-term logits, 2-term PV) ----------------
#define VROW 272
__global__ void __launch_bounds__(512, 1) fa3_av(
    const bf16* __restrict__ Qh,
    const bf16* __restrict__ Kh,
    const bf16* __restrict__ Vth, const bf16* __restrict__ Vtl,
    bf16* __restrict__ AVTh, bf16* __restrict__ AVTl,
    ll sQ, ll sK, ll sVT, ll sAVT)
{
    extern __shared__ char smem[];
    __shared__ float Os[64 * 68];
    __shared__ float rsm[64];
    const int tid = threadIdx.x, wid = tid >> 5, lane = tid & 31;
    const int bz = blockIdx.y;
    const int m0 = blockIdx.x * 64;
    const int wm = (wid & 3) * 16;
    const int wn = (wid >> 2) * 32;
    uint32_t sb = smem_u32(smem);
    constexpr uint32_t ST0 = 8192;                  // q hi only
    constexpr uint32_t OVT = 16384;                 // vt hi within stage (after 16KB k hi)
    constexpr uint32_t VLo = OVT + 64 * VROW;
    constexpr uint32_t STG = OVT + 2 * 64 * VROW;   // 16384 + 34816 = 51200

    for (int i = tid; i < 64 * 68; i += 512) Os[i] = 0.f;
    if (tid < 64) rsm[tid] = 0.f;

    const bf16* pQh = Qh + bz * sQ + (ll)m0 * 64;
    const bf16* pKh = Kh + bz * sK;
    const bf16* pVh = Vth + bz * sVT;
    const bf16* pVl = Vtl + bz * sVT;

    // resident q hi tile
    {
        int r = tid >> 3, c = tid & 7;
        uint32_t so = SWZ128((uint32_t)(r * 128 + c * 16));
        cp16(sb + so, pQh + (ll)r * 64 + c * 8);
    }
    // chunk 0: k hi + v hi/lo
    {
        uint32_t s = sb + ST0;
#pragma unroll
        for (int i = 0; i < 2; i++) {
            int idx = tid + i * 512;
            int r = idx >> 3, c = idx & 7;
            uint32_t so = SWZ128((uint32_t)(r * 128 + c * 16));
            cp16(s + so, pKh + (ll)r * 64 + c * 8);
        }
#pragma unroll
        for (int i = 0; i < 2; i++) {
            int idx = tid + i * 512;
            int r = idx >> 4, c = idx & 15;
            uint32_t so = (uint32_t)(r * VROW + c * 16);
            ll g = (ll)r * NTOK + c * 8;
            cp16(s + OVT + so, pVh + g);
            cp16(s + VLo + so, pVl + g);
        }
    }
    CP_COMMIT;

    float acc_o[8][4];
#pragma unroll
    for (int b = 0; b < 8; b++)
#pragma unroll
        for (int c = 0; c < 4; c++) acc_o[b][c] = 0.f;
    float rs[2] = {0.f, 0.f};

    for (int ck = 0; ck < 32; ck++) {
        CP_WAIT0;
        __syncthreads();
        if (ck + 1 < 32) {
            uint32_t s = sb + ST0 + ((ck + 1) & 1) * STG;
            int tok = (ck + 1) * 128;
#pragma unroll
            for (int i = 0; i < 2; i++) {
                int idx = tid + i * 512;
                int r = idx >> 3, c = idx & 7;
                uint32_t so = SWZ128((uint32_t)(r * 128 + c * 16));
                cp16(s + so, pKh + (ll)(tok + r) * 64 + c * 8);
            }
#pragma unroll
            for (int i = 0; i < 2; i++) {
                int idx = tid + i * 512;
                int r = idx >> 4, c = idx & 15;
                uint32_t so = (uint32_t)(r * VROW + c * 16);
                ll g = (ll)r * NTOK + tok + c * 8;
                cp16(s + OVT + so, pVh + g);
                cp16(s + VLo + so, pVl + g);
            }
            CP_COMMIT;
        }
        uint32_t s = sb + ST0 + (ck & 1) * STG;

        // logits: qh·kh only (1-term; q_lo & k_lo wash through softmax)
        float accl[4][4];
#pragma unroll
        for (int b = 0; b < 4; b++)
#pragma unroll
            for (int c = 0; c < 4; c++) accl[b][c] = 0.f;
#pragma unroll
        for (int ks = 0; ks < 4; ks++) {
            int c16 = ks * 2 + (lane >> 4);
            uint32_t aH[4];
            {
                int row = wm + (lane & 15);
                uint32_t off = SWZ128((uint32_t)(row * 128 + c16 * 16));
                LDSM4(aH, sb + off);
            }
            uint32_t bHf[4][2];
#pragma unroll
            for (int bj = 0; bj < 2; bj++) {
                int row = wn + bj * 16 + (lane & 15);
                uint32_t off = SWZ128((uint32_t)(row * 128 + c16 * 16));
                uint32_t t[4];
                LDSM4(t, s + off);
                bHf[bj * 2][0] = t[0]; bHf[bj * 2 + 1][0] = t[1];
                bHf[bj * 2][1] = t[2]; bHf[bj * 2 + 1][1] = t[3];
            }
#pragma unroll
            for (int g = 0; g < 4; g++) MMA16816(accl[g], aH, bHf[g]);
        }
        // exp (no max) + rowsum
#pragma unroll
        for (int half = 0; half < 2; half++) {
            float srow = 0.f;
#pragma unroll
            for (int g = 0; g < 4; g++) {
                float e0 = __expf(accl[g][half * 2]);
                float e1 = __expf(accl[g][half * 2 + 1]);
                accl[g][half * 2] = e0;
                accl[g][half * 2 + 1] = e1;
                srow += e0 + e1;
            }
            rs[half] += srow;
        }
        // P @ vT: Ph·vh + Ph·vl
#pragma unroll
        for (int kk = 0; kk < 2; kk++) {
            uint32_t aPh[4];
            aPh[0] = packh2(accl[2 * kk][0], accl[2 * kk][1]);
            aPh[1] = packh2(accl[2 * kk][2], accl[2 * kk][3]);
            aPh[2] = packh2(accl[2 * kk + 1][0], accl[2 * kk + 1][1]);
            aPh[3] = packh2(accl[2 * kk + 1][2], accl[2 * kk + 1][3]);
#pragma unroll
            for (int bj = 0; bj < 4; bj++) {
                uint32_t addr = s + OVT + (uint32_t)((bj * 16 + (lane & 15)) * VROW)
                              + (uint32_t)((wn + kk * 16) * 2 + (lane >> 4) * 16);
                uint32_t t[4], u[4];
                LDSM4(t, addr);
                LDSM4(u, addr + 64 * VROW);
                uint32_t bh0[2] = {t[0], t[2]}, bh1[2] = {t[1], t[3]};
                uint32_t bl0[2] = {u[0], u[2]}, bl1[2] = {u[1], u[3]};
                MMA16816(acc_o[2 * bj],     aPh, bh0);
                MMA16816(acc_o[2 * bj],     aPh, bl0);
                MMA16816(acc_o[2 * bj + 1], aPh, bh1);
                MMA16816(acc_o[2 * bj + 1], aPh, bl1);
            }
        }
    }

#pragma unroll
    for (int half = 0; half < 2; half++) {
        float v = rs[half];
        v += __shfl_xor_sync(0xffffffffu, v, 1);
        v += __shfl_xor_sync(0xffffffffu, v, 2);
        if ((lane & 3) == 0)
            atomicAdd(&rsm[wm + (lane >> 2) + half * 8], v);
    }
#pragma unroll
    for (int g = 0; g < 8; g++) {
        int r0 = wm + (lane >> 2);
        int c = g * 8 + (lane & 3) * 2;
        atomicAdd(&Os[r0 * 68 + c],           acc_o[g][0]);
        atomicAdd(&Os[r0 * 68 + c + 1],       acc_o[g][1]);
        atomicAdd(&Os[(r0 + 8) * 68 + c],     acc_o[g][2]);
        atomicAdd(&Os[(r0 + 8) * 68 + c + 1], acc_o[g][3]);
    }
    __syncthreads();
#pragma unroll
    for (int i = 0; i < 8; i++) {
        int idx = tid + i * 512;
        int r = idx >> 6, d = idx & 63;
        float val = Os[r * 68 + d] / rsm[r];
        bf16 hh, lo; split2(val, hh, lo);
        ll o = bz * sAVT + (ll)d * MLM + (m0 + r);
        AVTh[o] = hh; AVTl[o] = lo;
    }
}

// ---------------- fused attn1 + softmax + P@zav + conv -> y (512 thr) ----------------
#define ZROW 528
__global__ void __launch_bounds__(512, 1) attn1_outh(
    const bf16* __restrict__ Ah,
    const bf16* __restrict__ Bh, const bf16* __restrict__ Bl,
    const bf16* __restrict__ Zh, const bf16* __restrict__ Zl,
    const float* __restrict__ Vv, const float* __restrict__ kern,
    bf16* __restrict__ Yh, bf16* __restrict__ Yl,
    ll sA, ll sB, ll sZ, ll sV, int bzoff)
{
    extern __shared__ char smem[];
    __shared__ float redm[4][16][4];
    __shared__ float reds[4][16][4];
    __shared__ float khs[33];
    const int tid = threadIdx.x, wid = tid >> 5, lane = tid & 31;
    const int bz = blockIdx.y + bzoff;
    const int m0 = blockIdx.x * 64;
    const int wm = (wid & 3) * 16;
    const int wn = (wid >> 2) * 64;
    const int b_ = bz >> 3, h_ = bz & 7;
    uint32_t sb = smem_u32(smem);
    constexpr uint32_t OZH = 81920;
    constexpr uint32_t OZL = OZH + 64 * ZROW;
    constexpr uint32_t OO  = OZL + 64 * ZROW;
    constexpr uint32_t OV  = OO + 64 * 68 * 4;
    float* Os = (float*)(smem + OO);
    float* sv = (float*)(smem + OV);

    if (tid < 33) khs[tid] = kern[h_ * 33 + tid];

    const bf16* pAh = Ah + bz * sA + (ll)m0 * 64;
    const bf16* pBh = Bh + bz * sB;
    const bf16* pBl = Bl + bz * sB;
    const bf16* pZh = Zh + bz * sZ;
    const bf16* pZl = Zl + bz * sZ;
    const float* pV = Vv + bz * sV;

    {
        int r = tid >> 3, c = tid & 7;
        uint32_t so = SWZ128((uint32_t)(r * 128 + c * 16));
        cp16(sb + so, pAh + (ll)r * 64 + c * 8);
    }
#pragma unroll
    for (int i = 0; i < 4; i++) {
        int idx = tid + i * 512;
        int r = idx >> 3, c = idx & 7;
        uint32_t so = SWZ128((uint32_t)(r * 128 + c * 16));
        cp16(sb + 16384 + so, pBh + (ll)r * 64 + c * 8);
        cp16(sb + 49152 + so, pBl + (ll)r * 64 + c * 8);
    }
#pragma unroll
    for (int i = 0; i < 4; i++) {
        int idx = tid + i * 512;
        int r = idx >> 5, c = idx & 31;
        uint32_t so = (uint32_t)(r * ZROW + c * 16);
        cp16(sb + OZH + so, pZh + (ll)r * 256 + c * 8);
        cp16(sb + OZL + so, pZl + (ll)r * 256 + c * 8);
    }
#pragma unroll
    for (int i = 0; i < 3; i++) {
        int idx = tid + i * 512;
        int r = idx >> 4, c = idx & 15;
        int tt = m0 - 16 + r;
        if (tt >= 0 && tt < NTOK)
            cp16(sb + OV + (uint32_t)(r * 256 + c * 16), pV + (ll)tt * 64 + c * 4);
        else
            *(float4*)(smem + OV + r * 256 + c * 16) = make_float4(0.f, 0.f, 0.f, 0.f);
    }
    CP_COMMIT;
#pragma unroll
    for (int i = 0; i < 9; i++) {
        int idx = tid + i * 512;
        if (idx < 64 * 68) Os[idx] = 0.f;
    }

    float acc[8][4];
#pragma unroll
    for (int b = 0; b < 8; b++)
#pragma unroll
        for (int c = 0; c < 4; c++) acc[b][c] = 0.f;

    CP_WAIT0;
    __syncthreads();
#pragma unroll
    for (int ks = 0; ks < 4; ks++) {
        uint32_t aH[4];
        {
            int row = wm + (lane & 15);
            int c16 = ks * 2 + (lane >> 4);
            uint32_t off = SWZ128((uint32_t)(row * 128 + c16 * 16));
            LDSM4(aH, sb + off);
        }
        uint32_t bHf[8][2], bLf[8][2];
#pragma unroll
        for (int bj = 0; bj < 4; bj++) {
            int row = wn + bj * 16 + (lane & 15);
            int c16 = ks * 2 + (lane >> 4);
            uint32_t off = SWZ128((uint32_t)(row * 128 + c16 * 16));
            uint32_t t[4];
            LDSM4(t, sb + 16384 + off);
            bHf[bj * 2][0] = t[0]; bHf[bj * 2 + 1][0] = t[1];
            bHf[bj * 2][1] = t[2]; bHf[bj * 2 + 1][1] = t[3];
            LDSM4(t, sb + 49152 + off);
            bLf[bj * 2][0] = t[0]; bLf[bj * 2 + 1][0] = t[1];
            bLf[bj * 2][1] = t[2]; bLf[bj * 2 + 1][1] = t[3];
        }
#pragma unroll
        for (int g = 0; g < 8; g++) MMA16816(acc[g], aH, bHf[g]);
#pragma unroll
        for (int g = 0; g < 8; g++) MMA16816(acc[g], aH, bLf[g]);
    }

    float mx[2];
#pragma unroll
    for (int half = 0; half < 2; half++) {
        float m = -1e30f;
#pragma unroll
        for (int g = 0; g < 8; g++) {
            m = fmaxf(m, acc[g][half * 2]);
            m = fmaxf(m, acc[g][half * 2 + 1]);
        }
        m = fmaxf(m, __shfl_xor_sync(0xffffffffu, m, 1));
        m = fmaxf(m, __shfl_xor_sync(0xffffffffu, m, 2));
        mx[half] = m;
    }
    if ((lane & 3) == 0) {
#pragma unroll
        for (int half = 0; half < 2; half++)
            redm[wid & 3][(lane >> 2) + half * 8][wid >> 2] = mx[half];
    }
    __syncthreads();
    float sm[2];
#pragma unroll
    for (int half = 0; half < 2; half++) {
        int ri = (lane >> 2) + half * 8;
        float m = fmaxf(fmaxf(redm[wid & 3][ri][0], redm[wid & 3][ri][1]),
                        fmaxf(redm[wid & 3][ri][2], redm[wid & 3][ri][3]));
        float s = 0.f;
#pragma unroll
        for (int g = 0; g < 8; g++) {
            float e0 = __expf(acc[g][half * 2] - m);
            float e1 = __expf(acc[g][half * 2 + 1] - m);
            acc[g][half * 2] = e0; acc[g][half * 2 + 1] = e1;
            s += e0 + e1;
        }
        s += __shfl_xor_sync(0xffffffffu, s, 1);
        s += __shfl_xor_sync(0xffffffffu, s, 2);
        sm[half] = s;
    }
    if ((lane & 3) == 0) {
#pragma unroll
        for (int half = 0; half < 2; half++)
            reds[wid & 3][(lane >> 2) + half * 8][wid >> 2] = sm[half];
    }
    __syncthreads();
#pragma unroll
    for (int half = 0; half < 2; half++) {
        int ri = (lane >> 2) + half * 8;
        float tot = reds[wid & 3][ri][0] + reds[wid & 3][ri][1]
                  + reds[wid & 3][ri][2] + reds[wid & 3][ri][3];
        float inv = 1.f / tot;
#pragma unroll
        for (int g = 0; g < 8; g++) {
            acc[g][half * 2]     *= inv;
            acc[g][half * 2 + 1] *= inv;
        }
    }

    float acc_o[8][4];
#pragma unroll
    for (int b = 0; b < 8; b++)
#pragma unroll
        for (int c = 0; c < 4; c++) acc_o[b][c] = 0.f;

#pragma unroll
    for (int ks = 0; ks < 4; ks++) {
        uint32_t aPh[4];
        aPh[0] = packh2(acc[2 * ks][0], acc[2 * ks][1]);
        aPh[1] = packh2(acc[2 * ks][2], acc[2 * ks][3]);
        aPh[2] = packh2(acc[2 * ks + 1][0], acc[2 * ks + 1][1]);
        aPh[3] = packh2(acc[2 * ks + 1][2], acc[2 * ks + 1][3]);
#pragma unroll
        for (int bj = 0; bj < 4; bj++) {
            uint32_t addr = sb + OZH + (uint32_t)((bj * 16 + (lane & 15)) * ZROW)
                          + (uint32_t)((wn + ks * 16) * 2 + (lane >> 4) * 16);
            uint32_t t[4], u[4];
            LDSM4(t, addr);
            LDSM4(u, addr + (OZL - OZH));
            uint32_t bh0[2] = {t[0], t[2]}, bh1[2] = {t[1], t[3]};
            uint32_t bl0[2] = {u[0], u[2]}, bl1[2] = {u[1], u[3]};
            MMA16816(acc_o[2 * bj],     aPh, bh0);
            MMA16816(acc_o[2 * bj],     aPh, bl0);
            MMA16816(acc_o[2 * bj + 1], aPh, bh1);
            MMA16816(acc_o[2 * bj + 1], aPh, bl1);
        }
    }

#pragma unroll
    for (int g = 0; g < 8; g++) {
        int r0 = wm + (lane >> 2);
        int c = g * 8 + (lane & 3) * 2;
        atomicAdd(&Os[r0 * 68 + c],           acc_o[g][0]);
        atomicAdd(&Os[r0 * 68 + c + 1],       acc_o[g][1]);
        atomicAdd(&Os[(r0 + 8) * 68 + c],     acc_o[g][2]);
        atomicAdd(&Os[(r0 + 8) * 68 + c + 1], acc_o[g][3]);
    }
    __syncthreads();
#pragma unroll
    for (int i = 0; i < 8; i++) {
        int idx = tid + i * 512;
        int r = idx >> 6, d = idx & 63;
        float s = Os[r * 68 + d];
#pragma unroll
        for (int j = 0; j < 33; j++)
            s = fmaf(sv[(r + j) * 64 + d], khs[j], s);
        ll yo = ((ll)(b_ * NTOK + m0 + r)) * INNER + h_ * 64 + d;
        bf16 hh, lo; split2(s, hh, lo);
        Yh[yo] = hh; Yl[yo] = lo;
    }
}

// ---------------- elementwise kernels ----------------
__global__ void split_f32(const float* __restrict__ in, bf16* __restrict__ oh,
                          bf16* __restrict__ ol, ll n)
{
    ll i = (ll)blockIdx.x * 256 + threadIdx.x;
    if (i >= n) return;
    bf16 h, l; split2(in[i], h, l);
    oh[i] = h; ol[i] = l;
}

__global__ void transpose_split(const float* __restrict__ in, bf16* __restrict__ oh,
                                bf16* __restrict__ ol, int R, int C, ll sIn, ll sOut,
                                const float* __restrict__ nrmp, float dc, int usediag)
{
    __shared__ float t[32][33];
    ll b = blockIdx.z;
    const float* ip = in + b * sIn;
    int c0 = blockIdx.x * 32, r0 = blockIdx.y * 32;
    int tx = threadIdx.x, ty = threadIdx.y;
#pragma unroll
    for (int i = 0; i < 4; i++)
        t[ty + i * 8][tx] = ip[(ll)(r0 + ty + i * 8) * C + c0 + tx];
    __syncthreads();
    float alpha = nrmp ? 1.f / (nrmp[0] * nrmp[1]) : 1.f;
#pragma unroll
    for (int i = 0; i < 4; i++) {
        int cg = c0 + ty + i * 8, rg = r0 + tx;
        float v = t[tx][ty + i * 8];
        v = usediag ? ((rg == cg ? dc : 0.f) - v) : alpha * v;
        ll o = b * sOut + (ll)cg * R + rg;
        bf16 h, l; split2(v, h, l);
        oh[o] = h; ol[o] = l;
    }
}

__global__ void scale_split(const float* __restrict__ in, bf16* __restrict__ oh,
                            bf16* __restrict__ ol, ll n, const float* __restrict__ nrmp)
{
    ll i = (ll)blockIdx.x * 256 + threadIdx.x;
    if (i >= n) return;
    float inv = 1.f / (nrmp[0] * nrmp[1]);
    bf16 h, l; split2(in[i] * inv, h, l);
    oh[i] = h; ol[i] = l;
}

__global__ void landmark_split_bf(const bf16* __restrict__ xh, const bf16* __restrict__ xl,
                                  bf16* __restrict__ oh, bf16* __restrict__ ol)
{
    ll idx = (ll)blockIdx.x * 256 + threadIdx.x;
    if (idx >= SZ_LM) return;
    int d = (int)(idx & 63);
    int mi = (int)((idx >> 6) & 255);
    ll bh = idx >> 14;
    ll base = (bh * NTOK + (ll)mi * LGRP) * DH + d;
    float s = 0.f;
#pragma unroll
    for (int t = 0; t < LGRP; t++) {
        ll o = base + (ll)t * DH;
        s += __bfloat162float(xh[o]) + __bfloat162float(xl[o]);
    }
    bf16 h, l; split2(s * (1.f / LGRP), h, l);
    oh[idx] = h; ol[idx] = l;
}

__global__ void norm_init_kernel(float* nrm) { nrm[0] = 0.f; nrm[1] = 0.f; }

__global__ void pinv_norm_kernel(const float* __restrict__ x, float* __restrict__ nrm)
{
    int r = threadIdx.x;
    const float* xb = x + (ll)blockIdx.x * MLM * MLM;
    float rs = 0.f, cs = 0.f;
    for (int j = 0; j < MLM; j++) {
        rs += fabsf(xb[(ll)r * MLM + j]);
        cs += fabsf(xb[(ll)j * MLM + r]);
    }
    __shared__ float s1[256], s2[256];
    s1[r] = rs; s2[r] = cs; __syncthreads();
    for (int s = 128; s > 0; s >>= 1) {
        if (r < s) { s1[r] = fmaxf(s1[r], s1[r + s]); s2[r] = fmaxf(s2[r], s2[r + s]); }
        __syncthreads();
    }
    if (r == 0) {
        atomicMax((int*)&nrm[0], __float_as_int(s1[0]));
        atomicMax((int*)&nrm[1], __float_as_int(s2[0]));
    }
}

// ---------------- host ----------------
template<int TM, int TN, int SPLIT, int NT>
static inline void tcg(cudaStream_t st,
                       const bf16* Ah, const bf16* Al, const bf16* Bh, const bf16* Bl,
                       float* C, bf16* Ch, bf16* Cl, bf16* CTh, bf16* CTl,
                       const float* bias,
                       int M, int N, int K, int Kc, int ldc, int ldct,
                       ll sA, ll sB, ll sC, ll sCT, int batch, int kz,
                       float alpha, float diagc, int flags)
{
    dim3 grid(N / TN, M / TM, batch * kz);
    size_t sm = 2 * (size_t)stage_bytes<TM, TN, SPLIT>();
    gemm_mma<TM, TN, SPLIT, NT><<<grid, NT, sm, st>>>(Ah, Al, Bh, Bl, C, Ch, Cl, CTh, CTl, bias,
                                                      K, Kc, batch, ldc, ldct, sA, sB, sC, sCT,
                                                      alpha, diagc, flags);
}

extern "C" void kernel_launch(void* const* d_in, const int* in_sizes, int n_in,
                              void* d_out, int out_size)
{
    const float* x     = (const float*)d_in[0];
    const float* w_qkv = (const float*)d_in[1];
    const float* w_out = (const float*)d_in[2];
    const float* b_out = (const float*)d_in[3];
    const float* res_k = (const float*)d_in[4];
    float* out = (float*)d_out;

    const int A1O_SMEM = 81920 + 2 * 64 * ZROW + 64 * 68 * 4 + 96 * 64 * 4;
    const int FA3_SMEM = 8192 + 2 * (16384 + 2 * 64 * VROW);   // 8192 + 2*51200 = 110592

    cudaFuncSetAttribute(gemm_mma<128, 128, 1, 512>, cudaFuncAttributeMaxDynamicSharedMemorySize, 131072);
    cudaFuncSetAttribute(gemm_mma<128, 128, 2, 512>, cudaFuncAttributeMaxDynamicSharedMemorySize, 98304);
    cudaFuncSetAttribute(gemm_mma<64, 128, 1, 256>,  cudaFuncAttributeMaxDynamicSharedMemorySize, 98304);
    cudaFuncSetAttribute(gemm_mma<64, 128, 0, 256>,  cudaFuncAttributeMaxDynamicSharedMemorySize, 49152);
    cudaFuncSetAttribute(gemm_mma<64, 64, 1, 256>,   cudaFuncAttributeMaxDynamicSharedMemorySize, 65536);
    cudaFuncSetAttribute(attn_gemm_softmax, cudaFuncAttributeMaxDynamicSharedMemorySize, 81920);
    cudaFuncSetAttribute(attn1_outh, cudaFuncAttributeMaxDynamicSharedMemorySize, A1O_SMEM);
    cudaFuncSetAttribute(fa3_av, cudaFuncAttributeMaxDynamicSharedMemorySize, FA3_SMEM);

    float* F;  cudaGetSymbolAddress((void**)&F, g_f32);
    bf16*  Bp; cudaGetSymbolAddress((void**)&Bp, g_bf);
    float* nrm; cudaGetSymbolAddress((void**)&nrm, g_norm);

    const ll SH = (ll)NTOK * DH, SL = (ll)MLM * DH;
    const ll SA2 = (ll)MLM * MLM;

    cudaStream_t s0 = 0;
    cudaStream_t s2 = g_ctx.s2;

    // prep on s0
    {
        dim3 blk(32, 8);
        transpose_split<<<dim3(3 * INNER / 32, DIM / 32, 1), blk, 0, s0>>>(
            w_qkv, Bp + B_WQTH, Bp + B_WQTL, DIM, 3 * INNER, 0, 0, nullptr, 0.f, 0);
        split_f32<<<(int)((SZ_Y + 255) / 256), 256, 0, s0>>>(x, Bp + B_XH, Bp + B_XL, SZ_Y);
    }

    // fork s2: w_out transpose overlaps qkv
    cudaEventRecord(g_ctx.e0, s0);
    cudaStreamWaitEvent(s2, g_ctx.e0, 0);
    transpose_split<<<dim3(DIM / 32, INNER / 32, 1), dim3(32, 8), 0, s2>>>(
        w_out, Bp + B_WOTH, Bp + B_WOTL, INNER, DIM, 0, 0, nullptr, 0.f, 0);

    // 1a. qkv GEMM, q+k columns — 2-term
    tcg<128, 128, 2, 512>(s0, Bp + B_XH, Bp + B_XL, Bp + B_WQTH, Bp + B_WQTL,
                          nullptr, nullptr, nullptr, nullptr, nullptr, nullptr,
                          BB * NTOK, 2 * INNER, DIM, DIM, 0, 0,
                          0, 0, 0, 0, 1, 1, 1.f, 0.f, 64);

    landmark_split_bf<<<(int)((SZ_LM + 255) / 256), 256, 0, s0>>>(Bp + B_QH, Bp + B_QL, Bp + B_QLMH, Bp + B_QLML);
    landmark_split_bf<<<(int)((SZ_LM + 255) / 256), 256, 0, s0>>>(Bp + B_KH, Bp + B_KL, Bp + B_KLMH, Bp + B_KLML);

    // 2. attn2 fused (+fp32 for pinv init)
    attn_gemm_softmax<<<dim3(MLM / 64, BH), 256, 81920, s0>>>(
        Bp + B_QLMH, Bp + B_QLML, Bp + B_KLMH, Bp + B_KLML,
        F + F_A2, Bp + B_A2H, Bp + B_A2L, SL, SL, SA2);

    // fork s2: pinv
    cudaEventRecord(g_ctx.e1, s0);
    cudaStreamWaitEvent(s2, g_ctx.e1, 0);

    norm_init_kernel<<<1, 1, 0, s2>>>(nrm);
    pinv_norm_kernel<<<BH, 256, 0, s2>>>(F + F_A2, nrm);
    {
        int blocks = (int)((SZ_A2 + 255) / 256);
        scale_split<<<blocks, 256, 0, s2>>>(F + F_A2, Bp + B_Z0TH, Bp + B_Z0TL, SZ_A2, nrm);
        transpose_split<<<dim3(8, 8, BH), dim3(32, 8), 0, s2>>>(
            F + F_A2, Bp + B_Z0H, Bp + B_Z0L, MLM, MLM, SA2, SA2, nrm, 0.f, 0);
    }

    bf16 *zch = Bp + B_Z0H,  *zcl = Bp + B_Z0L,  *zcth = Bp + B_Z0TH, *zctl = Bp + B_Z0TL;
    bf16 *znh = Bp + B_Z1H,  *znl = Bp + B_Z1L,  *znth = Bp + B_Z1TH, *zntl = Bp + B_Z1TL;

    for (int it = 0; it < 6; it++) {
#define PINV_STEP(S) \
        tcg<64, 128, S, 256>(s2, Bp + B_A2H, Bp + B_A2L, zcth, zctl, \
                    nullptr, Bp + B_XZH, Bp + B_XZL, Bp + B_T1TH, Bp + B_T1TL, nullptr, \
                    MLM, MLM, MLM, MLM, MLM, MLM, SA2, SA2, SA2, SA2, BH, 1, 1.f, 7.f, 2|4|8|16); \
        tcg<64, 128, S, 256>(s2, Bp + B_XZH, Bp + B_XZL, Bp + B_T1TH, Bp + B_T1TL, \
                    nullptr, nullptr, nullptr, Bp + B_T2TH, Bp + B_T2TL, nullptr, \
                    MLM, MLM, MLM, MLM, MLM, MLM, SA2, SA2, 0, SA2, BH, 1, 1.f, 15.f, 4|8); \
        tcg<64, 128, S, 256>(s2, Bp + B_XZH, Bp + B_XZL, Bp + B_T2TH, Bp + B_T2TL, \
                    nullptr, nullptr, nullptr, Bp + B_T3TH, Bp + B_T3TL, nullptr, \
                    MLM, MLM, MLM, MLM, MLM, MLM, SA2, SA2, 0, SA2, BH, 1, 1.f, 13.f, 4|8); \
        tcg<64, 128, S, 256>(s2, zch, zcl, Bp + B_T3TH, Bp + B_T3TL, \
                    nullptr, znh, znl, znth, zntl, nullptr, \
                    MLM, MLM, MLM, MLM, MLM, MLM, SA2, SA2, SA2, SA2, BH, 1, 0.25f, 0.f, 2|4);
        if (it < 5) { PINV_STEP(0) } else { PINV_STEP(1) }
#undef PINV_STEP
        bf16* t;
        t = zch;  zch  = znh;  znh  = t;   t = zcl;  zcl  = znl;  znl  = t;
        t = zcth; zcth = znth; znth = t;   t = zctl; zctl = zntl; zntl = t;
    }
    cudaEventRecord(g_ctx.e2, s2);

    // 1b. qkv GEMM, v columns — 3-term, concurrent with pinv
    tcg<128, 128, 1, 512>(s0, Bp + B_XH, Bp + B_XL,
                          Bp + B_WQTH + (ll)2 * INNER * DIM, Bp + B_WQTL + (ll)2 * INNER * DIM,
                          nullptr, nullptr, nullptr, nullptr, nullptr, nullptr,
                          BB * NTOK, INNER, DIM, DIM, 0, 2 * INNER,
                          0, 0, 0, 0, 1, 1, 1.f, 0.f, 64);

    // 3. fa3 (s0), 1-term logits, concurrent with pinv (s2)
    fa3_av<<<dim3(MLM / 64, BH), 512, FA3_SMEM, s0>>>(
        Bp + B_QLMH, Bp + B_KH,
        Bp + B_VTH, Bp + B_VTL, Bp + B_AVTH, Bp + B_AVTL,
        SL, SH, SH, SL);

    // join pinv
    cudaStreamWaitEvent(s0, g_ctx.e2, 0);

    // 4. zav^T = (z @ av)^T
    tcg<64, 64, 1, 256>(s0, zch, zcl, Bp + B_AVTH, Bp + B_AVTL,
                        nullptr, nullptr, nullptr, Bp + B_ZVTH, Bp + B_ZVTL, nullptr,
                        MLM, DH, MLM, MLM, DH, MLM, SA2, SL, 0, SL, BH, 1, 1.f, 0.f, 4);

    // 5. a1o chunk0 then chunk1; out-proj chunk0 on s2 overlaps chunk1
    attn1_outh<<<dim3(NTOK / 64, 16), 512, A1O_SMEM, s0>>>(
        Bp + B_QH, Bp + B_KLMH, Bp + B_KLML,
        Bp + B_ZVTH, Bp + B_ZVTL, F + F_V, res_k,
        Bp + B_YH, Bp + B_YL, SH, SL, SL, SH, 0);
    cudaEventRecord(g_ctx.e3, s0);

    attn1_outh<<<dim3(NTOK / 64, 16), 512, A1O_SMEM, s0>>>(
        Bp + B_QH, Bp + B_KLMH, Bp + B_KLML,
        Bp + B_ZVTH, Bp + B_ZVTL, F + F_V, res_k,
        Bp + B_YH, Bp + B_YL, SH, SL, SL, SH, 16);

    cudaStreamWaitEvent(s2, g_ctx.e3, 0);
    // out-proj rows 0..8191 on s2 (3-term, precision-critical)
    tcg<128, 128, 1, 512>(s2, Bp + B_YH, Bp + B_YL, Bp + B_WOTH, Bp + B_WOTL,
                          out, nullptr, nullptr, nullptr, nullptr, b_out,
                          2 * NTOK, DIM, INNER, INNER, DIM, 0, 0, 0, 0, 0, 1, 1, 1.f, 0.f, 1);
    cudaEventRecord(g_ctx.e4, s2);

    // out-proj rows 8192..16383 on s0
    tcg<128, 128, 1, 512>(s0, Bp + B_YH + (ll)2 * NTOK * INNER, Bp + B_YL + (ll)2 * NTOK * INNER,
                          Bp + B_WOTH, Bp + B_WOTL,
                          out + (ll)2 * NTOK * DIM, nullptr, nullptr, nullptr, nullptr, b_out,
                          2 * NTOK, DIM, INNER, INNER, DIM, 0, 0, 0, 0, 0, 1, 1, 1.f, 0.f, 1);

    // final join
    cudaStreamWaitEvent(s0, g_ctx.e4, 0);
}

// round 16
// speedup vs baseline: 1.0979x; 1.0224x over previous
#include <cuda_runtime.h>
#include <cuda_bf16.h>
#include <cstdint>

typedef __nv_bfloat16 bf16;
typedef long long ll;

#define BB    4
#define NTOK  4096
#define DIM   512
#define H     8
#define DH    64
#define MLM   256
#define LGRP  16
#define BH    32
#define INNER 512

// ---------------- sizes ----------------
static const ll SZ_Y     = (ll)BB*NTOK*INNER;
static const ll SZ_HEADS = (ll)BH*NTOK*DH;
static const ll SZ_LM    = (ll)BH*MLM*DH;
static const ll SZ_A2    = (ll)BH*MLM*MLM;

// fp32 scratch
static const ll F_V    = 0;
static const ll F_A2   = F_V    + SZ_HEADS;
static const ll F_TOTAL= F_A2   + SZ_A2;

// bf16 scratch
static const ll B_XH   = 0;
static const ll B_XL   = B_XH   + SZ_Y;
static const ll B_WQTH = B_XL   + SZ_Y;
static const ll B_WQTL = B_WQTH + (ll)DIM*3*INNER;
static const ll B_WOTH = B_WQTL + (ll)DIM*3*INNER;
static const ll B_WOTL = B_WOTH + (ll)DIM*INNER;
static const ll B_QH   = B_WOTL + (ll)DIM*INNER;
static const ll B_QL   = B_QH   + SZ_HEADS;
static const ll B_KH   = B_QL   + SZ_HEADS;
static const ll B_KL   = B_KH   + SZ_HEADS;
static const ll B_VTH  = B_KL   + SZ_HEADS;
static const ll B_VTL  = B_VTH  + SZ_HEADS;
static const ll B_QLMH = B_VTL  + SZ_HEADS;
static const ll B_QLML = B_QLMH + SZ_LM;
static const ll B_KLMH = B_QLML + SZ_LM;
static const ll B_KLML = B_KLMH + SZ_LM;
static const ll B_A2H  = B_KLML + SZ_LM;
static const ll B_A2L  = B_A2H  + SZ_A2;
static const ll B_Z0H  = B_A2L  + SZ_A2;
static const ll B_Z0L  = B_Z0H  + SZ_A2;
static const ll B_Z0TH = B_Z0L  + SZ_A2;
static const ll B_Z0TL = B_Z0TH + SZ_A2;
static const ll B_Z1H  = B_Z0TL + SZ_A2;
static const ll B_Z1L  = B_Z1H  + SZ_A2;
static const ll B_Z1TH = B_Z1L  + SZ_A2;
static const ll B_Z1TL = B_Z1TH + SZ_A2;
static const ll B_XZH  = B_Z1TL + SZ_A2;
static const ll B_XZL  = B_XZH  + SZ_A2;
static const ll B_T1TH = B_XZL  + SZ_A2;
static const ll B_T1TL = B_T1TH + SZ_A2;
static const ll B_T2TH = B_T1TL + SZ_A2;
static const ll B_T2TL = B_T2TH + SZ_A2;
static const ll B_T3TH = B_T2TL + SZ_A2;
static const ll B_T3TL = B_T3TH + SZ_A2;
static const ll B_AVTH = B_T3TL + SZ_A2;
static const ll B_AVTL = B_AVTH + SZ_LM;
static const ll B_ZVTH = B_AVTL + SZ_LM;
static const ll B_ZVTL = B_ZVTH + SZ_LM;
static const ll B_YH   = B_ZVTL + SZ_LM;
static const ll B_YL   = B_YH   + SZ_Y;
static const ll B_TOTAL= B_YL   + SZ_Y;

__device__ __align__(16) float g_f32[F_TOTAL];
__device__ __align__(16) bf16  g_bf[B_TOTAL];
__device__ float g_norm[2];

// ---------------- stream/event context ----------------
struct StreamCtx {
    cudaStream_t s2;
    cudaEvent_t e0, e1, e2, e3, e4;
    StreamCtx() {
        cudaStreamCreateWithFlags(&s2, cudaStreamNonBlocking);
        cudaEventCreateWithFlags(&e0, cudaEventDisableTiming);
        cudaEventCreateWithFlags(&e1, cudaEventDisableTiming);
        cudaEventCreateWithFlags(&e2, cudaEventDisableTiming);
        cudaEventCreateWithFlags(&e3, cudaEventDisableTiming);
        cudaEventCreateWithFlags(&e4, cudaEventDisableTiming);
    }
};
static StreamCtx g_ctx;

// ---------------- helpers ----------------
__device__ __forceinline__ uint32_t smem_u32(const void* p) {
    uint32_t a;
    asm("{ .reg .u64 t; cvta.to.shared.u64 t, %1; cvt.u32.u64 %0, t; }" : "=r"(a) : "l"(p));
    return a;
}
__device__ __forceinline__ void cp16(uint32_t s, const void* g) {
    asm volatile("cp.async.cg.shared.global [%0], [%1], 16;" :: "r"(s), "l"(g));
}
#define CP_COMMIT asm volatile("cp.async.commit_group;" ::: "memory")
#define CP_WAIT0  asm volatile("cp.async.wait_group 0;" ::: "memory")

#define LDSM4(R, A) \
    asm volatile("ldmatrix.sync.aligned.m8n8.x4.shared.b16 {%0,%1,%2,%3}, [%4];" \
        : "=r"((R)[0]), "=r"((R)[1]), "=r"((R)[2]), "=r"((R)[3]) : "r"(A))

#define MMA16816(D, Aa, Bb) \
    asm volatile("mma.sync.aligned.m16n8k16.row.col.f32.bf16.bf16.f32 " \
        "{%0,%1,%2,%3}, {%4,%5,%6,%7}, {%8,%9}, {%0,%1,%2,%3};" \
        : "+f"((D)[0]), "+f"((D)[1]), "+f"((D)[2]), "+f"((D)[3]) \
        : "r"((Aa)[0]), "r"((Aa)[1]), "r"((Aa)[2]), "r"((Aa)[3]), \
          "r"((Bb)[0]), "r"((Bb)[1]))

#define SWZ128(o) ((o) ^ (((o) >> 3) & 0x70))

__device__ __forceinline__ void split2(float v, bf16& h, bf16& l) {
    h = __float2bfloat16(v);
    l = __float2bfloat16(v - __bfloat162float(h));
}
__device__ __forceinline__ uint32_t packh2(float a, float b) {
    __nv_bfloat162 p; p.x = __float2bfloat16(a); p.y = __float2bfloat16(b);
    return *(uint32_t*)&p;
}
__device__ __forceinline__ uint32_t packl2(float a, float b) {
    __nv_bfloat162 p;
    p.x = __float2bfloat16(a - __bfloat162float(__float2bfloat16(a)));
    p.y = __float2bfloat16(b - __bfloat162float(__float2bfloat16(b)));
    return *(uint32_t*)&p;
}

// ---------------- generic split-bf16 HMMA NT GEMM ----------------
// SPLIT modes: 0 = hi-only, 1 = full split (3 terms), 2 = A-hi/B-split (2 terms)
template<int TM, int TN, int SPLIT>
__host__ __device__ constexpr int stage_bytes() {
    return ((SPLIT == 1) ? 2 * (TM + TN) : (SPLIT == 2) ? (TM + 2 * TN) : (TM + TN)) * 128;
}

template<int TM, int TN, int SPLIT, int NT>
__device__ __forceinline__ void load_stage(uint32_t sbase,
    const bf16* pAh, const bf16* pAl, const bf16* pBh, const bf16* pBl,
    int K, int k0, int tid)
{
    constexpr uint32_t OAL = TM * 128;
    constexpr uint32_t OBH = ((SPLIT == 1) ? 2 : 1) * TM * 128;
    constexpr uint32_t OBL = OBH + TN * 128;
#pragma unroll
    for (int i = 0; i < TM * 8 / NT; i++) {
        int idx = tid + i * NT;
        int r = idx >> 3, c = idx & 7;
        uint32_t so = SWZ128((uint32_t)(r * 128 + c * 16));
        ll go = (ll)r * K + k0 + c * 8;
        cp16(sbase + so, pAh + go);
        if (SPLIT == 1) cp16(sbase + OAL + so, pAl + go);
    }
#pragma unroll
    for (int i = 0; i < TN * 8 / NT; i++) {
        int idx = tid + i * NT;
        int r = idx >> 3, c = idx & 7;
        uint32_t so = SWZ128((uint32_t)(r * 128 + c * 16));
        ll go = (ll)r * K + k0 + c * 8;
        cp16(sbase + OBH + so, pBh + go);
        if (SPLIT >= 1) cp16(sbase + OBL + so, pBl + go);
    }
}

template<int TM, int TN, int SPLIT, int NT>
__global__ void __launch_bounds__(NT, (NT == 256 && TM == 64) ? 2 : 1) gemm_mma(
    const bf16* __restrict__ Ah, const bf16* __restrict__ Al,
    const bf16* __restrict__ Bh, const bf16* __restrict__ Bl,
    float* __restrict__ C, bf16* __restrict__ Ch, bf16* __restrict__ Cl,
    bf16* __restrict__ CTh, bf16* __restrict__ CTl,
    const float* __restrict__ bias,
    int K, int Kc, int nbatch, int ldc, int ldct,
    ll sA, ll sB, ll sC, ll sCT,
    float alpha, float diagc, int flags)
{
    extern __shared__ char smem[];
    constexpr int WR = (NT == 512) ? 4 : 2;
    constexpr int MI = TM / WR / 16;
    constexpr int NG = TN / 4 / 8;
    constexpr uint32_t OBH = ((SPLIT == 1) ? 2 : 1) * TM * 128;
    constexpr uint32_t OBL = OBH + TN * 128;
    constexpr int STAGE = stage_bytes<TM, TN, SPLIT>();

    const int tid = threadIdx.x, wid = tid >> 5, lane = tid & 31;
    const int bz = blockIdx.z % nbatch;
    const int koff = (blockIdx.z / nbatch) * Kc;
    const int m0 = blockIdx.y * TM, n0 = blockIdx.x * TN;
    const int wm = (wid % WR) * (TM / WR);
    const int wn = (wid / WR) * (TN / 4);
    uint32_t sb = smem_u32(smem);

    const bf16* pAh = Ah + bz * sA + (ll)m0 * K + koff;
    const bf16* pAl = (SPLIT == 1) ? (Al + bz * sA + (ll)m0 * K + koff) : pAh;
    const bf16* pBh = Bh + bz * sB + (ll)n0 * K + koff;
    const bf16* pBl = (SPLIT >= 1) ? (Bl + bz * sB + (ll)n0 * K + koff) : pBh;

    float acc[MI][NG][4];
#pragma unroll
    for (int a = 0; a < MI; a++)
#pragma unroll
        for (int b = 0; b < NG; b++)
#pragma unroll
            for (int c = 0; c < 4; c++) acc[a][b][c] = 0.f;

    const int nch = Kc >> 6;
    load_stage<TM, TN, SPLIT, NT>(sb, pAh, pAl, pBh, pBl, K, 0, tid);
    CP_COMMIT;

    for (int ck = 0; ck < nch; ck++) {
        CP_WAIT0;
        __syncthreads();
        if (ck + 1 < nch) {
            load_stage<TM, TN, SPLIT, NT>(sb + ((ck + 1) & 1) * STAGE, pAh, pAl, pBh, pBl, K, (ck + 1) * 64, tid);
            CP_COMMIT;
        }
        uint32_t s = sb + (ck & 1) * STAGE;
#pragma unroll
        for (int ks = 0; ks < 4; ks++) {
            uint32_t aH[MI][4], aL[MI][4];
#pragma unroll
            for (int mi = 0; mi < MI; mi++) {
                int row = wm + mi * 16 + (lane & 15);
                int c16 = ks * 2 + (lane >> 4);
                uint32_t off = SWZ128((uint32_t)(row * 128 + c16 * 16));
                LDSM4(aH[mi], s + off);
                if (SPLIT == 1) LDSM4(aL[mi], s + TM * 128 + off);
            }
            uint32_t bH[NG][2], bL[NG][2];
#pragma unroll
            for (int bj = 0; bj < NG / 2; bj++) {
                int row = wn + bj * 16 + (lane & 15);
                int c16 = ks * 2 + (lane >> 4);
                uint32_t off = SWZ128((uint32_t)(row * 128 + c16 * 16));
                uint32_t t[4];
                LDSM4(t, s + OBH + off);
                bH[bj * 2][0] = t[0]; bH[bj * 2 + 1][0] = t[1];
                bH[bj * 2][1] = t[2]; bH[bj * 2 + 1][1] = t[3];
                if (SPLIT >= 1) {
                    LDSM4(t, s + OBL + off);
                    bL[bj * 2][0] = t[0]; bL[bj * 2 + 1][0] = t[1];
                    bL[bj * 2][1] = t[2]; bL[bj * 2 + 1][1] = t[3];
                }
            }
#pragma unroll
            for (int mi = 0; mi < MI; mi++)
#pragma unroll
                for (int g = 0; g < NG; g++) MMA16816(acc[mi][g], aH[mi], bH[g]);
            if (SPLIT >= 1) {
#pragma unroll
                for (int mi = 0; mi < MI; mi++)
#pragma unroll
                    for (int g = 0; g < NG; g++) MMA16816(acc[mi][g], aH[mi], bL[g]);
            }
            if (SPLIT == 1) {
#pragma unroll
                for (int mi = 0; mi < MI; mi++)
#pragma unroll
                    for (int g = 0; g < NG; g++) MMA16816(acc[mi][g], aL[mi], bH[g]);
            }
        }
    }

    const bool diagT = (flags & 8) != 0;
    const bool diagN = diagT && !(flags & 16);
#pragma unroll
    for (int mi = 0; mi < MI; mi++) {
#pragma unroll
        for (int g = 0; g < NG; g++) {
#pragma unroll
            for (int half = 0; half < 2; half++) {
                int r = m0 + wm + mi * 16 + (lane >> 2) + half * 8;
                int n = n0 + wn + g * 8 + (lane & 3) * 2;
                float a0 = acc[mi][g][half * 2 + 0];
                float a1v = acc[mi][g][half * 2 + 1];
                if (flags & 64) {
                    int nq = n + ldct;
                    int sel = nq >> 9;
                    int hh = (nq >> 6) & 7;
                    int d  = nq & 63;
                    int b  = r >> 12, t = r & 4095;
                    ll hidx = ((ll)((b << 3) + hh) * NTOK + t) * 64 + d;
                    if (sel == 0) {
                        *(uint32_t*)(g_bf + B_QH + hidx) = packh2(a0 * 0.125f, a1v * 0.125f);
                        *(uint32_t*)(g_bf + B_QL + hidx) = packl2(a0 * 0.125f, a1v * 0.125f);
                    } else if (sel == 1) {
                        *(uint32_t*)(g_bf + B_KH + hidx) = packh2(a0, a1v);
                        *(uint32_t*)(g_bf + B_KL + hidx) = packl2(a0, a1v);
                    } else {
                        *(float2*)(g_f32 + F_V + hidx) = make_float2(a0, a1v);
                        bf16 h0, l0, h1, l1;
                        split2(a0, h0, l0); split2(a1v, h1, l1);
                        ll vt = ((ll)((b << 3) + hh) * 64 + d) * NTOK + t;
                        g_bf[B_VTH + vt] = h0;
                        g_bf[B_VTH + vt + NTOK] = h1;
                    }
                    continue;
                }
                if (flags & 3) {
                    float n0v = diagN ? ((r == n)     ? diagc : 0.f) - a0  : alpha * a0;
                    float n1v = diagN ? ((r == n + 1) ? diagc : 0.f) - a1v : alpha * a1v;
                    if (bias) { n0v += bias[n]; n1v += bias[n + 1]; }
                    ll o = bz * sC + (ll)r * ldc + n;
                    if (flags & 1) {
                        if (flags & 32) { atomicAdd(C + o, n0v); atomicAdd(C + o + 1, n1v); }
                        else *(float2*)(C + o) = make_float2(n0v, n1v);
                    }
                    if (flags & 2) {
                        *(uint32_t*)(Ch + o) = packh2(n0v, n1v);
                        *(uint32_t*)(Cl + o) = packl2(n0v, n1v);
                    }
                }
                if (flags & 4) {
                    float t0v = diagT ? ((r == n)     ? diagc : 0.f) - a0  : alpha * a0;
                    float t1v = diagT ? ((r == n + 1) ? diagc : 0.f) - a1v : alpha * a1v;
                    bf16 h0, l0, h1, l1;
                    split2(t0v, h0, l0); split2(t1v, h1, l1);
                    ll ot0 = bz * sCT + (ll)n * ldct + r;
                    ll ot1 = bz * sCT + (ll)(n + 1) * ldct + r;
                    CTh[ot0] = h0; CTl[ot0] = l0;
                    CTh[ot1] = h1; CTl[ot1] = l1;
                }
            }
        }
    }
}

// ---------------- fused GEMM + row softmax (attn2) ----------------
__global__ void __launch_bounds__(256, 1) attn_gemm_softmax(
    const bf16* __restrict__ Ah, const bf16* __restrict__ Al,
    const bf16* __restrict__ Bh, const bf16* __restrict__ Bl,
    float* __restrict__ C32, bf16* __restrict__ Ch, bf16* __restrict__ Cl,
    ll sA, ll sB, ll sC)
{
    extern __shared__ char smem[];
    __shared__ float redm[2][32][4];
    __shared__ float reds[2][32][4];
    const int tid = threadIdx.x, wid = tid >> 5, lane = tid & 31;
    const int bz = blockIdx.y;
    const int m0 = blockIdx.x * 64;
    const int wm = (wid & 1) * 32;
    const int wn = (wid >> 1) * 64;
    uint32_t sb = smem_u32(smem);

    const bf16* pAh = Ah + bz * sA + (ll)m0 * 64;
    const bf16* pAl = Al + bz * sA + (ll)m0 * 64;
    const bf16* pBh = Bh + bz * sB;
    const bf16* pBl = Bl + bz * sB;

#pragma unroll
    for (int i = 0; i < 2; i++) {
        int idx = tid + i * 256;
        int r = idx >> 3, c = idx & 7;
        uint32_t so = SWZ128((uint32_t)(r * 128 + c * 16));
        cp16(sb + so, pAh + (ll)r * 64 + c * 8);
        cp16(sb + 8192 + so, pAl + (ll)r * 64 + c * 8);
    }
#pragma unroll
    for (int i = 0; i < 8; i++) {
        int idx = tid + i * 256;
        int r = idx >> 3, c = idx & 7;
        uint32_t so = SWZ128((uint32_t)(r * 128 + c * 16));
        cp16(sb + 16384 + so, pBh + (ll)r * 64 + c * 8);
        cp16(sb + 49152 + so, pBl + (ll)r * 64 + c * 8);
    }
    CP_COMMIT;

    float acc[2][8][4];
#pragma unroll
    for (int a = 0; a < 2; a++)
#pragma unroll
        for (int b = 0; b < 8; b++)
#pragma unroll
            for (int c = 0; c < 4; c++) acc[a][b][c] = 0.f;

    CP_WAIT0;
    __syncthreads();
#pragma unroll
    for (int ks = 0; ks < 4; ks++) {
        uint32_t aH[2][4], aL[2][4];
#pragma unroll
        for (int mi = 0; mi < 2; mi++) {
            int row = wm + mi * 16 + (lane & 15);
            int c16 = ks * 2 + (lane >> 4);
            uint32_t off = SWZ128((uint32_t)(row * 128 + c16 * 16));
            LDSM4(aH[mi], sb + off);
            LDSM4(aL[mi], sb + 8192 + off);
        }
        uint32_t bHf[8][2], bLf[8][2];
#pragma unroll
        for (int bj = 0; bj < 4; bj++) {
            int row = wn + bj * 16 + (lane & 15);
            int c16 = ks * 2 + (lane >> 4);
            uint32_t off = SWZ128((uint32_t)(row * 128 + c16 * 16));
            uint32_t t[4];
            LDSM4(t, sb + 16384 + off);
            bHf[bj * 2][0] = t[0]; bHf[bj * 2 + 1][0] = t[1];
            bHf[bj * 2][1] = t[2]; bHf[bj * 2 + 1][1] = t[3];
            LDSM4(t, sb + 49152 + off);
            bLf[bj * 2][0] = t[0]; bLf[bj * 2 + 1][0] = t[1];
            bLf[bj * 2][1] = t[2]; bLf[bj * 2 + 1][1] = t[3];
        }
#pragma unroll
        for (int mi = 0; mi < 2; mi++)
#pragma unroll
            for (int g = 0; g < 8; g++) MMA16816(acc[mi][g], aH[mi], bHf[g]);
#pragma unroll
        for (int mi = 0; mi < 2; mi++)
#pragma unroll
            for (int g = 0; g < 8; g++) MMA16816(acc[mi][g], aH[mi], bLf[g]);
#pragma unroll
        for (int mi = 0; mi < 2; mi++)
#pragma unroll
            for (int g = 0; g < 8; g++) MMA16816(acc[mi][g], aL[mi], bHf[g]);
    }

    float mx[2][2];
#pragma unroll
    for (int mi = 0; mi < 2; mi++)
#pragma unroll
        for (int half = 0; half < 2; half++) {
            float m = -1e30f;
#pragma unroll
            for (int g = 0; g < 8; g++) {
                m = fmaxf(m, acc[mi][g][half * 2]);
                m = fmaxf(m, acc[mi][g][half * 2 + 1]);
            }
            m = fmaxf(m, __shfl_xor_sync(0xffffffffu, m, 1));
            m = fmaxf(m, __shfl_xor_sync(0xffffffffu, m, 2));
            mx[mi][half] = m;
        }
    if ((lane & 3) == 0) {
#pragma unroll
        for (int mi = 0; mi < 2; mi++)
#pragma unroll
            for (int half = 0; half < 2; half++)
                redm[wid & 1][mi * 16 + (lane >> 2) + half * 8][wid >> 1] = mx[mi][half];
    }
    __syncthreads();
    float sm[2][2];
#pragma unroll
    for (int mi = 0; mi < 2; mi++)
#pragma unroll
        for (int half = 0; half < 2; half++) {
            int ri = mi * 16 + (lane >> 2) + half * 8;
            float m = fmaxf(fmaxf(redm[wid & 1][ri][0], redm[wid & 1][ri][1]),
                            fmaxf(redm[wid & 1][ri][2], redm[wid & 1][ri][3]));
            float s = 0.f;
#pragma unroll
            for (int g = 0; g < 8; g++) {
                float e0 = __expf(acc[mi][g][half * 2] - m);
                float e1 = __expf(acc[mi][g][half * 2 + 1] - m);
                acc[mi][g][half * 2] = e0; acc[mi][g][half * 2 + 1] = e1;
                s += e0 + e1;
            }
            s += __shfl_xor_sync(0xffffffffu, s, 1);
            s += __shfl_xor_sync(0xffffffffu, s, 2);
            sm[mi][half] = s;
        }
    if ((lane & 3) == 0) {
#pragma unroll
        for (int mi = 0; mi < 2; mi++)
#pragma unroll
            for (int half = 0; half < 2; half++)
                reds[wid & 1][mi * 16 + (lane >> 2) + half * 8][wid >> 1] = sm[mi][half];
    }
    __syncthreads();
#pragma unroll
    for (int mi = 0; mi < 2; mi++)
#pragma unroll
        for (int half = 0; half < 2; half++) {
            int ri = mi * 16 + (lane >> 2) + half * 8;
            float tot = reds[wid & 1][ri][0] + reds[wid & 1][ri][1]
                      + reds[wid & 1][ri][2] + reds[wid & 1][ri][3];
            float inv = 1.f / tot;
            int r = m0 + wm + ri;
#pragma unroll
            for (int g = 0; g < 8; g++) {
                int n = wn + g * 8 + (lane & 3) * 2;
                float v0 = acc[mi][g][half * 2] * inv;
                float v1 = acc[mi][g][half * 2 + 1] * inv;
                ll o = bz * sC + (ll)r * 256 + n;
                *(uint32_t*)(Ch + o) = packh2(v0, v1);
                *(uint32_t*)(Cl + o) = packl2(v0, v1);
                *(float2*)(C32 + o) = make_float2(v0, v1);
            }
        }
}

// ---------------- fused attn3 + softmax + @v -> avT (512 thr; 1-term logits & PV) ----------------
#define VROW 272
__global__ void __launch_bounds__(512, 1) fa3_av(
    const bf16* __restrict__ Qh,
    const bf16* __restrict__ Kh,
    const bf16* __restrict__ Vth,
    bf16* __restrict__ AVTh, bf16* __restrict__ AVTl,
    ll sQ, ll sK, ll sVT, ll sAVT)
{
    extern __shared__ char smem[];
    __shared__ float Os[64 * 68];
    __shared__ float rsm[64];
    const int tid = threadIdx.x, wid = tid >> 5, lane = tid & 31;
    const int bz = blockIdx.y;
    const int m0 = blockIdx.x * 64;
    const int wm = (wid & 3) * 16;
    const int wn = (wid >> 2) * 32;
    uint32_t sb = smem_u32(smem);
    constexpr uint32_t ST0 = 8192;                  // q hi only
    constexpr uint32_t OVT = 16384;                 // vt hi within stage (after 16KB k hi)
    constexpr uint32_t STG = OVT + 64 * VROW;       // 16384 + 17408 = 33792

    for (int i = tid; i < 64 * 68; i += 512) Os[i] = 0.f;
    if (tid < 64) rsm[tid] = 0.f;

    const bf16* pQh = Qh + bz * sQ + (ll)m0 * 64;
    const bf16* pKh = Kh + bz * sK;
    const bf16* pVh = Vth + bz * sVT;

    // resident q hi tile
    {
        int r = tid >> 3, c = tid & 7;
        uint32_t so = SWZ128((uint32_t)(r * 128 + c * 16));
        cp16(sb + so, pQh + (ll)r * 64 + c * 8);
    }
    // chunk 0: k hi + v hi
    {
        uint32_t s = sb + ST0;
#pragma unroll
        for (int i = 0; i < 2; i++) {
            int idx = tid + i * 512;
            int r = idx >> 3, c = idx & 7;
            uint32_t so = SWZ128((uint32_t)(r * 128 + c * 16));
            cp16(s + so, pKh + (ll)r * 64 + c * 8);
        }
#pragma unroll
        for (int i = 0; i < 2; i++) {
            int idx = tid + i * 512;
            int r = idx >> 4, c = idx & 15;
            uint32_t so = (uint32_t)(r * VROW + c * 16);
            cp16(s + OVT + so, pVh + (ll)r * NTOK + c * 8);
        }
    }
    CP_COMMIT;

    float acc_o[8][4];
#pragma unroll
    for (int b = 0; b < 8; b++)
#pragma unroll
        for (int c = 0; c < 4; c++) acc_o[b][c] = 0.f;
    float rs[2] = {0.f, 0.f};

    for (int ck = 0; ck < 32; ck++) {
        CP_WAIT0;
        __syncthreads();
        if (ck + 1 < 32) {
            uint32_t s = sb + ST0 + ((ck + 1) & 1) * STG;
            int tok = (ck + 1) * 128;
#pragma unroll
            for (int i = 0; i < 2; i++) {
                int idx = tid + i * 512;
                int r = idx >> 3, c = idx & 7;
                uint32_t so = SWZ128((uint32_t)(r * 128 + c * 16));
                cp16(s + so, pKh + (ll)(tok + r) * 64 + c * 8);
            }
#pragma unroll
            for (int i = 0; i < 2; i++) {
                int idx = tid + i * 512;
                int r = idx >> 4, c = idx & 15;
                uint32_t so = (uint32_t)(r * VROW + c * 16);
                cp16(s + OVT + so, pVh + (ll)r * NTOK + tok + c * 8);
            }
            CP_COMMIT;
        }
        uint32_t s = sb + ST0 + (ck & 1) * STG;

        // logits: qh·kh only
        float accl[4][4];
#pragma unroll
        for (int b = 0; b < 4; b++)
#pragma unroll
            for (int c = 0; c < 4; c++) accl[b][c] = 0.f;
#pragma unroll
        for (int ks = 0; ks < 4; ks++) {
            int c16 = ks * 2 + (lane >> 4);
            uint32_t aH[4];
            {
                int row = wm + (lane & 15);
                uint32_t off = SWZ128((uint32_t)(row * 128 + c16 * 16));
                LDSM4(aH, sb + off);
            }
            uint32_t bHf[4][2];
#pragma unroll
            for (int bj = 0; bj < 2; bj++) {
                int row = wn + bj * 16 + (lane & 15);
                uint32_t off = SWZ128((uint32_t)(row * 128 + c16 * 16));
                uint32_t t[4];
                LDSM4(t, s + off);
                bHf[bj * 2][0] = t[0]; bHf[bj * 2 + 1][0] = t[1];
                bHf[bj * 2][1] = t[2]; bHf[bj * 2 + 1][1] = t[3];
            }
#pragma unroll
            for (int g = 0; g < 4; g++) MMA16816(accl[g], aH, bHf[g]);
        }
        // exp (no max) + rowsum
#pragma unroll
        for (int half = 0; half < 2; half++) {
            float srow = 0.f;
#pragma unroll
            for (int g = 0; g < 4; g++) {
                float e0 = __expf(accl[g][half * 2]);
                float e1 = __expf(accl[g][half * 2 + 1]);
                accl[g][half * 2] = e0;
                accl[g][half * 2 + 1] = e1;
                srow += e0 + e1;
            }
            rs[half] += srow;
        }
        // P @ vT: Ph·vh only (1-term; v_lo washes per validated drop evidence)
#pragma unroll
        for (int kk = 0; kk < 2; kk++) {
            uint32_t aPh[4];
            aPh[0] = packh2(accl[2 * kk][0], accl[2 * kk][1]);
            aPh[1] = packh2(accl[2 * kk][2], accl[2 * kk][3]);
            aPh[2] = packh2(accl[2 * kk + 1][0], accl[2 * kk + 1][1]);
            aPh[3] = packh2(accl[2 * kk + 1][2], accl[2 * kk + 1][3]);
#pragma unroll
            for (int bj = 0; bj < 4; bj++) {
                uint32_t addr = s + OVT + (uint32_t)((bj * 16 + (lane & 15)) * VROW)
                              + (uint32_t)((wn + kk * 16) * 2 + (lane >> 4) * 16);
                uint32_t t[4];
                LDSM4(t, addr);
                uint32_t bh0[2] = {t[0], t[2]}, bh1[2] = {t[1], t[3]};
                MMA16816(acc_o[2 * bj],     aPh, bh0);
                MMA16816(acc_o[2 * bj + 1], aPh, bh1);
            }
        }
    }

#pragma unroll
    for (int half = 0; half < 2; half++) {
        float v = rs[half];
        v += __shfl_xor_sync(0xffffffffu, v, 1);
        v += __shfl_xor_sync(0xffffffffu, v, 2);
        if ((lane & 3) == 0)
            atomicAdd(&rsm[wm + (lane >> 2) + half * 8], v);
    }
#pragma unroll
    for (int g = 0; g < 8; g++) {
        int r0 = wm + (lane >> 2);
        int c = g * 8 + (lane & 3) * 2;
        atomicAdd(&Os[r0 * 68 + c],           acc_o[g][0]);
        atomicAdd(&Os[r0 * 68 + c + 1],       acc_o[g][1]);
        atomicAdd(&Os[(r0 + 8) * 68 + c],     acc_o[g][2]);
        atomicAdd(&Os[(r0 + 8) * 68 + c + 1], acc_o[g][3]);
    }
    __syncthreads();
#pragma unroll
    for (int i = 0; i < 8; i++) {
        int idx = tid + i * 512;
        int r = idx >> 6, d = idx & 63;
        float val = Os[r * 68 + d] / rsm[r];
        bf16 hh, lo; split2(val, hh, lo);
        ll o = bz * sAVT + (ll)d * MLM + (m0 + r);
        AVTh[o] = hh; AVTl[o] = lo;
    }
}

// ---------------- fused attn1 + softmax + P@zav + conv -> y (512 thr) ----------------
#define ZROW 528
__global__ void __launch_bounds__(512, 1) attn1_outh(
    const bf16* __restrict__ Ah,
    const bf16* __restrict__ Bh, const bf16* __restrict__ Bl,
    const bf16* __restrict__ Zh, const bf16* __restrict__ Zl,
    const float* __restrict__ Vv, const float* __restrict__ kern,
    bf16* __restrict__ Yh, bf16* __restrict__ Yl,
    ll sA, ll sB, ll sZ, ll sV, int bzoff)
{
    extern __shared__ char smem[];
    __shared__ float redm[4][16][4];
    __shared__ float reds[4][16][4];
    __shared__ float khs[33];
    const int tid = threadIdx.x, wid = tid >> 5, lane = tid & 31;
    const int bz = blockIdx.y + bzoff;
    const int m0 = blockIdx.x * 64;
    const int wm = (wid & 3) * 16;
    const int wn = (wid >> 2) * 64;
    const int b_ = bz >> 3, h_ = bz & 7;
    uint32_t sb = smem_u32(smem);
    constexpr uint32_t OZH = 81920;
    constexpr uint32_t OZL = OZH + 64 * ZROW;
    constexpr uint32_t OO  = OZL + 64 * ZROW;
    constexpr uint32_t OV  = OO + 64 * 68 * 4;
    float* Os = (float*)(smem + OO);
    float* sv = (float*)(smem + OV);

    if (tid < 33) khs[tid] = kern[h_ * 33 + tid];

    const bf16* pAh = Ah + bz * sA + (ll)m0 * 64;
    const bf16* pBh = Bh + bz * sB;
    const bf16* pBl = Bl + bz * sB;
    const bf16* pZh = Zh + bz * sZ;
    const bf16* pZl = Zl + bz * sZ;
    const float* pV = Vv + bz * sV;

    {
        int r = tid >> 3, c = tid & 7;
        uint32_t so = SWZ128((uint32_t)(r * 128 + c * 16));
        cp16(sb + so, pAh + (ll)r * 64 + c * 8);
    }
#pragma unroll
    for (int i = 0; i < 4; i++) {
        int idx = tid + i * 512;
        int r = idx >> 3, c = idx & 7;
        uint32_t so = SWZ128((uint32_t)(r * 128 + c * 16));
        cp16(sb + 16384 + so, pBh + (ll)r * 64 + c * 8);
        cp16(sb + 49152 + so, pBl + (ll)r * 64 + c * 8);
    }
#pragma unroll
    for (int i = 0; i < 4; i++) {
        int idx = tid + i * 512;
        int r = idx >> 5, c = idx & 31;
        uint32_t so = (uint32_t)(r * ZROW + c * 16);
        cp16(sb + OZH + so, pZh + (ll)r * 256 + c * 8);
        cp16(sb + OZL + so, pZl + (ll)r * 256 + c * 8);
    }
#pragma unroll
    for (int i = 0; i < 3; i++) {
        int idx = tid + i * 512;
        int r = idx >> 4, c = idx & 15;
        int tt = m0 - 16 + r;
        if (tt >= 0 && tt < NTOK)
            cp16(sb + OV + (uint32_t)(r * 256 + c * 16), pV + (ll)tt * 64 + c * 4);
        else
            *(float4*)(smem + OV + r * 256 + c * 16) = make_float4(0.f, 0.f, 0.f, 0.f);
    }
    CP_COMMIT;
#pragma unroll
    for (int i = 0; i < 9; i++) {
        int idx = tid + i * 512;
        if (idx < 64 * 68) Os[idx] = 0.f;
    }

    float acc[8][4];
#pragma unroll
    for (int b = 0; b < 8; b++)
#pragma unroll
        for (int c = 0; c < 4; c++) acc[b][c] = 0.f;

    CP_WAIT0;
    __syncthreads();
#pragma unroll
    for (int ks = 0; ks < 4; ks++) {
        uint32_t aH[4];
        {
            int row = wm + (lane & 15);
            int c16 = ks * 2 + (lane >> 4);
            uint32_t off = SWZ128((uint32_t)(row * 128 + c16 * 16));
            LDSM4(aH, sb + off);
        }
        uint32_t bHf[8][2], bLf[8][2];
#pragma unroll
        for (int bj = 0; bj < 4; bj++) {
            int row = wn + bj * 16 + (lane & 15);
            int c16 = ks * 2 + (lane >> 4);
            uint32_t off = SWZ128((uint32_t)(row * 128 + c16 * 16));
            uint32_t t[4];
            LDSM4(t, sb + 16384 + off);
            bHf[bj * 2][0] = t[0]; bHf[bj * 2 + 1][0] = t[1];
            bHf[bj * 2][1] = t[2]; bHf[bj * 2 + 1][1] = t[3];
            LDSM4(t, sb + 49152 + off);
            bLf[bj * 2][0] = t[0]; bLf[bj * 2 + 1][0] = t[1];
            bLf[bj * 2][1] = t[2]; bLf[bj * 2 + 1][1] = t[3];
        }
#pragma unroll
        for (int g = 0; g < 8; g++) MMA16816(acc[g], aH, bHf[g]);
#pragma unroll
        for (int g = 0; g < 8; g++) MMA16816(acc[g], aH, bLf[g]);
    }

    float mx[2];
#pragma unroll
    for (int half = 0; half < 2; half++) {
        float m = -1e30f;
#pragma unroll
        for (int g = 0; g < 8; g++) {
            m = fmaxf(m, acc[g][half * 2]);
            m = fmaxf(m, acc[g][half * 2 + 1]);
        }
        m = fmaxf(m, __shfl_xor_sync(0xffffffffu, m, 1));
        m = fmaxf(m, __shfl_xor_sync(0xffffffffu, m, 2));
        mx[half] = m;
    }
    if ((lane & 3) == 0) {
#pragma unroll
        for (int half = 0; half < 2; half++)
            redm[wid & 3][(lane >> 2) + half * 8][wid >> 2] = mx[half];
    }
    __syncthreads();
    float sm[2];
#pragma unroll
    for (int half = 0; half < 2; half++) {
        int ri = (lane >> 2) + half * 8;
        float m = fmaxf(fmaxf(redm[wid & 3][ri][0], redm[wid & 3][ri][1]),
                        fmaxf(redm[wid & 3][ri][2], redm[wid & 3][ri][3]));
        float s = 0.f;
#pragma unroll
        for (int g = 0; g < 8; g++) {
            float e0 = __expf(acc[g][half * 2] - m);
            float e1 = __expf(acc[g][half * 2 + 1] - m);
            acc[g][half * 2] = e0; acc[g][half * 2 + 1] = e1;
            s += e0 + e1;
        }
        s += __shfl_xor_sync(0xffffffffu, s, 1);
        s += __shfl_xor_sync(0xffffffffu, s, 2);
        sm[half] = s;
    }
    if ((lane & 3) == 0) {
#pragma unroll
        for (int half = 0; half < 2; half++)
            reds[wid & 3][(lane >> 2) + half * 8][wid >> 2] = sm[half];
    }
    __syncthreads();
#pragma unroll
    for (int half = 0; half < 2; half++) {
        int ri = (lane >> 2) + half * 8;
        float tot = reds[wid & 3][ri][0] + reds[wid & 3][ri][1]
                  + reds[wid & 3][ri][2] + reds[wid & 3][ri][3];
        float inv = 1.f / tot;
#pragma unroll
        for (int g = 0; g < 8; g++) {
            acc[g][half * 2]     *= inv;
            acc[g][half * 2 + 1] *= inv;
        }
    }

    float acc_o[8][4];
#pragma unroll
    for (int b = 0; b < 8; b++)
#pragma unroll
        for (int c = 0; c < 4; c++) acc_o[b][c] = 0.f;

#pragma unroll
    for (int ks = 0; ks < 4; ks++) {
        uint32_t aPh[4];
        aPh[0] = packh2(acc[2 * ks][0], acc[2 * ks][1]);
        aPh[1] = packh2(acc[2 * ks][2], acc[2 * ks][3]);
        aPh[2] = packh2(acc[2 * ks + 1][0], acc[2 * ks + 1][1]);
        aPh[3] = packh2(acc[2 * ks + 1][2], acc[2 * ks + 1][3]);
#pragma unroll
        for (int bj = 0; bj < 4; bj++) {
            uint32_t addr = sb + OZH + (uint32_t)((bj * 16 + (lane & 15)) * ZROW)
                          + (uint32_t)((wn + ks * 16) * 2 + (lane >> 4) * 16);
            uint32_t t[4], u[4];
            LDSM4(t, addr);
            LDSM4(u, addr + (OZL - OZH));
            uint32_t bh0[2] = {t[0], t[2]}, bh1[2] = {t[1], t[3]};
            uint32_t bl0[2] = {u[0], u[2]}, bl1[2] = {u[1], u[3]};
            MMA16816(acc_o[2 * bj],     aPh, bh0);
            MMA16816(acc_o[2 * bj],     aPh, bl0);
            MMA16816(acc_o[2 * bj + 1], aPh, bh1);
            MMA16816(acc_o[2 * bj + 1], aPh, bl1);
        }
    }

#pragma unroll
    for (int g = 0; g < 8; g++) {
        int r0 = wm + (lane >> 2);
        int c = g * 8 + (lane & 3) * 2;
        atomicAdd(&Os[r0 * 68 + c],           acc_o[g][0]);
        atomicAdd(&Os[r0 * 68 + c + 1],       acc_o[g][1]);
        atomicAdd(&Os[(r0 + 8) * 68 + c],     acc_o[g][2]);
        atomicAdd(&Os[(r0 + 8) * 68 + c + 1], acc_o[g][3]);
    }
    __syncthreads();
#pragma unroll
    for (int i = 0; i < 8; i++) {
        int idx = tid + i * 512;
        int r = idx >> 6, d = idx & 63;
        float s = Os[r * 68 + d];
#pragma unroll
        for (int j = 0; j < 33; j++)
            s = fmaf(sv[(r + j) * 64 + d], khs[j], s);
        ll yo = ((ll)(b_ * NTOK + m0 + r)) * INNER + h_ * 64 + d;
        bf16 hh, lo; split2(s, hh, lo);
        Yh[yo] = hh; Yl[yo] = lo;
    }
}

// ---------------- elementwise kernels ----------------
__global__ void split_f32(const float* __restrict__ in, bf16* __restrict__ oh,
                          bf16* __restrict__ ol, ll n)
{
    ll i = (ll)blockIdx.x * 256 + threadIdx.x;
    if (i >= n) return;
    bf16 h, l; split2(in[i], h, l);
    oh[i] = h; ol[i] = l;
}

__global__ void transpose_split(const float* __restrict__ in, bf16* __restrict__ oh,
                                bf16* __restrict__ ol, int R, int C, ll sIn, ll sOut,
                                const float* __restrict__ nrmp, float dc, int usediag)
{
    __shared__ float t[32][33];
    ll b = blockIdx.z;
    const float* ip = in + b * sIn;
    int c0 = blockIdx.x * 32, r0 = blockIdx.y * 32;
    int tx = threadIdx.x, ty = threadIdx.y;
#pragma unroll
    for (int i = 0; i < 4; i++)
        t[ty + i * 8][tx] = ip[(ll)(r0 + ty + i * 8) * C + c0 + tx];
    __syncthreads();
    float alpha = nrmp ? 1.f / (nrmp[0] * nrmp[1]) : 1.f;
#pragma unroll
    for (int i = 0; i < 4; i++) {
        int cg = c0 + ty + i * 8, rg = r0 + tx;
        float v = t[tx][ty + i * 8];
        v = usediag ? ((rg == cg ? dc : 0.f) - v) : alpha * v;
        ll o = b * sOut + (ll)cg * R + rg;
        bf16 h, l; split2(v, h, l);
        oh[o] = h; ol[o] = l;
    }
}

__global__ void scale_split(const float* __restrict__ in, bf16* __restrict__ oh,
                            bf16* __restrict__ ol, ll n, const float* __restrict__ nrmp)
{
    ll i = (ll)blockIdx.x * 256 + threadIdx.x;
    if (i >= n) return;
    float inv = 1.f / (nrmp[0] * nrmp[1]);
    bf16 h, l; split2(in[i] * inv, h, l);
    oh[i] = h; ol[i] = l;
}

__global__ void landmark_split_bf(const bf16* __restrict__ xh, const bf16* __restrict__ xl,
                                  bf16* __restrict__ oh, bf16* __restrict__ ol)
{
    ll idx = (ll)blockIdx.x * 256 + threadIdx.x;
    if (idx >= SZ_LM) return;
    int d = (int)(idx & 63);
    int mi = (int)((idx >> 6) & 255);
    ll bh = idx >> 14;
    ll base = (bh * NTOK + (ll)mi * LGRP) * DH + d;
    float s = 0.f;
#pragma unroll
    for (int t = 0; t < LGRP; t++) {
        ll o = base + (ll)t * DH;
        s += __bfloat162float(xh[o]) + __bfloat162float(xl[o]);
    }
    bf16 h, l; split2(s * (1.f / LGRP), h, l);
    oh[idx] = h; ol[idx] = l;
}

__global__ void norm_init_kernel(float* nrm) { nrm[0] = 0.f; nrm[1] = 0.f; }

__global__ void pinv_norm_kernel(const float* __restrict__ x, float* __restrict__ nrm)
{
    int r = threadIdx.x;
    const float* xb = x + (ll)blockIdx.x * MLM * MLM;
    float rs = 0.f, cs = 0.f;
    for (int j = 0; j < MLM; j++) {
        rs += fabsf(xb[(ll)r * MLM + j]);
        cs += fabsf(xb[(ll)j * MLM + r]);
    }
    __shared__ float s1[256], s2[256];
    s1[r] = rs; s2[r] = cs; __syncthreads();
    for (int s = 128; s > 0; s >>= 1) {
        if (r < s) { s1[r] = fmaxf(s1[r], s1[r + s]); s2[r] = fmaxf(s2[r], s2[r + s]); }
        __syncthreads();
    }
    if (r == 0) {
        atomicMax((int*)&nrm[0], __float_as_int(s1[0]));
        atomicMax((int*)&nrm[1], __float_as_int(s2[0]));
    }
}

// ---------------- host ----------------
template<int TM, int TN, int SPLIT, int NT>
static inline void tcg(cudaStream_t st,
                       const bf16* Ah, const bf16* Al, const bf16* Bh, const bf16* Bl,
                       float* C, bf16* Ch, bf16* Cl, bf16* CTh, bf16* CTl,
                       const float* bias,
                       int M, int N, int K, int Kc, int ldc, int ldct,
                       ll sA, ll sB, ll sC, ll sCT, int batch, int kz,
                       float alpha, float diagc, int flags)
{
    dim3 grid(N / TN, M / TM, batch * kz);
    size_t sm = 2 * (size_t)stage_bytes<TM, TN, SPLIT>();
    gemm_mma<TM, TN, SPLIT, NT><<<grid, NT, sm, st>>>(Ah, Al, Bh, Bl, C, Ch, Cl, CTh, CTl, bias,
                                                      K, Kc, batch, ldc, ldct, sA, sB, sC, sCT,
                                                      alpha, diagc, flags);
}

extern "C" void kernel_launch(void* const* d_in, const int* in_sizes, int n_in,
                              void* d_out, int out_size)
{
    const float* x     = (const float*)d_in[0];
    const float* w_qkv = (const float*)d_in[1];
    const float* w_out = (const float*)d_in[2];
    const float* b_out = (const float*)d_in[3];
    const float* res_k = (const float*)d_in[4];
    float* out = (float*)d_out;

    const int A1O_SMEM = 81920 + 2 * 64 * ZROW + 64 * 68 * 4 + 96 * 64 * 4;
    const int FA3_SMEM = 8192 + 2 * (16384 + 64 * VROW);   // 8192 + 2*33792 = 75776

    cudaFuncSetAttribute(gemm_mma<128, 128, 1, 512>, cudaFuncAttributeMaxDynamicSharedMemorySize, 131072);
    cudaFuncSetAttribute(gemm_mma<128, 128, 2, 512>, cudaFuncAttributeMaxDynamicSharedMemorySize, 98304);
    cudaFuncSetAttribute(gemm_mma<64, 128, 1, 256>,  cudaFuncAttributeMaxDynamicSharedMemorySize, 98304);
    cudaFuncSetAttribute(gemm_mma<64, 128, 0, 256>,  cudaFuncAttributeMaxDynamicSharedMemorySize, 49152);
    cudaFuncSetAttribute(gemm_mma<64, 64, 1, 256>,   cudaFuncAttributeMaxDynamicSharedMemorySize, 65536);
    cudaFuncSetAttribute(attn_gemm_softmax, cudaFuncAttributeMaxDynamicSharedMemorySize, 81920);
    cudaFuncSetAttribute(attn1_outh, cudaFuncAttributeMaxDynamicSharedMemorySize, A1O_SMEM);
    cudaFuncSetAttribute(fa3_av, cudaFuncAttributeMaxDynamicSharedMemorySize, FA3_SMEM);

    float* F;  cudaGetSymbolAddress((void**)&F, g_f32);
    bf16*  Bp; cudaGetSymbolAddress((void**)&Bp, g_bf);
    float* nrm; cudaGetSymbolAddress((void**)&nrm, g_norm);

    const ll SH = (ll)NTOK * DH, SL = (ll)MLM * DH;
    const ll SA2 = (ll)MLM * MLM;

    cudaStream_t s0 = 0;
    cudaStream_t s2 = g_ctx.s2;

    // prep on s0
    {
        dim3 blk(32, 8);
        transpose_split<<<dim3(3 * INNER / 32, DIM / 32, 1), blk, 0, s0>>>(
            w_qkv, Bp + B_WQTH, Bp + B_WQTL, DIM, 3 * INNER, 0, 0, nullptr, 0.f, 0);
        split_f32<<<(int)((SZ_Y + 255) / 256), 256, 0, s0>>>(x, Bp + B_XH, Bp + B_XL, SZ_Y);
    }

    // fork s2: w_out transpose overlaps qkv
    cudaEventRecord(g_ctx.e0, s0);
    cudaStreamWaitEvent(s2, g_ctx.e0, 0);
    transpose_split<<<dim3(DIM / 32, INNER / 32, 1), dim3(32, 8), 0, s2>>>(
        w_out, Bp + B_WOTH, Bp + B_WOTL, INNER, DIM, 0, 0, nullptr, 0.f, 0);

    // 1a. qkv GEMM, q+k columns — 2-term
    tcg<128, 128, 2, 512>(s0, Bp + B_XH, Bp + B_XL, Bp + B_WQTH, Bp + B_WQTL,
                          nullptr, nullptr, nullptr, nullptr, nullptr, nullptr,
                          BB * NTOK, 2 * INNER, DIM, DIM, 0, 0,
                          0, 0, 0, 0, 1, 1, 1.f, 0.f, 64);

    landmark_split_bf<<<(int)((SZ_LM + 255) / 256), 256, 0, s0>>>(Bp + B_QH, Bp + B_QL, Bp + B_QLMH, Bp + B_QLML);
    landmark_split_bf<<<(int)((SZ_LM + 255) / 256), 256, 0, s0>>>(Bp + B_KH, Bp + B_KL, Bp + B_KLMH, Bp + B_KLML);

    // 2. attn2 fused (+fp32 for pinv init)
    attn_gemm_softmax<<<dim3(MLM / 64, BH), 256, 81920, s0>>>(
        Bp + B_QLMH, Bp + B_QLML, Bp + B_KLMH, Bp + B_KLML,
        F + F_A2, Bp + B_A2H, Bp + B_A2L, SL, SL, SA2);

    // fork s2: pinv
    cudaEventRecord(g_ctx.e1, s0);
    cudaStreamWaitEvent(s2, g_ctx.e1, 0);

    norm_init_kernel<<<1, 1, 0, s2>>>(nrm);
    pinv_norm_kernel<<<BH, 256, 0, s2>>>(F + F_A2, nrm);
    {
        int blocks = (int)((SZ_A2 + 255) / 256);
        scale_split<<<blocks, 256, 0, s2>>>(F + F_A2, Bp + B_Z0TH, Bp + B_Z0TL, SZ_A2, nrm);
        transpose_split<<<dim3(8, 8, BH), dim3(32, 8), 0, s2>>>(
            F + F_A2, Bp + B_Z0H, Bp + B_Z0L, MLM, MLM, SA2, SA2, nrm, 0.f, 0);
    }

    bf16 *zch = Bp + B_Z0H,  *zcl = Bp + B_Z0L,  *zcth = Bp + B_Z0TH, *zctl = Bp + B_Z0TL;
    bf16 *znh = Bp + B_Z1H,  *znl = Bp + B_Z1L,  *znth = Bp + B_Z1TH, *zntl = Bp + B_Z1TL;

    for (int it = 0; it < 6; it++) {
#define PINV_STEP(S) \
        tcg<64, 128, S, 256>(s2, Bp + B_A2H, Bp + B_A2L, zcth, zctl, \
                    nullptr, Bp + B_XZH, Bp + B_XZL, Bp + B_T1TH, Bp + B_T1TL, nullptr, \
                    MLM, MLM, MLM, MLM, MLM, MLM, SA2, SA2, SA2, SA2, BH, 1, 1.f, 7.f, 2|4|8|16); \
        tcg<64, 128, S, 256>(s2, Bp + B_XZH, Bp + B_XZL, Bp + B_T1TH, Bp + B_T1TL, \
                    nullptr, nullptr, nullptr, Bp + B_T2TH, Bp + B_T2TL, nullptr, \
                    MLM, MLM, MLM, MLM, MLM, MLM, SA2, SA2, 0, SA2, BH, 1, 1.f, 15.f, 4|8); \
        tcg<64, 128, S, 256>(s2, Bp + B_XZH, Bp + B_XZL, Bp + B_T2TH, Bp + B_T2TL, \
                    nullptr, nullptr, nullptr, Bp + B_T3TH, Bp + B_T3TL, nullptr, \
                    MLM, MLM, MLM, MLM, MLM, MLM, SA2, SA2, 0, SA2, BH, 1, 1.f, 13.f, 4|8); \
        tcg<64, 128, S, 256>(s2, zch, zcl, Bp + B_T3TH, Bp + B_T3TL, \
                    nullptr, znh, znl, znth, zntl, nullptr, \
                    MLM, MLM, MLM, MLM, MLM, MLM, SA2, SA2, SA2, SA2, BH, 1, 0.25f, 0.f, 2|4);
        if (it < 5) { PINV_STEP(0) } else { PINV_STEP(1) }
#undef PINV_STEP
        bf16* t;
        t = zch;  zch  = znh;  znh  = t;   t = zcl;  zcl  = znl;  znl  = t;
        t = zcth; zcth = znth; znth = t;   t = zctl; zctl = zntl; zntl = t;
    }
    cudaEventRecord(g_ctx.e2, s2);

    // 1b. qkv GEMM, v columns — 3-term, concurrent with pinv
    tcg<128, 128, 1, 512>(s0, Bp + B_XH, Bp + B_XL,
                          Bp + B_WQTH + (ll)2 * INNER * DIM, Bp + B_WQTL + (ll)2 * INNER * DIM,
                          nullptr, nullptr, nullptr, nullptr, nullptr, nullptr,
                          BB * NTOK, INNER, DIM, DIM, 0, 2 * INNER,
                          0, 0, 0, 0, 1, 1, 1.f, 0.f, 64);

    // 3. fa3 (s0), 1-term logits + 1-term PV, concurrent with pinv (s2)
    fa3_av<<<dim3(MLM / 64, BH), 512, FA3_SMEM, s0>>>(
        Bp + B_QLMH, Bp + B_KH,
        Bp + B_VTH, Bp + B_AVTH, Bp + B_AVTL,
        SL, SH, SH, SL);

    // join pinv
    cudaStreamWaitEvent(s0, g_ctx.e2, 0);

    // 4. zav^T = (z @ av)^T
    tcg<64, 64, 1, 256>(s0, zch, zcl, Bp + B_AVTH, Bp + B_AVTL,
                        nullptr, nullptr, nullptr, Bp + B_ZVTH, Bp + B_ZVTL, nullptr,
                        MLM, DH, MLM, MLM, DH, MLM, SA2, SL, 0, SL, BH, 1, 1.f, 0.f, 4);

    // 5. a1o chunk0 then chunk1; out-proj chunk0 on s2 overlaps chunk1
    attn1_outh<<<dim3(NTOK / 64, 16), 512, A1O_SMEM, s0>>>(
        Bp + B_QH, Bp + B_KLMH, Bp + B_KLML,
        Bp + B_ZVTH, Bp + B_ZVTL, F + F_V, res_k,
        Bp + B_YH, Bp + B_YL, SH, SL, SL, SH, 0);
    cudaEventRecord(g_ctx.e3, s0);

    attn1_outh<<<dim3(NTOK / 64, 16), 512, A1O_SMEM, s0>>>(
        Bp + B_QH, Bp + B_KLMH, Bp + B_KLML,
        Bp + B_ZVTH, Bp + B_ZVTL, F + F_V, res_k,
        Bp + B_YH, Bp + B_YL, SH, SL, SL, SH, 16);

    cudaStreamWaitEvent(s2, g_ctx.e3, 0);
    // out-proj rows 0..8191 on s2 (3-term, precision-critical)
    tcg<128, 128, 1, 512>(s2, Bp + B_YH, Bp + B_YL, Bp + B_WOTH, Bp + B_WOTL,
                          out, nullptr, nullptr, nullptr, nullptr, b_out,
                          2 * NTOK, DIM, INNER, INNER, DIM, 0, 0, 0, 0, 0, 1, 1, 1.f, 0.f, 1);
    cudaEventRecord(g_ctx.e4, s2);

    // out-proj rows 8192..16383 on s0
    tcg<128, 128, 1, 512>(s0, Bp + B_YH + (ll)2 * NTOK * INNER, Bp + B_YL + (ll)2 * NTOK * INNER,
                          Bp + B_WOTH, Bp + B_WOTL,
                          out + (ll)2 * NTOK * DIM, nullptr, nullptr, nullptr, nullptr, b_out,
                          2 * NTOK, DIM, INNER, INNER, DIM, 0, 0, 0, 0, 0, 1, 1, 1.f, 0.f, 1);

    // final join
    cudaStreamWaitEvent(s0, g_ctx.e4, 0);
}

// round 17
// speedup vs baseline: 1.1094x; 1.0105x over previous
#include <cuda_runtime.h>
#include <cuda_bf16.h>
#include <cstdint>

typedef __nv_bfloat16 bf16;
typedef long long ll;

#define BB    4
#define NTOK  4096
#define DIM   512
#define H     8
#define DH    64
#define MLM   256
#define LGRP  16
#define BH    32
#define INNER 512

// ---------------- sizes ----------------
static const ll SZ_Y     = (ll)BB*NTOK*INNER;
static const ll SZ_HEADS = (ll)BH*NTOK*DH;
static const ll SZ_LM    = (ll)BH*MLM*DH;
static const ll SZ_A2    = (ll)BH*MLM*MLM;

// fp32 scratch
static const ll F_V    = 0;
static const ll F_A2   = F_V    + SZ_HEADS;
static const ll F_TOTAL= F_A2   + SZ_A2;

// bf16 scratch
static const ll B_XH   = 0;
static const ll B_XL   = B_XH   + SZ_Y;
static const ll B_WQTH = B_XL   + SZ_Y;
static const ll B_WQTL = B_WQTH + (ll)DIM*3*INNER;
static const ll B_WOTH = B_WQTL + (ll)DIM*3*INNER;
static const ll B_WOTL = B_WOTH + (ll)DIM*INNER;
static const ll B_QH   = B_WOTL + (ll)DIM*INNER;
static const ll B_QL   = B_QH   + SZ_HEADS;
static const ll B_KH   = B_QL   + SZ_HEADS;
static const ll B_KL   = B_KH   + SZ_HEADS;
static const ll B_VTH  = B_KL   + SZ_HEADS;
static const ll B_VTL  = B_VTH  + SZ_HEADS;
static const ll B_QLMH = B_VTL  + SZ_HEADS;
static const ll B_QLML = B_QLMH + SZ_LM;
static const ll B_KLMH = B_QLML + SZ_LM;
static const ll B_KLML = B_KLMH + SZ_LM;
static const ll B_A2H  = B_KLML + SZ_LM;
static const ll B_A2L  = B_A2H  + SZ_A2;
static const ll B_Z0H  = B_A2L  + SZ_A2;
static const ll B_Z0L  = B_Z0H  + SZ_A2;
static const ll B_Z0TH = B_Z0L  + SZ_A2;
static const ll B_Z0TL = B_Z0TH + SZ_A2;
static const ll B_Z1H  = B_Z0TL + SZ_A2;
static const ll B_Z1L  = B_Z1H  + SZ_A2;
static const ll B_Z1TH = B_Z1L  + SZ_A2;
static const ll B_Z1TL = B_Z1TH + SZ_A2;
static const ll B_XZH  = B_Z1TL + SZ_A2;
static const ll B_XZL  = B_XZH  + SZ_A2;
static const ll B_T1TH = B_XZL  + SZ_A2;
static const ll B_T1TL = B_T1TH + SZ_A2;
static const ll B_T2TH = B_T1TL + SZ_A2;
static const ll B_T2TL = B_T2TH + SZ_A2;
static const ll B_T3TH = B_T2TL + SZ_A2;
static const ll B_T3TL = B_T3TH + SZ_A2;
static const ll B_AVTH = B_T3TL + SZ_A2;
static const ll B_AVTL = B_AVTH + SZ_LM;
static const ll B_ZVTH = B_AVTL + SZ_LM;
static const ll B_ZVTL = B_ZVTH + SZ_LM;
static const ll B_YH   = B_ZVTL + SZ_LM;
static const ll B_YL   = B_YH   + SZ_Y;
static const ll B_TOTAL= B_YL   + SZ_Y;

__device__ __align__(16) float g_f32[F_TOTAL];
__device__ __align__(16) bf16  g_bf[B_TOTAL];
__device__ float g_norm[2];

// ---------------- stream/event context ----------------
struct StreamCtx {
    cudaStream_t s2;
    cudaEvent_t e0, e1, e2, e3, e4;
    StreamCtx() {
        cudaStreamCreateWithFlags(&s2, cudaStreamNonBlocking);
        cudaEventCreateWithFlags(&e0, cudaEventDisableTiming);
        cudaEventCreateWithFlags(&e1, cudaEventDisableTiming);
        cudaEventCreateWithFlags(&e2, cudaEventDisableTiming);
        cudaEventCreateWithFlags(&e3, cudaEventDisableTiming);
        cudaEventCreateWithFlags(&e4, cudaEventDisableTiming);
    }
};
static StreamCtx g_ctx;

// ---------------- helpers ----------------
__device__ __forceinline__ uint32_t smem_u32(const void* p) {
    uint32_t a;
    asm("{ .reg .u64 t; cvta.to.shared.u64 t, %1; cvt.u32.u64 %0, t; }" : "=r"(a) : "l"(p));
    return a;
}
__device__ __forceinline__ void cp16(uint32_t s, const void* g) {
    asm volatile("cp.async.cg.shared.global [%0], [%1], 16;" :: "r"(s), "l"(g));
}
#define CP_COMMIT asm volatile("cp.async.commit_group;" ::: "memory")
#define CP_WAIT0  asm volatile("cp.async.wait_group 0;" ::: "memory")

#define LDSM4(R, A) \
    asm volatile("ldmatrix.sync.aligned.m8n8.x4.shared.b16 {%0,%1,%2,%3}, [%4];" \
        : "=r"((R)[0]), "=r"((R)[1]), "=r"((R)[2]), "=r"((R)[3]) : "r"(A))

#define MMA16816(D, Aa, Bb) \
    asm volatile("mma.sync.aligned.m16n8k16.row.col.f32.bf16.bf16.f32 " \
        "{%0,%1,%2,%3}, {%4,%5,%6,%7}, {%8,%9}, {%0,%1,%2,%3};" \
        : "+f"((D)[0]), "+f"((D)[1]), "+f"((D)[2]), "+f"((D)[3]) \
        : "r"((Aa)[0]), "r"((Aa)[1]), "r"((Aa)[2]), "r"((Aa)[3]), \
          "r"((Bb)[0]), "r"((Bb)[1]))

#define SWZ128(o) ((o) ^ (((o) >> 3) & 0x70))

__device__ __forceinline__ void split2(float v, bf16& h, bf16& l) {
    h = __float2bfloat16(v);
    l = __float2bfloat16(v - __bfloat162float(h));
}
__device__ __forceinline__ uint32_t packh2(float a, float b) {
    __nv_bfloat162 p; p.x = __float2bfloat16(a); p.y = __float2bfloat16(b);
    return *(uint32_t*)&p;
}
__device__ __forceinline__ uint32_t packl2(float a, float b) {
    __nv_bfloat162 p;
    p.x = __float2bfloat16(a - __bfloat162float(__float2bfloat16(a)));
    p.y = __float2bfloat16(b - __bfloat162float(__float2bfloat16(b)));
    return *(uint32_t*)&p;
}

// ---------------- generic split-bf16 HMMA NT GEMM ----------------
// SPLIT modes: 0 = hi-only, 1 = full split (3 terms), 2 = A-hi/B-split (2 terms)
template<int TM, int TN, int SPLIT>
__host__ __device__ constexpr int stage_bytes() {
    return ((SPLIT == 1) ? 2 * (TM + TN) : (SPLIT == 2) ? (TM + 2 * TN) : (TM + TN)) * 128;
}

template<int TM, int TN, int SPLIT, int NT>
__device__ __forceinline__ void load_stage(uint32_t sbase,
    const bf16* pAh, const bf16* pAl, const bf16* pBh, const bf16* pBl,
    int K, int k0, int tid)
{
    constexpr uint32_t OAL = TM * 128;
    constexpr uint32_t OBH = ((SPLIT == 1) ? 2 : 1) * TM * 128;
    constexpr uint32_t OBL = OBH + TN * 128;
#pragma unroll
    for (int i = 0; i < TM * 8 / NT; i++) {
        int idx = tid + i * NT;
        int r = idx >> 3, c = idx & 7;
        uint32_t so = SWZ128((uint32_t)(r * 128 + c * 16));
        ll go = (ll)r * K + k0 + c * 8;
        cp16(sbase + so, pAh + go);
        if (SPLIT == 1) cp16(sbase + OAL + so, pAl + go);
    }
#pragma unroll
    for (int i = 0; i < TN * 8 / NT; i++) {
        int idx = tid + i * NT;
        int r = idx >> 3, c = idx & 7;
        uint32_t so = SWZ128((uint32_t)(r * 128 + c * 16));
        ll go = (ll)r * K + k0 + c * 8;
        cp16(sbase + OBH + so, pBh + go);
        if (SPLIT >= 1) cp16(sbase + OBL + so, pBl + go);
    }
}

template<int TM, int TN, int SPLIT, int NT>
__global__ void __launch_bounds__(NT, (NT == 256 && TM == 64) ? 2 : 1) gemm_mma(
    const bf16* __restrict__ Ah, const bf16* __restrict__ Al,
    const bf16* __restrict__ Bh, const bf16* __restrict__ Bl,
    float* __restrict__ C, bf16* __restrict__ Ch, bf16* __restrict__ Cl,
    bf16* __restrict__ CTh, bf16* __restrict__ CTl,
    const float* __restrict__ bias,
    int K, int Kc, int nbatch, int ldc, int ldct,
    ll sA, ll sB, ll sC, ll sCT,
    float alpha, float diagc, int flags)
{
    extern __shared__ char smem[];
    constexpr int WR = (NT == 512) ? 4 : 2;
    constexpr int MI = TM / WR / 16;
    constexpr int NG = TN / 4 / 8;
    constexpr uint32_t OBH = ((SPLIT == 1) ? 2 : 1) * TM * 128;
    constexpr uint32_t OBL = OBH + TN * 128;
    constexpr int STAGE = stage_bytes<TM, TN, SPLIT>();

    const int tid = threadIdx.x, wid = tid >> 5, lane = tid & 31;
    const int bz = blockIdx.z % nbatch;
    const int koff = (blockIdx.z / nbatch) * Kc;
    const int m0 = blockIdx.y * TM, n0 = blockIdx.x * TN;
    const int wm = (wid % WR) * (TM / WR);
    const int wn = (wid / WR) * (TN / 4);
    uint32_t sb = smem_u32(smem);

    const bf16* pAh = Ah + bz * sA + (ll)m0 * K + koff;
    const bf16* pAl = (SPLIT == 1) ? (Al + bz * sA + (ll)m0 * K + koff) : pAh;
    const bf16* pBh = Bh + bz * sB + (ll)n0 * K + koff;
    const bf16* pBl = (SPLIT >= 1) ? (Bl + bz * sB + (ll)n0 * K + koff) : pBh;

    float acc[MI][NG][4];
#pragma unroll
    for (int a = 0; a < MI; a++)
#pragma unroll
        for (int b = 0; b < NG; b++)
#pragma unroll
            for (int c = 0; c < 4; c++) acc[a][b][c] = 0.f;

    const int nch = Kc >> 6;
    load_stage<TM, TN, SPLIT, NT>(sb, pAh, pAl, pBh, pBl, K, 0, tid);
    CP_COMMIT;

    for (int ck = 0; ck < nch; ck++) {
        CP_WAIT0;
        __syncthreads();
        if (ck + 1 < nch) {
            load_stage<TM, TN, SPLIT, NT>(sb + ((ck + 1) & 1) * STAGE, pAh, pAl, pBh, pBl, K, (ck + 1) * 64, tid);
            CP_COMMIT;
        }
        uint32_t s = sb + (ck & 1) * STAGE;
#pragma unroll
        for (int ks = 0; ks < 4; ks++) {
            uint32_t aH[MI][4], aL[MI][4];
#pragma unroll
            for (int mi = 0; mi < MI; mi++) {
                int row = wm + mi * 16 + (lane & 15);
                int c16 = ks * 2 + (lane >> 4);
                uint32_t off = SWZ128((uint32_t)(row * 128 + c16 * 16));
                LDSM4(aH[mi], s + off);
                if (SPLIT == 1) LDSM4(aL[mi], s + TM * 128 + off);
            }
            uint32_t bH[NG][2], bL[NG][2];
#pragma unroll
            for (int bj = 0; bj < NG / 2; bj++) {
                int row = wn + bj * 16 + (lane & 15);
                int c16 = ks * 2 + (lane >> 4);
                uint32_t off = SWZ128((uint32_t)(row * 128 + c16 * 16));
                uint32_t t[4];
                LDSM4(t, s + OBH + off);
                bH[bj * 2][0] = t[0]; bH[bj * 2 + 1][0] = t[1];
                bH[bj * 2][1] = t[2]; bH[bj * 2 + 1][1] = t[3];
                if (SPLIT >= 1) {
                    LDSM4(t, s + OBL + off);
                    bL[bj * 2][0] = t[0]; bL[bj * 2 + 1][0] = t[1];
                    bL[bj * 2][1] = t[2]; bL[bj * 2 + 1][1] = t[3];
                }
            }
#pragma unroll
            for (int mi = 0; mi < MI; mi++)
#pragma unroll
                for (int g = 0; g < NG; g++) MMA16816(acc[mi][g], aH[mi], bH[g]);
            if (SPLIT >= 1) {
#pragma unroll
                for (int mi = 0; mi < MI; mi++)
#pragma unroll
                    for (int g = 0; g < NG; g++) MMA16816(acc[mi][g], aH[mi], bL[g]);
            }
            if (SPLIT == 1) {
#pragma unroll
                for (int mi = 0; mi < MI; mi++)
#pragma unroll
                    for (int g = 0; g < NG; g++) MMA16816(acc[mi][g], aL[mi], bH[g]);
            }
        }
    }

    const bool diagT = (flags & 8) != 0;
    const bool diagN = diagT && !(flags & 16);
#pragma unroll
    for (int mi = 0; mi < MI; mi++) {
#pragma unroll
        for (int g = 0; g < NG; g++) {
#pragma unroll
            for (int half = 0; half < 2; half++) {
                int r = m0 + wm + mi * 16 + (lane >> 2) + half * 8;
                int n = n0 + wn + g * 8 + (lane & 3) * 2;
                float a0 = acc[mi][g][half * 2 + 0];
                float a1v = acc[mi][g][half * 2 + 1];
                if (flags & 64) {
                    int nq = n + ldct;
                    int sel = nq >> 9;
                    int hh = (nq >> 6) & 7;
                    int d  = nq & 63;
                    int b  = r >> 12, t = r & 4095;
                    ll hidx = ((ll)((b << 3) + hh) * NTOK + t) * 64 + d;
                    if (sel == 0) {
                        *(uint32_t*)(g_bf + B_QH + hidx) = packh2(a0 * 0.125f, a1v * 0.125f);
                        *(uint32_t*)(g_bf + B_QL + hidx) = packl2(a0 * 0.125f, a1v * 0.125f);
                    } else if (sel == 1) {
                        *(uint32_t*)(g_bf + B_KH + hidx) = packh2(a0, a1v);
                        *(uint32_t*)(g_bf + B_KL + hidx) = packl2(a0, a1v);
                    } else {
                        *(float2*)(g_f32 + F_V + hidx) = make_float2(a0, a1v);
                        bf16 h0, l0, h1, l1;
                        split2(a0, h0, l0); split2(a1v, h1, l1);
                        ll vt = ((ll)((b << 3) + hh) * 64 + d) * NTOK + t;
                        g_bf[B_VTH + vt] = h0;
                        g_bf[B_VTH + vt + NTOK] = h1;
                    }
                    continue;
                }
                if (flags & 3) {
                    float n0v = diagN ? ((r == n)     ? diagc : 0.f) - a0  : alpha * a0;
                    float n1v = diagN ? ((r == n + 1) ? diagc : 0.f) - a1v : alpha * a1v;
                    if (bias) { n0v += bias[n]; n1v += bias[n + 1]; }
                    ll o = bz * sC + (ll)r * ldc + n;
                    if (flags & 1) {
                        if (flags & 32) { atomicAdd(C + o, n0v); atomicAdd(C + o + 1, n1v); }
                        else *(float2*)(C + o) = make_float2(n0v, n1v);
                    }
                    if (flags & 2) {
                        *(uint32_t*)(Ch + o) = packh2(n0v, n1v);
                        *(uint32_t*)(Cl + o) = packl2(n0v, n1v);
                    }
                }
                if (flags & 4) {
                    float t0v = diagT ? ((r == n)     ? diagc : 0.f) - a0  : alpha * a0;
                    float t1v = diagT ? ((r == n + 1) ? diagc : 0.f) - a1v : alpha * a1v;
                    bf16 h0, l0, h1, l1;
                    split2(t0v, h0, l0); split2(t1v, h1, l1);
                    ll ot0 = bz * sCT + (ll)n * ldct + r;
                    ll ot1 = bz * sCT + (ll)(n + 1) * ldct + r;
                    CTh[ot0] = h0; CTl[ot0] = l0;
                    CTh[ot1] = h1; CTl[ot1] = l1;
                }
            }
        }
    }
}

// ---------------- fused GEMM + row softmax (attn2) ----------------
__global__ void __launch_bounds__(256, 1) attn_gemm_softmax(
    const bf16* __restrict__ Ah, const bf16* __restrict__ Al,
    const bf16* __restrict__ Bh, const bf16* __restrict__ Bl,
    float* __restrict__ C32, bf16* __restrict__ Ch, bf16* __restrict__ Cl,
    ll sA, ll sB, ll sC)
{
    extern __shared__ char smem[];
    __shared__ float redm[2][32][4];
    __shared__ float reds[2][32][4];
    const int tid = threadIdx.x, wid = tid >> 5, lane = tid & 31;
    const int bz = blockIdx.y;
    const int m0 = blockIdx.x * 64;
    const int wm = (wid & 1) * 32;
    const int wn = (wid >> 1) * 64;
    uint32_t sb = smem_u32(smem);

    const bf16* pAh = Ah + bz * sA + (ll)m0 * 64;
    const bf16* pAl = Al + bz * sA + (ll)m0 * 64;
    const bf16* pBh = Bh + bz * sB;
    const bf16* pBl = Bl + bz * sB;

#pragma unroll
    for (int i = 0; i < 2; i++) {
        int idx = tid + i * 256;
        int r = idx >> 3, c = idx & 7;
        uint32_t so = SWZ128((uint32_t)(r * 128 + c * 16));
        cp16(sb + so, pAh + (ll)r * 64 + c * 8);
        cp16(sb + 8192 + so, pAl + (ll)r * 64 + c * 8);
    }
#pragma unroll
    for (int i = 0; i < 8; i++) {
        int idx = tid + i * 256;
        int r = idx >> 3, c = idx & 7;
        uint32_t so = SWZ128((uint32_t)(r * 128 + c * 16));
        cp16(sb + 16384 + so, pBh + (ll)r * 64 + c * 8);
        cp16(sb + 49152 + so, pBl + (ll)r * 64 + c * 8);
    }
    CP_COMMIT;

    float acc[2][8][4];
#pragma unroll
    for (int a = 0; a < 2; a++)
#pragma unroll
        for (int b = 0; b < 8; b++)
#pragma unroll
            for (int c = 0; c < 4; c++) acc[a][b][c] = 0.f;

    CP_WAIT0;
    __syncthreads();
#pragma unroll
    for (int ks = 0; ks < 4; ks++) {
        uint32_t aH[2][4], aL[2][4];
#pragma unroll
        for (int mi = 0; mi < 2; mi++) {
            int row = wm + mi * 16 + (lane & 15);
            int c16 = ks * 2 + (lane >> 4);
            uint32_t off = SWZ128((uint32_t)(row * 128 + c16 * 16));
            LDSM4(aH[mi], sb + off);
            LDSM4(aL[mi], sb + 8192 + off);
        }
        uint32_t bHf[8][2], bLf[8][2];
#pragma unroll
        for (int bj = 0; bj < 4; bj++) {
            int row = wn + bj * 16 + (lane & 15);
            int c16 = ks * 2 + (lane >> 4);
            uint32_t off = SWZ128((uint32_t)(row * 128 + c16 * 16));
            uint32_t t[4];
            LDSM4(t, sb + 16384 + off);
            bHf[bj * 2][0] = t[0]; bHf[bj * 2 + 1][0] = t[1];
            bHf[bj * 2][1] = t[2]; bHf[bj * 2 + 1][1] = t[3];
            LDSM4(t, sb + 49152 + off);
            bLf[bj * 2][0] = t[0]; bLf[bj * 2 + 1][0] = t[1];
            bLf[bj * 2][1] = t[2]; bLf[bj * 2 + 1][1] = t[3];
        }
#pragma unroll
        for (int mi = 0; mi < 2; mi++)
#pragma unroll
            for (int g = 0; g < 8; g++) MMA16816(acc[mi][g], aH[mi], bHf[g]);
#pragma unroll
        for (int mi = 0; mi < 2; mi++)
#pragma unroll
            for (int g = 0; g < 8; g++) MMA16816(acc[mi][g], aH[mi], bLf[g]);
#pragma unroll
        for (int mi = 0; mi < 2; mi++)
#pragma unroll
            for (int g = 0; g < 8; g++) MMA16816(acc[mi][g], aL[mi], bHf[g]);
    }

    float mx[2][2];
#pragma unroll
    for (int mi = 0; mi < 2; mi++)
#pragma unroll
        for (int half = 0; half < 2; half++) {
            float m = -1e30f;
#pragma unroll
            for (int g = 0; g < 8; g++) {
                m = fmaxf(m, acc[mi][g][half * 2]);
                m = fmaxf(m, acc[mi][g][half * 2 + 1]);
            }
            m = fmaxf(m, __shfl_xor_sync(0xffffffffu, m, 1));
            m = fmaxf(m, __shfl_xor_sync(0xffffffffu, m, 2));
            mx[mi][half] = m;
        }
    if ((lane & 3) == 0) {
#pragma unroll
        for (int mi = 0; mi < 2; mi++)
#pragma unroll
            for (int half = 0; half < 2; half++)
                redm[wid & 1][mi * 16 + (lane >> 2) + half * 8][wid >> 1] = mx[mi][half];
    }
    __syncthreads();
    float sm[2][2];
#pragma unroll
    for (int mi = 0; mi < 2; mi++)
#pragma unroll
        for (int half = 0; half < 2; half++) {
            int ri = mi * 16 + (lane >> 2) + half * 8;
            float m = fmaxf(fmaxf(redm[wid & 1][ri][0], redm[wid & 1][ri][1]),
                            fmaxf(redm[wid & 1][ri][2], redm[wid & 1][ri][3]));
            float s = 0.f;
#pragma unroll
            for (int g = 0; g < 8; g++) {
                float e0 = __expf(acc[mi][g][half * 2] - m);
                float e1 = __expf(acc[mi][g][half * 2 + 1] - m);
                acc[mi][g][half * 2] = e0; acc[mi][g][half * 2 + 1] = e1;
                s += e0 + e1;
            }
            s += __shfl_xor_sync(0xffffffffu, s, 1);
            s += __shfl_xor_sync(0xffffffffu, s, 2);
            sm[mi][half] = s;
        }
    if ((lane & 3) == 0) {
#pragma unroll
        for (int mi = 0; mi < 2; mi++)
#pragma unroll
            for (int half = 0; half < 2; half++)
                reds[wid & 1][mi * 16 + (lane >> 2) + half * 8][wid >> 1] = sm[mi][half];
    }
    __syncthreads();
#pragma unroll
    for (int mi = 0; mi < 2; mi++)
#pragma unroll
        for (int half = 0; half < 2; half++) {
            int ri = mi * 16 + (lane >> 2) + half * 8;
            float tot = reds[wid & 1][ri][0] + reds[wid & 1][ri][1]
                      + reds[wid & 1][ri][2] + reds[wid & 1][ri][3];
            float inv = 1.f / tot;
            int r = m0 + wm + ri;
#pragma unroll
            for (int g = 0; g < 8; g++) {
                int n = wn + g * 8 + (lane & 3) * 2;
                float v0 = acc[mi][g][half * 2] * inv;
                float v1 = acc[mi][g][half * 2 + 1] * inv;
                ll o = bz * sC + (ll)r * 256 + n;
                *(uint32_t*)(Ch + o) = packh2(v0, v1);
                *(uint32_t*)(Cl + o) = packl2(v0, v1);
                *(float2*)(C32 + o) = make_float2(v0, v1);
            }
        }
}

// ---------------- fused attn3 + softmax + @v -> avT (512 thr; 1-term logits & PV) ----------------
#define VROW 272
__global__ void __launch_bounds__(512, 1) fa3_av(
    const bf16* __restrict__ Qh,
    const bf16* __restrict__ Kh,
    const bf16* __restrict__ Vth,
    bf16* __restrict__ AVTh, bf16* __restrict__ AVTl,
    ll sQ, ll sK, ll sVT, ll sAVT)
{
    extern __shared__ char smem[];
    __shared__ float Os[64 * 68];
    __shared__ float rsm[64];
    const int tid = threadIdx.x, wid = tid >> 5, lane = tid & 31;
    const int bz = blockIdx.y;
    const int m0 = blockIdx.x * 64;
    const int wm = (wid & 3) * 16;
    const int wn = (wid >> 2) * 32;
    uint32_t sb = smem_u32(smem);
    constexpr uint32_t ST0 = 8192;
    constexpr uint32_t OVT = 16384;
    constexpr uint32_t STG = OVT + 64 * VROW;

    for (int i = tid; i < 64 * 68; i += 512) Os[i] = 0.f;
    if (tid < 64) rsm[tid] = 0.f;

    const bf16* pQh = Qh + bz * sQ + (ll)m0 * 64;
    const bf16* pKh = Kh + bz * sK;
    const bf16* pVh = Vth + bz * sVT;

    {
        int r = tid >> 3, c = tid & 7;
        uint32_t so = SWZ128((uint32_t)(r * 128 + c * 16));
        cp16(sb + so, pQh + (ll)r * 64 + c * 8);
    }
    {
        uint32_t s = sb + ST0;
#pragma unroll
        for (int i = 0; i < 2; i++) {
            int idx = tid + i * 512;
            int r = idx >> 3, c = idx & 7;
            uint32_t so = SWZ128((uint32_t)(r * 128 + c * 16));
            cp16(s + so, pKh + (ll)r * 64 + c * 8);
        }
#pragma unroll
        for (int i = 0; i < 2; i++) {
            int idx = tid + i * 512;
            int r = idx >> 4, c = idx & 15;
            uint32_t so = (uint32_t)(r * VROW + c * 16);
            cp16(s + OVT + so, pVh + (ll)r * NTOK + c * 8);
        }
    }
    CP_COMMIT;

    float acc_o[8][4];
#pragma unroll
    for (int b = 0; b < 8; b++)
#pragma unroll
        for (int c = 0; c < 4; c++) acc_o[b][c] = 0.f;
    float rs[2] = {0.f, 0.f};

    for (int ck = 0; ck < 32; ck++) {
        CP_WAIT0;
        __syncthreads();
        if (ck + 1 < 32) {
            uint32_t s = sb + ST0 + ((ck + 1) & 1) * STG;
            int tok = (ck + 1) * 128;
#pragma unroll
            for (int i = 0; i < 2; i++) {
                int idx = tid + i * 512;
                int r = idx >> 3, c = idx & 7;
                uint32_t so = SWZ128((uint32_t)(r * 128 + c * 16));
                cp16(s + so, pKh + (ll)(tok + r) * 64 + c * 8);
            }
#pragma unroll
            for (int i = 0; i < 2; i++) {
                int idx = tid + i * 512;
                int r = idx >> 4, c = idx & 15;
                uint32_t so = (uint32_t)(r * VROW + c * 16);
                cp16(s + OVT + so, pVh + (ll)r * NTOK + tok + c * 8);
            }
            CP_COMMIT;
        }
        uint32_t s = sb + ST0 + (ck & 1) * STG;

        float accl[4][4];
#pragma unroll
        for (int b = 0; b < 4; b++)
#pragma unroll
            for (int c = 0; c < 4; c++) accl[b][c] = 0.f;
#pragma unroll
        for (int ks = 0; ks < 4; ks++) {
            int c16 = ks * 2 + (lane >> 4);
            uint32_t aH[4];
            {
                int row = wm + (lane & 15);
                uint32_t off = SWZ128((uint32_t)(row * 128 + c16 * 16));
                LDSM4(aH, sb + off);
            }
            uint32_t bHf[4][2];
#pragma unroll
            for (int bj = 0; bj < 2; bj++) {
                int row = wn + bj * 16 + (lane & 15);
                uint32_t off = SWZ128((uint32_t)(row * 128 + c16 * 16));
                uint32_t t[4];
                LDSM4(t, s + off);
                bHf[bj * 2][0] = t[0]; bHf[bj * 2 + 1][0] = t[1];
                bHf[bj * 2][1] = t[2]; bHf[bj * 2 + 1][1] = t[3];
            }
#pragma unroll
            for (int g = 0; g < 4; g++) MMA16816(accl[g], aH, bHf[g]);
        }
#pragma unroll
        for (int half = 0; half < 2; half++) {
            float srow = 0.f;
#pragma unroll
            for (int g = 0; g < 4; g++) {
                float e0 = __expf(accl[g][half * 2]);
                float e1 = __expf(accl[g][half * 2 + 1]);
                accl[g][half * 2] = e0;
                accl[g][half * 2 + 1] = e1;
                srow += e0 + e1;
            }
            rs[half] += srow;
        }
#pragma unroll
        for (int kk = 0; kk < 2; kk++) {
            uint32_t aPh[4];
            aPh[0] = packh2(accl[2 * kk][0], accl[2 * kk][1]);
            aPh[1] = packh2(accl[2 * kk][2], accl[2 * kk][3]);
            aPh[2] = packh2(accl[2 * kk + 1][0], accl[2 * kk + 1][1]);
            aPh[3] = packh2(accl[2 * kk + 1][2], accl[2 * kk + 1][3]);
#pragma unroll
            for (int bj = 0; bj < 4; bj++) {
                uint32_t addr = s + OVT + (uint32_t)((bj * 16 + (lane & 15)) * VROW)
                              + (uint32_t)((wn + kk * 16) * 2 + (lane >> 4) * 16);
                uint32_t t[4];
                LDSM4(t, addr);
                uint32_t bh0[2] = {t[0], t[2]}, bh1[2] = {t[1], t[3]};
                MMA16816(acc_o[2 * bj],     aPh, bh0);
                MMA16816(acc_o[2 * bj + 1], aPh, bh1);
            }
        }
    }

#pragma unroll
    for (int half = 0; half < 2; half++) {
        float v = rs[half];
        v += __shfl_xor_sync(0xffffffffu, v, 1);
        v += __shfl_xor_sync(0xffffffffu, v, 2);
        if ((lane & 3) == 0)
            atomicAdd(&rsm[wm + (lane >> 2) + half * 8], v);
    }
#pragma unroll
    for (int g = 0; g < 8; g++) {
        int r0 = wm + (lane >> 2);
        int c = g * 8 + (lane & 3) * 2;
        atomicAdd(&Os[r0 * 68 + c],           acc_o[g][0]);
        atomicAdd(&Os[r0 * 68 + c + 1],       acc_o[g][1]);
        atomicAdd(&Os[(r0 + 8) * 68 + c],     acc_o[g][2]);
        atomicAdd(&Os[(r0 + 8) * 68 + c + 1], acc_o[g][3]);
    }
    __syncthreads();
#pragma unroll
    for (int i = 0; i < 8; i++) {
        int idx = tid + i * 512;
        int r = idx >> 6, d = idx & 63;
        float val = Os[r * 68 + d] / rsm[r];
        bf16 hh, lo; split2(val, hh, lo);
        ll o = bz * sAVT + (ll)d * MLM + (m0 + r);
        AVTh[o] = hh; AVTl[o] = lo;
    }
}

// ---------------- fused attn1 + softmax + P@zav + conv -> y (512 thr; 1-term logits) ----------------
#define ZROW 528
__global__ void __launch_bounds__(512, 1) attn1_outh(
    const bf16* __restrict__ Ah,
    const bf16* __restrict__ Bh,
    const bf16* __restrict__ Zh, const bf16* __restrict__ Zl,
    const float* __restrict__ Vv, const float* __restrict__ kern,
    bf16* __restrict__ Yh, bf16* __restrict__ Yl,
    ll sA, ll sB, ll sZ, ll sV, int bzoff)
{
    extern __shared__ char smem[];
    __shared__ float redm[4][16][4];
    __shared__ float reds[4][16][4];
    __shared__ float khs[33];
    const int tid = threadIdx.x, wid = tid >> 5, lane = tid & 31;
    const int bz = blockIdx.y + bzoff;
    const int m0 = blockIdx.x * 64;
    const int wm = (wid & 3) * 16;
    const int wn = (wid >> 2) * 64;
    const int b_ = bz >> 3, h_ = bz & 7;
    uint32_t sb = smem_u32(smem);
    // compacted layout: A hi [0,8K), B klm hi [8K,40K), Zh [40960,...), Zl, O, V
    constexpr uint32_t OBH2 = 8192;
    constexpr uint32_t OZH = 40960;
    constexpr uint32_t OZL = OZH + 64 * ZROW;
    constexpr uint32_t OO  = OZL + 64 * ZROW;
    constexpr uint32_t OV  = OO + 64 * 68 * 4;
    float* Os = (float*)(smem + OO);
    float* sv = (float*)(smem + OV);

    if (tid < 33) khs[tid] = kern[h_ * 33 + tid];

    const bf16* pAh = Ah + bz * sA + (ll)m0 * 64;
    const bf16* pBh = Bh + bz * sB;
    const bf16* pZh = Zh + bz * sZ;
    const bf16* pZl = Zl + bz * sZ;
    const float* pV = Vv + bz * sV;

    {
        int r = tid >> 3, c = tid & 7;
        uint32_t so = SWZ128((uint32_t)(r * 128 + c * 16));
        cp16(sb + so, pAh + (ll)r * 64 + c * 8);
    }
#pragma unroll
    for (int i = 0; i < 4; i++) {
        int idx = tid + i * 512;
        int r = idx >> 3, c = idx & 7;
        uint32_t so = SWZ128((uint32_t)(r * 128 + c * 16));
        cp16(sb + OBH2 + so, pBh + (ll)r * 64 + c * 8);
    }
#pragma unroll
    for (int i = 0; i < 4; i++) {
        int idx = tid + i * 512;
        int r = idx >> 5, c = idx & 31;
        uint32_t so = (uint32_t)(r * ZROW + c * 16);
        cp16(sb + OZH + so, pZh + (ll)r * 256 + c * 8);
        cp16(sb + OZL + so, pZl + (ll)r * 256 + c * 8);
    }
#pragma unroll
    for (int i = 0; i < 3; i++) {
        int idx = tid + i * 512;
        int r = idx >> 4, c = idx & 15;
        int tt = m0 - 16 + r;
        if (tt >= 0 && tt < NTOK)
            cp16(sb + OV + (uint32_t)(r * 256 + c * 16), pV + (ll)tt * 64 + c * 4);
        else
            *(float4*)(smem + OV + r * 256 + c * 16) = make_float4(0.f, 0.f, 0.f, 0.f);
    }
    CP_COMMIT;
#pragma unroll
    for (int i = 0; i < 9; i++) {
        int idx = tid + i * 512;
        if (idx < 64 * 68) Os[idx] = 0.f;
    }

    float acc[8][4];
#pragma unroll
    for (int b = 0; b < 8; b++)
#pragma unroll
        for (int c = 0; c < 4; c++) acc[b][c] = 0.f;

    CP_WAIT0;
    __syncthreads();
    // logits: qh · klmh only (1-term; klm_lo washes per fa3 evidence)
#pragma unroll
    for (int ks = 0; ks < 4; ks++) {
        uint32_t aH[4];
        {
            int row = wm + (lane & 15);
            int c16 = ks * 2 + (lane >> 4);
            uint32_t off = SWZ128((uint32_t)(row * 128 + c16 * 16));
            LDSM4(aH, sb + off);
        }
        uint32_t bHf[8][2];
#pragma unroll
        for (int bj = 0; bj < 4; bj++) {
            int row = wn + bj * 16 + (lane & 15);
            int c16 = ks * 2 + (lane >> 4);
            uint32_t off = SWZ128((uint32_t)(row * 128 + c16 * 16));
            uint32_t t[4];
            LDSM4(t, sb + OBH2 + off);
            bHf[bj * 2][0] = t[0]; bHf[bj * 2 + 1][0] = t[1];
            bHf[bj * 2][1] = t[2]; bHf[bj * 2 + 1][1] = t[3];
        }
#pragma unroll
        for (int g = 0; g < 8; g++) MMA16816(acc[g], aH, bHf[g]);
    }

    float mx[2];
#pragma unroll
    for (int half = 0; half < 2; half++) {
        float m = -1e30f;
#pragma unroll
        for (int g = 0; g < 8; g++) {
            m = fmaxf(m, acc[g][half * 2]);
            m = fmaxf(m, acc[g][half * 2 + 1]);
        }
        m = fmaxf(m, __shfl_xor_sync(0xffffffffu, m, 1));
        m = fmaxf(m, __shfl_xor_sync(0xffffffffu, m, 2));
        mx[half] = m;
    }
    if ((lane & 3) == 0) {
#pragma unroll
        for (int half = 0; half < 2; half++)
            redm[wid & 3][(lane >> 2) + half * 8][wid >> 2] = mx[half];
    }
    __syncthreads();
    float sm[2];
#pragma unroll
    for (int half = 0; half < 2; half++) {
        int ri = (lane >> 2) + half * 8;
        float m = fmaxf(fmaxf(redm[wid & 3][ri][0], redm[wid & 3][ri][1]),
                        fmaxf(redm[wid & 3][ri][2], redm[wid & 3][ri][3]));
        float s = 0.f;
#pragma unroll
        for (int g = 0; g < 8; g++) {
            float e0 = __expf(acc[g][half * 2] - m);
            float e1 = __expf(acc[g][half * 2 + 1] - m);
            acc[g][half * 2] = e0; acc[g][half * 2 + 1] = e1;
            s += e0 + e1;
        }
        s += __shfl_xor_sync(0xffffffffu, s, 1);
        s += __shfl_xor_sync(0xffffffffu, s, 2);
        sm[half] = s;
    }
    if ((lane & 3) == 0) {
#pragma unroll
        for (int half = 0; half < 2; half++)
            reds[wid & 3][(lane >> 2) + half * 8][wid >> 2] = sm[half];
    }
    __syncthreads();
#pragma unroll
    for (int half = 0; half < 2; half++) {
        int ri = (lane >> 2) + half * 8;
        float tot = reds[wid & 3][ri][0] + reds[wid & 3][ri][1]
                  + reds[wid & 3][ri][2] + reds[wid & 3][ri][3];
        float inv = 1.f / tot;
#pragma unroll
        for (int g = 0; g < 8; g++) {
            acc[g][half * 2]     *= inv;
            acc[g][half * 2 + 1] *= inv;
        }
    }

    float acc_o[8][4];
#pragma unroll
    for (int b = 0; b < 8; b++)
#pragma unroll
        for (int c = 0; c < 4; c++) acc_o[b][c] = 0.f;

    // P @ zav: 2-term (Ph·zh + Ph·zl)
#pragma unroll
    for (int ks = 0; ks < 4; ks++) {
        uint32_t aPh[4];
        aPh[0] = packh2(acc[2 * ks][0], acc[2 * ks][1]);
        aPh[1] = packh2(acc[2 * ks][2], acc[2 * ks][3]);
        aPh[2] = packh2(acc[2 * ks + 1][0], acc[2 * ks + 1][1]);
        aPh[3] = packh2(acc[2 * ks + 1][2], acc[2 * ks + 1][3]);
#pragma unroll
        for (int bj = 0; bj < 4; bj++) {
            uint32_t addr = sb + OZH + (uint32_t)((bj * 16 + (lane & 15)) * ZROW)
                          + (uint32_t)((wn + ks * 16) * 2 + (lane >> 4) * 16);
            uint32_t t[4], u[4];
            LDSM4(t, addr);
            LDSM4(u, addr + (OZL - OZH));
            uint32_t bh0[2] = {t[0], t[2]}, bh1[2] = {t[1], t[3]};
            uint32_t bl0[2] = {u[0], u[2]}, bl1[2] = {u[1], u[3]};
            MMA16816(acc_o[2 * bj],     aPh, bh0);
            MMA16816(acc_o[2 * bj],     aPh, bl0);
            MMA16816(acc_o[2 * bj + 1], aPh, bh1);
            MMA16816(acc_o[2 * bj + 1], aPh, bl1);
        }
    }

#pragma unroll
    for (int g = 0; g < 8; g++) {
        int r0 = wm + (lane >> 2);
        int c = g * 8 + (lane & 3) * 2;
        atomicAdd(&Os[r0 * 68 + c],           acc_o[g][0]);
        atomicAdd(&Os[r0 * 68 + c + 1],       acc_o[g][1]);
        atomicAdd(&Os[(r0 + 8) * 68 + c],     acc_o[g][2]);
        atomicAdd(&Os[(r0 + 8) * 68 + c + 1], acc_o[g][3]);
    }
    __syncthreads();
#pragma unroll
    for (int i = 0; i < 8; i++) {
        int idx = tid + i * 512;
        int r = idx >> 6, d = idx & 63;
        float s = Os[r * 68 + d];
#pragma unroll
        for (int j = 0; j < 33; j++)
            s = fmaf(sv[(r + j) * 64 + d], khs[j], s);
        ll yo = ((ll)(b_ * NTOK + m0 + r)) * INNER + h_ * 64 + d;
        bf16 hh, lo; split2(s, hh, lo);
        Yh[yo] = hh; Yl[yo] = lo;
    }
}

// ---------------- elementwise kernels ----------------
__global__ void split_f32(const float* __restrict__ in, bf16* __restrict__ oh,
                          bf16* __restrict__ ol, ll n)
{
    ll i = (ll)blockIdx.x * 256 + threadIdx.x;
    if (i >= n) return;
    bf16 h, l; split2(in[i], h, l);
    oh[i] = h; ol[i] = l;
}

__global__ void transpose_split(const float* __restrict__ in, bf16* __restrict__ oh,
                                bf16* __restrict__ ol, int R, int C, ll sIn, ll sOut,
                                const float* __restrict__ nrmp, float dc, int usediag)
{
    __shared__ float t[32][33];
    ll b = blockIdx.z;
    const float* ip = in + b * sIn;
    int c0 = blockIdx.x * 32, r0 = blockIdx.y * 32;
    int tx = threadIdx.x, ty = threadIdx.y;
#pragma unroll
    for (int i = 0; i < 4; i++)
        t[ty + i * 8][tx] = ip[(ll)(r0 + ty + i * 8) * C + c0 + tx];
    __syncthreads();
    float alpha = nrmp ? 1.f / (nrmp[0] * nrmp[1]) : 1.f;
#pragma unroll
    for (int i = 0; i < 4; i++) {
        int cg = c0 + ty + i * 8, rg = r0 + tx;
        float v = t[tx][ty + i * 8];
        v = usediag ? ((rg == cg ? dc : 0.f) - v) : alpha * v;
        ll o = b * sOut + (ll)cg * R + rg;
        bf16 h, l; split2(v, h, l);
        oh[o] = h; ol[o] = l;
    }
}

__global__ void scale_split(const float* __restrict__ in, bf16* __restrict__ oh,
                            bf16* __restrict__ ol, ll n, const float* __restrict__ nrmp)
{
    ll i = (ll)blockIdx.x * 256 + threadIdx.x;
    if (i >= n) return;
    float inv = 1.f / (nrmp[0] * nrmp[1]);
    bf16 h, l; split2(in[i] * inv, h, l);
    oh[i] = h; ol[i] = l;
}

__global__ void landmark_split_bf(const bf16* __restrict__ xh, const bf16* __restrict__ xl,
                                  bf16* __restrict__ oh, bf16* __restrict__ ol)
{
    ll idx = (ll)blockIdx.x * 256 + threadIdx.x;
    if (idx >= SZ_LM) return;
    int d = (int)(idx & 63);
    int mi = (int)((idx >> 6) & 255);
    ll bh = idx >> 14;
    ll base = (bh * NTOK + (ll)mi * LGRP) * DH + d;
    float s = 0.f;
#pragma unroll
    for (int t = 0; t < LGRP; t++) {
        ll o = base + (ll)t * DH;
        s += __bfloat162float(xh[o]) + __bfloat162float(xl[o]);
    }
    bf16 h, l; split2(s * (1.f / LGRP), h, l);
    oh[idx] = h; ol[idx] = l;
}

__global__ void norm_init_kernel(float* nrm) { nrm[0] = 0.f; nrm[1] = 0.f; }

__global__ void pinv_norm_kernel(const float* __restrict__ x, float* __restrict__ nrm)
{
    int r = threadIdx.x;
    const float* xb = x + (ll)blockIdx.x * MLM * MLM;
    float rs = 0.f, cs = 0.f;
    for (int j = 0; j < MLM; j++) {
        rs += fabsf(xb[(ll)r * MLM + j]);
        cs += fabsf(xb[(ll)j * MLM + r]);
    }
    __shared__ float s1[256], s2[256];
    s1[r] = rs; s2[r] = cs; __syncthreads();
    for (int s = 128; s > 0; s >>= 1) {
        if (r < s) { s1[r] = fmaxf(s1[r], s1[r + s]); s2[r] = fmaxf(s2[r], s2[r + s]); }
        __syncthreads();
    }
    if (r == 0) {
        atomicMax((int*)&nrm[0], __float_as_int(s1[0]));
        atomicMax((int*)&nrm[1], __float_as_int(s2[0]));
    }
}

// ---------------- host ----------------
template<int TM, int TN, int SPLIT, int NT>
static inline void tcg(cudaStream_t st,
                       const bf16* Ah, const bf16* Al, const bf16* Bh, const bf16* Bl,
                       float* C, bf16* Ch, bf16* Cl, bf16* CTh, bf16* CTl,
                       const float* bias,
                       int M, int N, int K, int Kc, int ldc, int ldct,
                       ll sA, ll sB, ll sC, ll sCT, int batch, int kz,
                       float alpha, float diagc, int flags)
{
    dim3 grid(N / TN, M / TM, batch * kz);
    size_t sm = 2 * (size_t)stage_bytes<TM, TN, SPLIT>();
    gemm_mma<TM, TN, SPLIT, NT><<<grid, NT, sm, st>>>(Ah, Al, Bh, Bl, C, Ch, Cl, CTh, CTl, bias,
                                                      K, Kc, batch, ldc, ldct, sA, sB, sC, sCT,
                                                      alpha, diagc, flags);
}

extern "C" void kernel_launch(void* const* d_in, const int* in_sizes, int n_in,
                              void* d_out, int out_size)
{
    const float* x     = (const float*)d_in[0];
    const float* w_qkv = (const float*)d_in[1];
    const float* w_out = (const float*)d_in[2];
    const float* b_out = (const float*)d_in[3];
    const float* res_k = (const float*)d_in[4];
    float* out = (float*)d_out;

    const int A1O_SMEM = 40960 + 2 * 64 * ZROW + 64 * 68 * 4 + 96 * 64 * 4;  // 150528
    const int FA3_SMEM = 8192 + 2 * (16384 + 64 * VROW);                     // 75776

    cudaFuncSetAttribute(gemm_mma<128, 128, 1, 512>, cudaFuncAttributeMaxDynamicSharedMemorySize, 131072);
    cudaFuncSetAttribute(gemm_mma<128, 128, 2, 512>, cudaFuncAttributeMaxDynamicSharedMemorySize, 98304);
    cudaFuncSetAttribute(gemm_mma<64, 128, 1, 256>,  cudaFuncAttributeMaxDynamicSharedMemorySize, 98304);
    cudaFuncSetAttribute(gemm_mma<64, 128, 0, 256>,  cudaFuncAttributeMaxDynamicSharedMemorySize, 49152);
    cudaFuncSetAttribute(gemm_mma<64, 64, 1, 256>,   cudaFuncAttributeMaxDynamicSharedMemorySize, 65536);
    cudaFuncSetAttribute(attn_gemm_softmax, cudaFuncAttributeMaxDynamicSharedMemorySize, 81920);
    cudaFuncSetAttribute(attn1_outh, cudaFuncAttributeMaxDynamicSharedMemorySize, A1O_SMEM);
    cudaFuncSetAttribute(fa3_av, cudaFuncAttributeMaxDynamicSharedMemorySize, FA3_SMEM);

    float* F;  cudaGetSymbolAddress((void**)&F, g_f32);
    bf16*  Bp; cudaGetSymbolAddress((void**)&Bp, g_bf);
    float* nrm; cudaGetSymbolAddress((void**)&nrm, g_norm);

    const ll SH = (ll)NTOK * DH, SL = (ll)MLM * DH;
    const ll SA2 = (ll)MLM * MLM;

    cudaStream_t s0 = 0;
    cudaStream_t s2 = g_ctx.s2;

    // prep on s0
    {
        dim3 blk(32, 8);
        transpose_split<<<dim3(3 * INNER / 32, DIM / 32, 1), blk, 0, s0>>>(
            w_qkv, Bp + B_WQTH, Bp + B_WQTL, DIM, 3 * INNER, 0, 0, nullptr, 0.f, 0);
        split_f32<<<(int)((SZ_Y + 255) / 256), 256, 0, s0>>>(x, Bp + B_XH, Bp + B_XL, SZ_Y);
    }

    // fork s2: w_out transpose overlaps qkv
    cudaEventRecord(g_ctx.e0, s0);
    cudaStreamWaitEvent(s2, g_ctx.e0, 0);
    transpose_split<<<dim3(DIM / 32, INNER / 32, 1), dim3(32, 8), 0, s2>>>(
        w_out, Bp + B_WOTH, Bp + B_WOTL, INNER, DIM, 0, 0, nullptr, 0.f, 0);

    // 1a. qkv GEMM, q+k columns — 2-term
    tcg<128, 128, 2, 512>(s0, Bp + B_XH, Bp + B_XL, Bp + B_WQTH, Bp + B_WQTL,
                          nullptr, nullptr, nullptr, nullptr, nullptr, nullptr,
                          BB * NTOK, 2 * INNER, DIM, DIM, 0, 0,
                          0, 0, 0, 0, 1, 1, 1.f, 0.f, 64);

    landmark_split_bf<<<(int)((SZ_LM + 255) / 256), 256, 0, s0>>>(Bp + B_QH, Bp + B_QL, Bp + B_QLMH, Bp + B_QLML);
    landmark_split_bf<<<(int)((SZ_LM + 255) / 256), 256, 0, s0>>>(Bp + B_KH, Bp + B_KL, Bp + B_KLMH, Bp + B_KLML);

    // 2. attn2 fused (+fp32 for pinv init)
    attn_gemm_softmax<<<dim3(MLM / 64, BH), 256, 81920, s0>>>(
        Bp + B_QLMH, Bp + B_QLML, Bp + B_KLMH, Bp + B_KLML,
        F + F_A2, Bp + B_A2H, Bp + B_A2L, SL, SL, SA2);

    // fork s2: pinv
    cudaEventRecord(g_ctx.e1, s0);
    cudaStreamWaitEvent(s2, g_ctx.e1, 0);

    norm_init_kernel<<<1, 1, 0, s2>>>(nrm);
    pinv_norm_kernel<<<BH, 256, 0, s2>>>(F + F_A2, nrm);
    {
        int blocks = (int)((SZ_A2 + 255) / 256);
        scale_split<<<blocks, 256, 0, s2>>>(F + F_A2, Bp + B_Z0TH, Bp + B_Z0TL, SZ_A2, nrm);
        transpose_split<<<dim3(8, 8, BH), dim3(32, 8), 0, s2>>>(
            F + F_A2, Bp + B_Z0H, Bp + B_Z0L, MLM, MLM, SA2, SA2, nrm, 0.f, 0);
    }

    bf16 *zch = Bp + B_Z0H,  *zcl = Bp + B_Z0L,  *zcth = Bp + B_Z0TH, *zctl = Bp + B_Z0TL;
    bf16 *znh = Bp + B_Z1H,  *znl = Bp + B_Z1L,  *znth = Bp + B_Z1TH, *zntl = Bp + B_Z1TL;

    for (int it = 0; it < 6; it++) {
#define PINV_STEP(S) \
        tcg<64, 128, S, 256>(s2, Bp + B_A2H, Bp + B_A2L, zcth, zctl, \
                    nullptr, Bp + B_XZH, Bp + B_XZL, Bp + B_T1TH, Bp + B_T1TL, nullptr, \
                    MLM, MLM, MLM, MLM, MLM, MLM, SA2, SA2, SA2, SA2, BH, 1, 1.f, 7.f, 2|4|8|16); \
        tcg<64, 128, S, 256>(s2, Bp + B_XZH, Bp + B_XZL, Bp + B_T1TH, Bp + B_T1TL, \
                    nullptr, nullptr, nullptr, Bp + B_T2TH, Bp + B_T2TL, nullptr, \
                    MLM, MLM, MLM, MLM, MLM, MLM, SA2, SA2, 0, SA2, BH, 1, 1.f, 15.f, 4|8); \
        tcg<64, 128, S, 256>(s2, Bp + B_XZH, Bp + B_XZL, Bp + B_T2TH, Bp + B_T2TL, \
                    nullptr, nullptr, nullptr, Bp + B_T3TH, Bp + B_T3TL, nullptr, \
                    MLM, MLM, MLM, MLM, MLM, MLM, SA2, SA2, 0, SA2, BH, 1, 1.f, 13.f, 4|8); \
        tcg<64, 128, S, 256>(s2, zch, zcl, Bp + B_T3TH, Bp + B_T3TL, \
                    nullptr, znh, znl, znth, zntl, nullptr, \
                    MLM, MLM, MLM, MLM, MLM, MLM, SA2, SA2, SA2, SA2, BH, 1, 0.25f, 0.f, 2|4);
        if (it < 5) { PINV_STEP(0) } else { PINV_STEP(1) }
#undef PINV_STEP
        bf16* t;
        t = zch;  zch  = znh;  znh  = t;   t = zcl;  zcl  = znl;  znl  = t;
        t = zcth; zcth = znth; znth = t;   t = zctl; zctl = zntl; zntl = t;
    }
    cudaEventRecord(g_ctx.e2, s2);

    // 1b. qkv GEMM, v columns — 3-term, concurrent with pinv
    tcg<128, 128, 1, 512>(s0, Bp + B_XH, Bp + B_XL,
                          Bp + B_WQTH + (ll)2 * INNER * DIM, Bp + B_WQTL + (ll)2 * INNER * DIM,
                          nullptr, nullptr, nullptr, nullptr, nullptr, nullptr,
                          BB * NTOK, INNER, DIM, DIM, 0, 2 * INNER,
                          0, 0, 0, 0, 1, 1, 1.f, 0.f, 64);

    // 3. fa3 (s0), 1-term logits + 1-term PV, concurrent with pinv (s2)
    fa3_av<<<dim3(MLM / 64, BH), 512, FA3_SMEM, s0>>>(
        Bp + B_QLMH, Bp + B_KH,
        Bp + B_VTH, Bp + B_AVTH, Bp + B_AVTL,
        SL, SH, SH, SL);

    // join pinv
    cudaStreamWaitEvent(s0, g_ctx.e2, 0);

    // 4. zav^T = (z @ av)^T
    tcg<64, 64, 1, 256>(s0, zch, zcl, Bp + B_AVTH, Bp + B_AVTL,
                        nullptr, nullptr, nullptr, Bp + B_ZVTH, Bp + B_ZVTL, nullptr,
                        MLM, DH, MLM, MLM, DH, MLM, SA2, SL, 0, SL, BH, 1, 1.f, 0.f, 4);

    // 5. a1o chunk0 then chunk1; out-proj chunk0 on s2 overlaps chunk1
    attn1_outh<<<dim3(NTOK / 64, 16), 512, A1O_SMEM, s0>>>(
        Bp + B_QH, Bp + B_KLMH,
        Bp + B_ZVTH, Bp + B_ZVTL, F + F_V, res_k,
        Bp + B_YH, Bp + B_YL, SH, SL, SL, SH, 0);
    cudaEventRecord(g_ctx.e3, s0);

    attn1_outh<<<dim3(NTOK / 64, 16), 512, A1O_SMEM, s0>>>(
        Bp + B_QH, Bp + B_KLMH,
        Bp + B_ZVTH, Bp + B_ZVTL, F + F_V, res_k,
        Bp + B_YH, Bp + B_YL, SH, SL, SL, SH, 16);

    cudaStreamWaitEvent(s2, g_ctx.e3, 0);
    // out-proj rows 0..8191 on s2 (3-term, precision-critical)
    tcg<128, 128, 1, 512>(s2, Bp + B_YH, Bp + B_YL, Bp + B_WOTH, Bp + B_WOTL,
                          out, nullptr, nullptr, nullptr, nullptr, b_out,
                          2 * NTOK, DIM, INNER, INNER, DIM, 0, 0, 0, 0, 0, 1, 1, 1.f, 0.f, 1);
    cudaEventRecord(g_ctx.e4, s2);

    // out-proj rows 8192..16383 on s0
    tcg<128, 128, 1, 512>(s0, Bp + B_YH + (ll)2 * NTOK * INNER, Bp + B_YL + (ll)2 * NTOK * INNER,
                          Bp + B_WOTH, Bp + B_WOTL,
                          out + (ll)2 * NTOK * DIM, nullptr, nullptr, nullptr, nullptr, b_out,
                          2 * NTOK, DIM, INNER, INNER, DIM, 0, 0, 0, 0, 0, 1, 1, 1.f, 0.f, 1);

    // final join
    cudaStreamWaitEvent(s0, g_ctx.e4, 0);
}